// round 1
// baseline (speedup 1.0000x reference)
#include <cuda_runtime.h>
#include <cstdint>

// Problem constants
#define BB 2
#define TT 2048
#define DD 1024
#define HH 16
#define DHH 64
#define M_TOT (BB*TT)          // 4096
#define PRESENT_HALF (BB*HH*TT*DHH)  // 4194304

// Scratch (device globals: allocation-free rule)
__device__ float g_q[M_TOT * DD];    // Q in [B*T, D] layout (col = h*64+d)
__device__ float g_att[M_TOT * DD];  // pre-proj attention output, merged heads

// ----------------------------------------------------------------------------
// SGEMM: C[M,N] = A[M,K] @ B[K,N] + bias
// BM=128, BN=128, BK=8, 256 threads, 8x8 per thread.
// mode 0: QKV epilogue -> q to g_q, k/v scattered to present
// mode 1: plain write to C
// ----------------------------------------------------------------------------
#define BM 128
#define BN 128
#define BK 8

__global__ __launch_bounds__(256) void sgemm_kernel(
    const float* __restrict__ A, const float* __restrict__ Bw,
    const float* __restrict__ bias, float* __restrict__ C,
    float* __restrict__ present, int K, int N, int mode)
{
    __shared__ float As[BK][BM];
    __shared__ float Bs[BK][BN];

    const int tid = threadIdx.x;
    const int tx = tid & 15;
    const int ty = tid >> 4;
    const int rowBase = blockIdx.y * BM;
    const int colBase = blockIdx.x * BN;

    const int aRow = tid >> 1;          // 0..127
    const int aCol = (tid & 1) * 4;     // 0 or 4
    const int bRow = tid >> 5;          // 0..7
    const int bCol = (tid & 31) * 4;    // 0..124

    float acc[8][8];
#pragma unroll
    for (int i = 0; i < 8; i++)
#pragma unroll
        for (int j = 0; j < 8; j++) acc[i][j] = 0.0f;

    const float* Aptr = A + (size_t)(rowBase + aRow) * K + aCol;
    const float* Bptr = Bw + (size_t)bRow * N + colBase + bCol;

    for (int k0 = 0; k0 < K; k0 += BK) {
        float4 av = *(const float4*)(Aptr + k0);
        As[aCol + 0][aRow] = av.x;
        As[aCol + 1][aRow] = av.y;
        As[aCol + 2][aRow] = av.z;
        As[aCol + 3][aRow] = av.w;
        float4 bv = *(const float4*)(Bptr + (size_t)k0 * N);
        *(float4*)(&Bs[bRow][bCol]) = bv;
        __syncthreads();

#pragma unroll
        for (int kk = 0; kk < BK; kk++) {
            float ra[8], rb[8];
            *(float4*)(&ra[0]) = *(const float4*)(&As[kk][ty * 8]);
            *(float4*)(&ra[4]) = *(const float4*)(&As[kk][ty * 8 + 4]);
            *(float4*)(&rb[0]) = *(const float4*)(&Bs[kk][tx * 8]);
            *(float4*)(&rb[4]) = *(const float4*)(&Bs[kk][tx * 8 + 4]);
#pragma unroll
            for (int i = 0; i < 8; i++)
#pragma unroll
                for (int j = 0; j < 8; j++)
                    acc[i][j] = fmaf(ra[i], rb[j], acc[i][j]);
        }
        __syncthreads();
    }

    // Epilogue
    if (mode == 1) {
#pragma unroll
        for (int i = 0; i < 8; i++) {
            int m = rowBase + ty * 8 + i;
#pragma unroll
            for (int j = 0; j < 8; j++) {
                int n = colBase + tx * 8 + j;
                C[(size_t)m * N + n] = acc[i][j] + bias[n];
            }
        }
    } else {
        // N = 3072. colBase multiple of 128 -> whole block is q, k, or v.
#pragma unroll
        for (int i = 0; i < 8; i++) {
            int m = rowBase + ty * 8 + i;
            int b = m >> 11;           // /2048
            int t = m & 2047;
#pragma unroll
            for (int j = 0; j < 8; j++) {
                int n = colBase + tx * 8 + j;
                float v = acc[i][j] + bias[n];
                if (n < DD) {
                    g_q[(size_t)m * DD + n] = v;
                } else if (n < 2 * DD) {
                    int hd = n - DD;
                    int h = hd >> 6, d = hd & 63;
                    present[(((size_t)(b * HH + h)) * TT + t) * DHH + d] = v;
                } else {
                    int hd = n - 2 * DD;
                    int h = hd >> 6, d = hd & 63;
                    present[PRESENT_HALF +
                            (((size_t)(b * HH + h)) * TT + t) * DHH + d] = v;
                }
            }
        }
    }
}

// ----------------------------------------------------------------------------
// Flash attention (fp32): per block one (b, h, q-tile of 64 rows).
// S = Q K^T * 0.25, causal mask (-1e10 equiv), online softmax, O = P V.
// smem: Qt[64][68] (kk-major), Kt/Pt[64][68], Vs[64][64].
// 256 threads; each thread owns a 4x4 micro-tile of the 64x64 score tile.
// ----------------------------------------------------------------------------
#define QP 68

__global__ __launch_bounds__(256) void attn_kernel(
    const float* __restrict__ qbuf, const float* __restrict__ present,
    float* __restrict__ attout)
{
    extern __shared__ float smem[];
    float* Qt = smem;                  // [64][QP], Qt[kk][row]
    float* Kt = smem + 64 * QP;        // [64][QP], Kt[kk][col]; reused as Pt[kcol][row]
    float* Vs = smem + 2 * 64 * QP;    // [64][64], Vs[k][d]

    const int tid = threadIdx.x;
    const int tx = tid & 15;
    const int ty = tid >> 4;
    const int qt = blockIdx.x;         // q tile index
    const int h  = blockIdx.y;
    const int b  = blockIdx.z;
    const int q0 = qt * 64;

    const int lr = tid >> 4;           // 0..15, load row base
    const int lc = tid & 15;           // 0..15, float4 col

    // Load Q tile transposed: Qt[c][r] = Q[q0+r][c]
    {
        const float* baseq = qbuf + ((size_t)(b * TT + q0)) * DD + h * DHH;
#pragma unroll
        for (int it = 0; it < 4; it++) {
            int r = lr + it * 16;
            float4 qv = *(const float4*)(baseq + (size_t)r * DD + lc * 4);
            Qt[(lc * 4 + 0) * QP + r] = qv.x;
            Qt[(lc * 4 + 1) * QP + r] = qv.y;
            Qt[(lc * 4 + 2) * QP + r] = qv.z;
            Qt[(lc * 4 + 3) * QP + r] = qv.w;
        }
    }

    float acc_o[4][4];
#pragma unroll
    for (int i = 0; i < 4; i++)
#pragma unroll
        for (int j = 0; j < 4; j++) acc_o[i][j] = 0.0f;
    float m_i[4], l_i[4];
#pragma unroll
    for (int i = 0; i < 4; i++) { m_i[i] = -1e30f; l_i[i] = 0.0f; }

    const float* basek = present + ((size_t)(b * HH + h)) * TT * DHH;
    const float* basev = basek + (size_t)PRESENT_HALF;

    const int ntiles = qt + 1;
    for (int kt = 0; kt < ntiles; kt++) {
        const int k0 = kt * 64;
        __syncthreads();   // protect Kt(=Pt)/Vs from previous iteration reads

        // Load K tile transposed + V tile straight
#pragma unroll
        for (int it = 0; it < 4; it++) {
            int r = lr + it * 16;
            float4 kv = *(const float4*)(basek + (size_t)(k0 + r) * DHH + lc * 4);
            Kt[(lc * 4 + 0) * QP + r] = kv.x;
            Kt[(lc * 4 + 1) * QP + r] = kv.y;
            Kt[(lc * 4 + 2) * QP + r] = kv.z;
            Kt[(lc * 4 + 3) * QP + r] = kv.w;
            float4 vv = *(const float4*)(basev + (size_t)(k0 + r) * DHH + lc * 4);
            *(float4*)(&Vs[r * 64 + lc * 4]) = vv;
        }
        __syncthreads();

        // S = Q K^T
        float s[4][4];
#pragma unroll
        for (int i = 0; i < 4; i++)
#pragma unroll
            for (int j = 0; j < 4; j++) s[i][j] = 0.0f;

#pragma unroll 16
        for (int kk = 0; kk < 64; kk++) {
            float4 qv = *(const float4*)(&Qt[kk * QP + ty * 4]);
            float4 kv = *(const float4*)(&Kt[kk * QP + tx * 4]);
            float qa[4] = {qv.x, qv.y, qv.z, qv.w};
            float ka[4] = {kv.x, kv.y, kv.z, kv.w};
#pragma unroll
            for (int i = 0; i < 4; i++)
#pragma unroll
                for (int j = 0; j < 4; j++)
                    s[i][j] = fmaf(qa[i], ka[j], s[i][j]);
        }

        // scale + causal mask
        const bool diag = (k0 == q0);
#pragma unroll
        for (int i = 0; i < 4; i++) {
#pragma unroll
            for (int j = 0; j < 4; j++) {
                float sv = s[i][j] * 0.25f;
                if (diag && (k0 + tx * 4 + j) > (q0 + ty * 4 + i)) sv = -1e30f;
                s[i][j] = sv;
            }
        }

        // online softmax (row stats across 16 tx lanes; lane = (ty&1)*16+tx)
        float p[4][4];
#pragma unroll
        for (int i = 0; i < 4; i++) {
            float rm = fmaxf(fmaxf(s[i][0], s[i][1]), fmaxf(s[i][2], s[i][3]));
#pragma unroll
            for (int off = 8; off >= 1; off >>= 1)
                rm = fmaxf(rm, __shfl_xor_sync(0xffffffffu, rm, off));
            float mn = fmaxf(m_i[i], rm);
            float alpha = __expf(m_i[i] - mn);
            float rs = 0.0f;
#pragma unroll
            for (int j = 0; j < 4; j++) {
                float pv = __expf(s[i][j] - mn);
                p[i][j] = pv;
                rs += pv;
            }
#pragma unroll
            for (int off = 8; off >= 1; off >>= 1)
                rs += __shfl_xor_sync(0xffffffffu, rs, off);
            l_i[i] = l_i[i] * alpha + rs;
            m_i[i] = mn;
#pragma unroll
            for (int j = 0; j < 4; j++) acc_o[i][j] *= alpha;
        }

        __syncthreads();   // all S-phase reads of Kt done
        // write P transposed into Kt buffer: Pt[kcol][row]
#pragma unroll
        for (int i = 0; i < 4; i++)
#pragma unroll
            for (int j = 0; j < 4; j++)
                Kt[(tx * 4 + j) * QP + (ty * 4 + i)] = p[i][j];
        __syncthreads();

        // O += P @ V
#pragma unroll 16
        for (int kk = 0; kk < 64; kk++) {
            float4 pv = *(const float4*)(&Kt[kk * QP + ty * 4]);
            float4 vv = *(const float4*)(&Vs[kk * 64 + tx * 4]);
            float pa[4] = {pv.x, pv.y, pv.z, pv.w};
            float va[4] = {vv.x, vv.y, vv.z, vv.w};
#pragma unroll
            for (int i = 0; i < 4; i++)
#pragma unroll
                for (int j = 0; j < 4; j++)
                    acc_o[i][j] = fmaf(pa[i], va[j], acc_o[i][j]);
        }
    }

    // normalize + write merged-head output
#pragma unroll
    for (int i = 0; i < 4; i++) {
        float inv = 1.0f / l_i[i];
        int qg = q0 + ty * 4 + i;
        float4 ov;
        ov.x = acc_o[i][0] * inv;
        ov.y = acc_o[i][1] * inv;
        ov.z = acc_o[i][2] * inv;
        ov.w = acc_o[i][3] * inv;
        *(float4*)(&attout[((size_t)(b * TT + qg)) * DD + h * DHH + tx * 4]) = ov;
    }
}

// ----------------------------------------------------------------------------
extern "C" void kernel_launch(void* const* d_in, const int* in_sizes, int n_in,
                              void* d_out, int out_size)
{
    const float* x      = (const float*)d_in[0];
    const float* w_attn = (const float*)d_in[1];
    const float* b_attn = (const float*)d_in[2];
    const float* w_proj = (const float*)d_in[3];
    const float* b_proj = (const float*)d_in[4];

    float* out = (float*)d_out;
    float* a_out = out;                        // [B,T,D]
    float* present = out + (size_t)M_TOT * DD; // [2,B,H,T,dh]

    float *qp, *attp;
    cudaGetSymbolAddress((void**)&qp, g_q);
    cudaGetSymbolAddress((void**)&attp, g_att);

    const int smem_attn = (2 * 64 * QP + 64 * 64) * 4;  // 51200 bytes
    cudaFuncSetAttribute(attn_kernel,
                         cudaFuncAttributeMaxDynamicSharedMemorySize, smem_attn);

    // 1) QKV GEMM: [4096,1024] @ [1024,3072] + bias -> g_q + present(k,v)
    {
        dim3 grid(3 * DD / BN, M_TOT / BM);
        sgemm_kernel<<<grid, 256>>>(x, w_attn, b_attn, nullptr, present,
                                    DD, 3 * DD, 0);
    }
    // 2) attention
    {
        dim3 grid(TT / 64, HH, BB);
        attn_kernel<<<grid, 256, smem_attn>>>(qp, present, attp);
    }
    // 3) projection GEMM: [4096,1024] @ [1024,1024] + bias -> a_out
    {
        dim3 grid(DD / BN, M_TOT / BM);
        sgemm_kernel<<<grid, 256>>>(attp, w_proj, b_proj, a_out, nullptr,
                                    DD, DD, 1);
    }
}

// round 3
// speedup vs baseline: 1.3758x; 1.3758x over previous
#include <cuda_runtime.h>
#include <cuda_bf16.h>
#include <cstdint>

// Problem constants
#define BB 2
#define TT 2048
#define DD 1024
#define HH 16
#define DHH 64
#define M_TOT (BB*TT)                 // 4096
#define PRESENT_HALF (BB*HH*TT*DHH)   // 4194304

// ---------------------------------------------------------------------------
// Device-global scratch (allocation-free rule).
// "Packed split" layout: for each pair of k (2k,2k+1), 8 bytes:
//   [hi(2k), hi(2k+1), lo(2k), lo(2k+1)]  (bf16 each)
// Row byte stride = K*4.
// ---------------------------------------------------------------------------
__device__ unsigned char g_xs[(size_t)M_TOT * DD * 4];      // x packed-split
__device__ unsigned char g_bta[(size_t)3 * DD * DD * 4];    // w_attn^T packed-split [3072][1024]
__device__ unsigned char g_btp[(size_t)DD * DD * 4];        // w_proj^T packed-split [1024][1024]
__device__ float g_q[(size_t)M_TOT * DD];                   // Q fp32 [B*T, D]
__device__ unsigned char g_atts[(size_t)M_TOT * DD * 4];    // attn out packed-split

// ---------------------------------------------------------------------------
// Helpers
// ---------------------------------------------------------------------------
__device__ __forceinline__ uint32_t smem_to_u32(const void* smem_ptr) {
    uint32_t addr;
    asm("{ .reg .u64 tmp; cvta.to.shared.u64 tmp, %1; cvt.u32.u64 %0, tmp; }"
        : "=r"(addr) : "l"(smem_ptr));
    return addr;
}

__device__ __forceinline__ uint32_t pack2bf(float a, float b) {
    __nv_bfloat162 t = __floats2bfloat162_rn(a, b);   // x=a(low), y=b(high)
    return *reinterpret_cast<uint32_t*>(&t);
}

// pack 2 consecutive fp32 into (hi-pair, lo-pair) words
__device__ __forceinline__ void split_pair(float a, float b,
                                           uint32_t& wh, uint32_t& wl) {
    __nv_bfloat16 ha = __float2bfloat16_rn(a);
    __nv_bfloat16 hb = __float2bfloat16_rn(b);
    float la = a - __bfloat162float(ha);
    float lb = b - __bfloat162float(hb);
    wh = ((uint32_t)__bfloat16_as_ushort(hb) << 16) | __bfloat16_as_ushort(ha);
    wl = pack2bf(la, lb);
}

// Fast exp on the FMA pipe (arg <= 0 in our use). ~1e-6 rel error.
__device__ __forceinline__ float fast_exp(float x) {
    x = fmaxf(x, -87.0f);
    float t = fmaf(x, 1.4426950408889634f, 12582912.0f);
    int   ni = __float_as_int(t);
    float n = t - 12582912.0f;
    float f = fmaf(x, 1.4426950408889634f, -n);       // f in [-0.5, 0.5]
    float p = 1.3333558146e-3f;
    p = fmaf(p, f, 9.6181291076e-3f);
    p = fmaf(p, f, 5.5504108665e-2f);
    p = fmaf(p, f, 2.4022650696e-1f);
    p = fmaf(p, f, 6.9314718056e-1f);
    p = fmaf(p, f, 1.0f);
    return __int_as_float(__float_as_int(p) + (int)((unsigned)ni << 23));
}

#define CP16(s, g) \
    asm volatile("cp.async.cg.shared.global [%0], [%1], 16;" :: "r"(s), "l"(g))
#define CP_COMMIT() asm volatile("cp.async.commit_group;" ::: "memory")
#define CP_WAIT2()  asm volatile("cp.async.wait_group 2;" ::: "memory")

#define MMA_BF16(c, a, b) \
    asm volatile("mma.sync.aligned.m16n8k16.row.col.f32.bf16.bf16.f32 " \
        "{%0,%1,%2,%3},{%4,%5,%6,%7},{%8,%9},{%0,%1,%2,%3};" \
        : "+f"((c)[0]), "+f"((c)[1]), "+f"((c)[2]), "+f"((c)[3]) \
        : "r"((a)[0]), "r"((a)[1]), "r"((a)[2]), "r"((a)[3]), \
          "r"((b)[0]), "r"((b)[1]))

// ---------------------------------------------------------------------------
// Prepass 1: x -> packed-split (in: float4 = 2 pairs, out: uint4)
// ---------------------------------------------------------------------------
__global__ void split_kernel(const float4* __restrict__ src,
                             uint4* __restrict__ dst, int n4)
{
    int i = blockIdx.x * blockDim.x + threadIdx.x;
    if (i < n4) {
        float4 v = src[i];
        uint4 o;
        split_pair(v.x, v.y, o.x, o.y);
        split_pair(v.z, v.w, o.z, o.w);
        dst[i] = o;
    }
}

// ---------------------------------------------------------------------------
// Prepass 2: W[K,N] -> Bt[N][K] packed-split
// ---------------------------------------------------------------------------
__global__ void transpose_split_kernel(const float* __restrict__ w,
                                       unsigned char* __restrict__ bt,
                                       int Kd, int Nd)
{
    __shared__ float t[32][33];   // t[k][n]
    int n0 = blockIdx.x * 32, k0 = blockIdx.y * 32;
    int tx = threadIdx.x, ty = threadIdx.y;   // (32, 8)
#pragma unroll
    for (int i = 0; i < 32; i += 8)
        t[ty + i][tx] = w[(size_t)(k0 + ty + i) * Nd + n0 + tx];
    __syncthreads();
    int tid = ty * 32 + tx;
    int po = tid & 15;            // k-pair 0..15
    int nl = tid >> 4;            // 0..15 (+16)
#pragma unroll
    for (int half = 0; half < 2; half++) {
        int n_loc = nl + half * 16;
        float v0 = t[2 * po][n_loc];
        float v1 = t[2 * po + 1][n_loc];
        uint2 o;
        split_pair(v0, v1, o.x, o.y);
        *(uint2*)(bt + (size_t)(n0 + n_loc) * Kd * 4 + (size_t)(k0 / 2 + po) * 8) = o;
    }
}

// ---------------------------------------------------------------------------
// bf16 3-term mma.sync GEMM: C[M,N] = A[M,K] @ B^T + bias
// A, B in packed-split layout (row stride K*4 bytes).
// CTA 128x128, 256 thr (8 warps, 2m x 4n), k-chunk 16, 4-stage cp.async.
// mode 0: QKV scatter (q->qout fp32, k/v->present fp32). mode 1: plain C.
// ---------------------------------------------------------------------------
#define GSTAGE 20480      // A 128*80 + B 128*80
#define GSMEM  (4 * GSTAGE)

__global__ __launch_bounds__(256, 1) void bf16_gemm_kernel(
    const unsigned char* __restrict__ Ag, const unsigned char* __restrict__ Bg,
    const float* __restrict__ bias,
    float* __restrict__ Cout, float* __restrict__ qout,
    float* __restrict__ present, int K, int N, int mode)
{
    extern __shared__ char smem[];
    const uint32_t smem_u = smem_to_u32(smem);
    const int tid = threadIdx.x;
    const int lane = tid & 31, wid = tid >> 5;
    const int wm = wid & 1, wn = wid >> 1;
    const int rowBase = blockIdx.y * 128, colBase = blockIdx.x * 128;
    const size_t Arow = (size_t)K * 4, Brow = (size_t)K * 4;
    const int NCH = K >> 4;

    // per-thread load slots: row r = tid/2, parts {0,1} or {2,3}
    const int ldr = tid >> 1;
    const int ldp = (tid & 1) * 2;
    const unsigned char* gA = Ag + (size_t)(rowBase + ldr) * Arow + ldp * 16;
    const unsigned char* gB = Bg + (size_t)(colBase + ldr) * Brow + ldp * 16;
    const uint32_t sA = smem_u + ldr * 80 + ldp * 16;
    const uint32_t sB = smem_u + 10240 + ldr * 80 + ldp * 16;

#define LOAD_STAGE(chunk, stg) do {                        \
        size_t go = (size_t)(chunk) * 64;                  \
        uint32_t so = (uint32_t)(stg) * GSTAGE;            \
        CP16(sA + so,      gA + go);                       \
        CP16(sA + so + 16, gA + go + 16);                  \
        CP16(sB + so,      gB + go);                       \
        CP16(sB + so + 16, gB + go + 16);                  \
    } while (0)

    float c[4][4][4];
#pragma unroll
    for (int i = 0; i < 4; i++)
#pragma unroll
        for (int j = 0; j < 4; j++)
#pragma unroll
            for (int r = 0; r < 4; r++) c[i][j][r] = 0.0f;

    LOAD_STAGE(0, 0); CP_COMMIT();
    LOAD_STAGE(1, 1); CP_COMMIT();
    LOAD_STAGE(2, 2); CP_COMMIT();

    const char* smem_c = smem;
    for (int ch = 0; ch < NCH; ch++) {
        CP_WAIT2();
        __syncthreads();
        const int s = ch & 3;
        const char* As = smem_c + s * GSTAGE;
        const char* Bs = As + 10240;

        uint32_t ah[4][4], al[4][4];
#pragma unroll
        for (int mf = 0; mf < 4; mf++) {
            int r = wm * 64 + mf * 16 + (lane >> 2);
            const char* p = As + r * 80 + (lane & 3) * 8;
            ah[mf][0] = *(const uint32_t*)(p);
            al[mf][0] = *(const uint32_t*)(p + 4);
            ah[mf][1] = *(const uint32_t*)(p + 8 * 80);
            al[mf][1] = *(const uint32_t*)(p + 8 * 80 + 4);
            ah[mf][2] = *(const uint32_t*)(p + 32);
            al[mf][2] = *(const uint32_t*)(p + 36);
            ah[mf][3] = *(const uint32_t*)(p + 8 * 80 + 32);
            al[mf][3] = *(const uint32_t*)(p + 8 * 80 + 36);
        }
        uint32_t bh[4][2], bl[4][2];
#pragma unroll
        for (int nf = 0; nf < 4; nf++) {
            int n = wn * 32 + nf * 8 + (lane >> 2);
            const char* p = Bs + n * 80 + (lane & 3) * 8;
            bh[nf][0] = *(const uint32_t*)(p);
            bl[nf][0] = *(const uint32_t*)(p + 4);
            bh[nf][1] = *(const uint32_t*)(p + 32);
            bl[nf][1] = *(const uint32_t*)(p + 36);
        }
#pragma unroll
        for (int mf = 0; mf < 4; mf++)
#pragma unroll
            for (int nf = 0; nf < 4; nf++) {
                MMA_BF16(c[mf][nf], ah[mf], bh[nf]);
                MMA_BF16(c[mf][nf], ah[mf], bl[nf]);
                MMA_BF16(c[mf][nf], al[mf], bh[nf]);
            }
        __syncthreads();
        if (ch + 3 < NCH) LOAD_STAGE(ch + 3, (ch + 3) & 3);
        CP_COMMIT();
    }

    // Epilogue: direct stores (pairs of consecutive n)
#pragma unroll
    for (int mf = 0; mf < 4; mf++) {
#pragma unroll
        for (int nf = 0; nf < 4; nf++) {
            int m0 = rowBase + wm * 64 + mf * 16 + (lane >> 2);
            int n  = colBase + wn * 32 + nf * 8 + (lane & 3) * 2;
            float b0 = bias[n], b1 = bias[n + 1];
#pragma unroll
            for (int half = 0; half < 2; half++) {
                int m = m0 + half * 8;
                float2 v;
                v.x = c[mf][nf][half * 2 + 0] + b0;
                v.y = c[mf][nf][half * 2 + 1] + b1;
                if (mode == 1) {
                    *(float2*)&Cout[(size_t)m * N + n] = v;
                } else {
                    if (n < DD) {
                        *(float2*)&qout[(size_t)m * DD + n] = v;
                    } else {
                        int seg = n >> 10;
                        int nn = n & 1023;
                        int h = nn >> 6, d = nn & 63;
                        int b = m >> 11, t = m & 2047;
                        float* dst = present
                                   + (seg == 2 ? (size_t)PRESENT_HALF : (size_t)0)
                                   + (((size_t)(b * HH + h)) * TT + t) * DHH + d;
                        *(float2*)dst = v;
                    }
                }
            }
        }
    }
}

// ---------------------------------------------------------------------------
// Flash attention (fp32 SIMT), exp on FMA pipe; epilogue -> packed-split bf16
// ---------------------------------------------------------------------------
#define QP 68

__global__ __launch_bounds__(256) void attn_kernel(
    const float* __restrict__ qbuf, const float* __restrict__ present,
    unsigned char* __restrict__ atts)
{
    extern __shared__ float fsm[];
    float* Qt = fsm;                   // [64][QP], Qt[kk][row]
    float* Kt = fsm + 64 * QP;         // [64][QP], reused as Pt
    float* Vs = fsm + 2 * 64 * QP;     // [64][64]

    const int tid = threadIdx.x;
    const int tx = tid & 15;
    const int ty = tid >> 4;
    const int qt = blockIdx.x;
    const int h  = blockIdx.y;
    const int b  = blockIdx.z;
    const int q0 = qt * 64;

    const int lr = tid >> 4;
    const int lc = tid & 15;

    {
        const float* baseq = qbuf + ((size_t)(b * TT + q0)) * DD + h * DHH;
#pragma unroll
        for (int it = 0; it < 4; it++) {
            int r = lr + it * 16;
            float4 qv = *(const float4*)(baseq + (size_t)r * DD + lc * 4);
            Qt[(lc * 4 + 0) * QP + r] = qv.x;
            Qt[(lc * 4 + 1) * QP + r] = qv.y;
            Qt[(lc * 4 + 2) * QP + r] = qv.z;
            Qt[(lc * 4 + 3) * QP + r] = qv.w;
        }
    }

    float acc_o[4][4];
#pragma unroll
    for (int i = 0; i < 4; i++)
#pragma unroll
        for (int j = 0; j < 4; j++) acc_o[i][j] = 0.0f;
    float m_i[4], l_i[4];
#pragma unroll
    for (int i = 0; i < 4; i++) { m_i[i] = -1e30f; l_i[i] = 0.0f; }

    const float* basek = present + ((size_t)(b * HH + h)) * TT * DHH;
    const float* basev = basek + (size_t)PRESENT_HALF;

    const int ntiles = qt + 1;
    for (int kt = 0; kt < ntiles; kt++) {
        const int k0 = kt * 64;
        __syncthreads();

#pragma unroll
        for (int it = 0; it < 4; it++) {
            int r = lr + it * 16;
            float4 kv = *(const float4*)(basek + (size_t)(k0 + r) * DHH + lc * 4);
            Kt[(lc * 4 + 0) * QP + r] = kv.x;
            Kt[(lc * 4 + 1) * QP + r] = kv.y;
            Kt[(lc * 4 + 2) * QP + r] = kv.z;
            Kt[(lc * 4 + 3) * QP + r] = kv.w;
            float4 vv = *(const float4*)(basev + (size_t)(k0 + r) * DHH + lc * 4);
            *(float4*)(&Vs[r * 64 + lc * 4]) = vv;
        }
        __syncthreads();

        float s[4][4];
#pragma unroll
        for (int i = 0; i < 4; i++)
#pragma unroll
            for (int j = 0; j < 4; j++) s[i][j] = 0.0f;

#pragma unroll 16
        for (int kk = 0; kk < 64; kk++) {
            float4 qv = *(const float4*)(&Qt[kk * QP + ty * 4]);
            float4 kv = *(const float4*)(&Kt[kk * QP + tx * 4]);
            float qa[4] = {qv.x, qv.y, qv.z, qv.w};
            float ka[4] = {kv.x, kv.y, kv.z, kv.w};
#pragma unroll
            for (int i = 0; i < 4; i++)
#pragma unroll
                for (int j = 0; j < 4; j++)
                    s[i][j] = fmaf(qa[i], ka[j], s[i][j]);
        }

        const bool diag = (k0 == q0);
#pragma unroll
        for (int i = 0; i < 4; i++) {
#pragma unroll
            for (int j = 0; j < 4; j++) {
                float sv = s[i][j] * 0.25f;
                if (diag && (k0 + tx * 4 + j) > (q0 + ty * 4 + i)) sv = -1e30f;
                s[i][j] = sv;
            }
        }

        float p[4][4];
#pragma unroll
        for (int i = 0; i < 4; i++) {
            float rm = fmaxf(fmaxf(s[i][0], s[i][1]), fmaxf(s[i][2], s[i][3]));
#pragma unroll
            for (int off = 8; off >= 1; off >>= 1)
                rm = fmaxf(rm, __shfl_xor_sync(0xffffffffu, rm, off));
            float mn = fmaxf(m_i[i], rm);
            float alpha = fast_exp(m_i[i] - mn);
            float rs = 0.0f;
#pragma unroll
            for (int j = 0; j < 4; j++) {
                float pv = fast_exp(s[i][j] - mn);
                p[i][j] = pv;
                rs += pv;
            }
#pragma unroll
            for (int off = 8; off >= 1; off >>= 1)
                rs += __shfl_xor_sync(0xffffffffu, rs, off);
            l_i[i] = l_i[i] * alpha + rs;
            m_i[i] = mn;
#pragma unroll
            for (int j = 0; j < 4; j++) acc_o[i][j] *= alpha;
        }

        __syncthreads();
#pragma unroll
        for (int i = 0; i < 4; i++)
#pragma unroll
            for (int j = 0; j < 4; j++)
                Kt[(tx * 4 + j) * QP + (ty * 4 + i)] = p[i][j];
        __syncthreads();

#pragma unroll 16
        for (int kk = 0; kk < 64; kk++) {
            float4 pv = *(const float4*)(&Kt[kk * QP + ty * 4]);
            float4 vv = *(const float4*)(&Vs[kk * 64 + tx * 4]);
            float pa[4] = {pv.x, pv.y, pv.z, pv.w};
            float va[4] = {vv.x, vv.y, vv.z, vv.w};
#pragma unroll
            for (int i = 0; i < 4; i++)
#pragma unroll
                for (int j = 0; j < 4; j++)
                    acc_o[i][j] = fmaf(pa[i], va[j], acc_o[i][j]);
        }
    }

    // epilogue: normalize, write packed-split bf16 (4 elems = 16B)
#pragma unroll
    for (int i = 0; i < 4; i++) {
        float inv = 1.0f / l_i[i];
        int qg = q0 + ty * 4 + i;
        int m = b * TT + qg;
        int col = h * DHH + tx * 4;
        float o0 = acc_o[i][0] * inv, o1 = acc_o[i][1] * inv;
        float o2 = acc_o[i][2] * inv, o3 = acc_o[i][3] * inv;
        uint4 w;
        split_pair(o0, o1, w.x, w.y);
        split_pair(o2, o3, w.z, w.w);
        *(uint4*)(atts + (size_t)m * DD * 4 + (size_t)col * 4) = w;
    }
}

// ---------------------------------------------------------------------------
extern "C" void kernel_launch(void* const* d_in, const int* in_sizes, int n_in,
                              void* d_out, int out_size)
{
    const float* x      = (const float*)d_in[0];
    const float* w_attn = (const float*)d_in[1];
    const float* b_attn = (const float*)d_in[2];
    const float* w_proj = (const float*)d_in[3];
    const float* b_proj = (const float*)d_in[4];

    float* out = (float*)d_out;
    float* a_out = out;
    float* present = out + (size_t)M_TOT * DD;

    unsigned char *xs, *bta, *btp, *atts;
    float *qp;
    cudaGetSymbolAddress((void**)&xs,   g_xs);
    cudaGetSymbolAddress((void**)&bta,  g_bta);
    cudaGetSymbolAddress((void**)&btp,  g_btp);
    cudaGetSymbolAddress((void**)&qp,   g_q);
    cudaGetSymbolAddress((void**)&atts, g_atts);

    const int smem_attn = (2 * 64 * QP + 64 * 64) * 4;  // 51200
    cudaFuncSetAttribute(attn_kernel,
                         cudaFuncAttributeMaxDynamicSharedMemorySize, smem_attn);
    cudaFuncSetAttribute(bf16_gemm_kernel,
                         cudaFuncAttributeMaxDynamicSharedMemorySize, GSMEM);

    // Prepasses
    split_kernel<<<(M_TOT * DD / 4 + 255) / 256, 256>>>(
        (const float4*)x, (uint4*)xs, M_TOT * DD / 4);
    transpose_split_kernel<<<dim3(3 * DD / 32, DD / 32), dim3(32, 8)>>>(
        w_attn, bta, DD, 3 * DD);
    transpose_split_kernel<<<dim3(DD / 32, DD / 32), dim3(32, 8)>>>(
        w_proj, btp, DD, DD);

    // QKV GEMM -> g_q + present
    bf16_gemm_kernel<<<dim3(3 * DD / 128, M_TOT / 128), 256, GSMEM>>>(
        xs, bta, b_attn, nullptr, qp, present, DD, 3 * DD, 0);

    // Attention -> g_atts (packed split)
    attn_kernel<<<dim3(TT / 64, HH, BB), 256, smem_attn>>>(qp, present, atts);

    // Projection GEMM -> a_out
    bf16_gemm_kernel<<<dim3(DD / 128, M_TOT / 128), 256, GSMEM>>>(
        atts, btp, b_proj, a_out, nullptr, nullptr, DD, DD, 1);
}

// round 4
// speedup vs baseline: 1.3764x; 1.0005x over previous
#include <cuda_runtime.h>
#include <cuda_bf16.h>
#include <cstdint>

// Problem constants
#define BB 2
#define TT 2048
#define DD 1024
#define HH 16
#define DHH 64
#define M_TOT (BB*TT)                 // 4096
#define PRESENT_HALF (BB*HH*TT*DHH)   // 4194304

// ---------------------------------------------------------------------------
// Device-global scratch (allocation-free rule).
// "Packed split" layout: for each pair of k (2k,2k+1), 8 bytes:
//   [hi(2k), hi(2k+1), lo(2k), lo(2k+1)]  (bf16 each)
// Row byte stride = K*4.
// ---------------------------------------------------------------------------
__device__ unsigned char g_xs[(size_t)M_TOT * DD * 4];      // x packed-split
__device__ unsigned char g_bta[(size_t)3 * DD * DD * 4];    // w_attn^T packed-split [3072][1024]
__device__ unsigned char g_btp[(size_t)DD * DD * 4];        // w_proj^T packed-split [1024][1024]
__device__ float g_q[(size_t)M_TOT * DD];                   // Q fp32 [B*T, D]
__device__ unsigned char g_atts[(size_t)M_TOT * DD * 4];    // attn out packed-split

// ---------------------------------------------------------------------------
// Helpers
// ---------------------------------------------------------------------------
__device__ __forceinline__ uint32_t smem_to_u32(const void* smem_ptr) {
    uint32_t addr;
    asm("{ .reg .u64 tmp; cvta.to.shared.u64 tmp, %1; cvt.u32.u64 %0, tmp; }"
        : "=r"(addr) : "l"(smem_ptr));
    return addr;
}

__device__ __forceinline__ uint32_t pack2bf(float a, float b) {
    __nv_bfloat162 t = __floats2bfloat162_rn(a, b);   // x=a(low), y=b(high)
    return *reinterpret_cast<uint32_t*>(&t);
}

// pack 2 consecutive fp32 into (hi-pair, lo-pair) words
__device__ __forceinline__ void split_pair(float a, float b,
                                           uint32_t& wh, uint32_t& wl) {
    __nv_bfloat16 ha = __float2bfloat16_rn(a);
    __nv_bfloat16 hb = __float2bfloat16_rn(b);
    float la = a - __bfloat162float(ha);
    float lb = b - __bfloat162float(hb);
    wh = ((uint32_t)__bfloat16_as_ushort(hb) << 16) | __bfloat16_as_ushort(ha);
    wl = pack2bf(la, lb);
}

// Fast exp on the FMA pipe (arg <= 0 in our use). ~1e-6 rel error.
__device__ __forceinline__ float fast_exp(float x) {
    x = fmaxf(x, -87.0f);
    float t = fmaf(x, 1.4426950408889634f, 12582912.0f);
    int   ni = __float_as_int(t);
    float n = t - 12582912.0f;
    float f = fmaf(x, 1.4426950408889634f, -n);       // f in [-0.5, 0.5]
    float p = 1.3333558146e-3f;
    p = fmaf(p, f, 9.6181291076e-3f);
    p = fmaf(p, f, 5.5504108665e-2f);
    p = fmaf(p, f, 2.4022650696e-1f);
    p = fmaf(p, f, 6.9314718056e-1f);
    p = fmaf(p, f, 1.0f);
    return __int_as_float(__float_as_int(p) + (int)((unsigned)ni << 23));
}

#define CP16(s, g) \
    asm volatile("cp.async.cg.shared.global [%0], [%1], 16;" :: "r"(s), "l"(g))
#define CP_COMMIT() asm volatile("cp.async.commit_group;" ::: "memory")
#define CP_WAIT2()  asm volatile("cp.async.wait_group 2;" ::: "memory")

#define MMA_BF16(c, a, b) \
    asm volatile("mma.sync.aligned.m16n8k16.row.col.f32.bf16.bf16.f32 " \
        "{%0,%1,%2,%3},{%4,%5,%6,%7},{%8,%9},{%0,%1,%2,%3};" \
        : "+f"((c)[0]), "+f"((c)[1]), "+f"((c)[2]), "+f"((c)[3]) \
        : "r"((a)[0]), "r"((a)[1]), "r"((a)[2]), "r"((a)[3]), \
          "r"((b)[0]), "r"((b)[1]))

// ---------------------------------------------------------------------------
// Prepass 1: x -> packed-split (in: float4 = 2 pairs, out: uint4)
// ---------------------------------------------------------------------------
__global__ void split_kernel(const float4* __restrict__ src,
                             uint4* __restrict__ dst, int n4)
{
    int i = blockIdx.x * blockDim.x + threadIdx.x;
    if (i < n4) {
        float4 v = src[i];
        uint4 o;
        split_pair(v.x, v.y, o.x, o.y);
        split_pair(v.z, v.w, o.z, o.w);
        dst[i] = o;
    }
}

// ---------------------------------------------------------------------------
// Prepass 2: W[K,N] -> Bt[N][K] packed-split
// ---------------------------------------------------------------------------
__global__ void transpose_split_kernel(const float* __restrict__ w,
                                       unsigned char* __restrict__ bt,
                                       int Kd, int Nd)
{
    __shared__ float t[32][33];   // t[k][n]
    int n0 = blockIdx.x * 32, k0 = blockIdx.y * 32;
    int tx = threadIdx.x, ty = threadIdx.y;   // (32, 8)
#pragma unroll
    for (int i = 0; i < 32; i += 8)
        t[ty + i][tx] = w[(size_t)(k0 + ty + i) * Nd + n0 + tx];
    __syncthreads();
    int tid = ty * 32 + tx;
    int po = tid & 15;            // k-pair 0..15
    int nl = tid >> 4;            // 0..15 (+16)
#pragma unroll
    for (int half = 0; half < 2; half++) {
        int n_loc = nl + half * 16;
        float v0 = t[2 * po][n_loc];
        float v1 = t[2 * po + 1][n_loc];
        uint2 o;
        split_pair(v0, v1, o.x, o.y);
        *(uint2*)(bt + (size_t)(n0 + n_loc) * Kd * 4 + (size_t)(k0 / 2 + po) * 8) = o;
    }
}

// ---------------------------------------------------------------------------
// bf16 3-term mma.sync GEMM: C[M,N] = A[M,K] @ B^T + bias
// A, B in packed-split layout (row stride K*4 bytes).
// CTA 128x128, 256 thr (8 warps, 2m x 4n), k-chunk 16, 4-stage cp.async.
// mode 0: QKV scatter (q->qout fp32, k/v->present fp32). mode 1: plain C.
// ---------------------------------------------------------------------------
#define GSTAGE 20480      // A 128*80 + B 128*80
#define GSMEM  (4 * GSTAGE)

__global__ __launch_bounds__(256, 1) void bf16_gemm_kernel(
    const unsigned char* __restrict__ Ag, const unsigned char* __restrict__ Bg,
    const float* __restrict__ bias,
    float* __restrict__ Cout, float* __restrict__ qout,
    float* __restrict__ present, int K, int N, int mode)
{
    extern __shared__ char smem[];
    const uint32_t smem_u = smem_to_u32(smem);
    const int tid = threadIdx.x;
    const int lane = tid & 31, wid = tid >> 5;
    const int wm = wid & 1, wn = wid >> 1;
    const int rowBase = blockIdx.y * 128, colBase = blockIdx.x * 128;
    const size_t Arow = (size_t)K * 4, Brow = (size_t)K * 4;
    const int NCH = K >> 4;

    // per-thread load slots: row r = tid/2, parts {0,1} or {2,3}
    const int ldr = tid >> 1;
    const int ldp = (tid & 1) * 2;
    const unsigned char* gA = Ag + (size_t)(rowBase + ldr) * Arow + ldp * 16;
    const unsigned char* gB = Bg + (size_t)(colBase + ldr) * Brow + ldp * 16;
    const uint32_t sA = smem_u + ldr * 80 + ldp * 16;
    const uint32_t sB = smem_u + 10240 + ldr * 80 + ldp * 16;

#define LOAD_STAGE(chunk, stg) do {                        \
        size_t go = (size_t)(chunk) * 64;                  \
        uint32_t so = (uint32_t)(stg) * GSTAGE;            \
        CP16(sA + so,      gA + go);                       \
        CP16(sA + so + 16, gA + go + 16);                  \
        CP16(sB + so,      gB + go);                       \
        CP16(sB + so + 16, gB + go + 16);                  \
    } while (0)

    float c[4][4][4];
#pragma unroll
    for (int i = 0; i < 4; i++)
#pragma unroll
        for (int j = 0; j < 4; j++)
#pragma unroll
            for (int r = 0; r < 4; r++) c[i][j][r] = 0.0f;

    LOAD_STAGE(0, 0); CP_COMMIT();
    LOAD_STAGE(1, 1); CP_COMMIT();
    LOAD_STAGE(2, 2); CP_COMMIT();

    const char* smem_c = smem;
    for (int ch = 0; ch < NCH; ch++) {
        CP_WAIT2();
        __syncthreads();
        const int s = ch & 3;
        const char* As = smem_c + s * GSTAGE;
        const char* Bs = As + 10240;

        uint32_t ah[4][4], al[4][4];
#pragma unroll
        for (int mf = 0; mf < 4; mf++) {
            int r = wm * 64 + mf * 16 + (lane >> 2);
            const char* p = As + r * 80 + (lane & 3) * 8;
            ah[mf][0] = *(const uint32_t*)(p);
            al[mf][0] = *(const uint32_t*)(p + 4);
            ah[mf][1] = *(const uint32_t*)(p + 8 * 80);
            al[mf][1] = *(const uint32_t*)(p + 8 * 80 + 4);
            ah[mf][2] = *(const uint32_t*)(p + 32);
            al[mf][2] = *(const uint32_t*)(p + 36);
            ah[mf][3] = *(const uint32_t*)(p + 8 * 80 + 32);
            al[mf][3] = *(const uint32_t*)(p + 8 * 80 + 36);
        }
        uint32_t bh[4][2], bl[4][2];
#pragma unroll
        for (int nf = 0; nf < 4; nf++) {
            int n = wn * 32 + nf * 8 + (lane >> 2);
            const char* p = Bs + n * 80 + (lane & 3) * 8;
            bh[nf][0] = *(const uint32_t*)(p);
            bl[nf][0] = *(const uint32_t*)(p + 4);
            bh[nf][1] = *(const uint32_t*)(p + 32);
            bl[nf][1] = *(const uint32_t*)(p + 36);
        }
#pragma unroll
        for (int mf = 0; mf < 4; mf++)
#pragma unroll
            for (int nf = 0; nf < 4; nf++) {
                MMA_BF16(c[mf][nf], ah[mf], bh[nf]);
                MMA_BF16(c[mf][nf], ah[mf], bl[nf]);
                MMA_BF16(c[mf][nf], al[mf], bh[nf]);
            }
        __syncthreads();
        if (ch + 3 < NCH) LOAD_STAGE(ch + 3, (ch + 3) & 3);
        CP_COMMIT();
    }

    // Epilogue: direct stores (pairs of consecutive n)
#pragma unroll
    for (int mf = 0; mf < 4; mf++) {
#pragma unroll
        for (int nf = 0; nf < 4; nf++) {
            int m0 = rowBase + wm * 64 + mf * 16 + (lane >> 2);
            int n  = colBase + wn * 32 + nf * 8 + (lane & 3) * 2;
            float b0 = bias[n], b1 = bias[n + 1];
#pragma unroll
            for (int half = 0; half < 2; half++) {
                int m = m0 + half * 8;
                float2 v;
                v.x = c[mf][nf][half * 2 + 0] + b0;
                v.y = c[mf][nf][half * 2 + 1] + b1;
                if (mode == 1) {
                    *(float2*)&Cout[(size_t)m * N + n] = v;
                } else {
                    if (n < DD) {
                        *(float2*)&qout[(size_t)m * DD + n] = v;
                    } else {
                        int seg = n >> 10;
                        int nn = n & 1023;
                        int h = nn >> 6, d = nn & 63;
                        int b = m >> 11, t = m & 2047;
                        float* dst = present
                                   + (seg == 2 ? (size_t)PRESENT_HALF : (size_t)0)
                                   + (((size_t)(b * HH + h)) * TT + t) * DHH + d;
                        *(float2*)dst = v;
                    }
                }
            }
        }
    }
}

// ---------------------------------------------------------------------------
// Flash attention (fp32 SIMT), exp on FMA pipe; epilogue -> packed-split bf16
// ---------------------------------------------------------------------------
#define QP 68

__global__ __launch_bounds__(256) void attn_kernel(
    const float* __restrict__ qbuf, const float* __restrict__ present,
    unsigned char* __restrict__ atts)
{
    extern __shared__ float fsm[];
    float* Qt = fsm;                   // [64][QP], Qt[kk][row]
    float* Kt = fsm + 64 * QP;         // [64][QP], reused as Pt
    float* Vs = fsm + 2 * 64 * QP;     // [64][64]

    const int tid = threadIdx.x;
    const int tx = tid & 15;
    const int ty = tid >> 4;
    const int qt = blockIdx.x;
    const int h  = blockIdx.y;
    const int b  = blockIdx.z;
    const int q0 = qt * 64;

    const int lr = tid >> 4;
    const int lc = tid & 15;

    {
        const float* baseq = qbuf + ((size_t)(b * TT + q0)) * DD + h * DHH;
#pragma unroll
        for (int it = 0; it < 4; it++) {
            int r = lr + it * 16;
            float4 qv = *(const float4*)(baseq + (size_t)r * DD + lc * 4);
            Qt[(lc * 4 + 0) * QP + r] = qv.x;
            Qt[(lc * 4 + 1) * QP + r] = qv.y;
            Qt[(lc * 4 + 2) * QP + r] = qv.z;
            Qt[(lc * 4 + 3) * QP + r] = qv.w;
        }
    }

    float acc_o[4][4];
#pragma unroll
    for (int i = 0; i < 4; i++)
#pragma unroll
        for (int j = 0; j < 4; j++) acc_o[i][j] = 0.0f;
    float m_i[4], l_i[4];
#pragma unroll
    for (int i = 0; i < 4; i++) { m_i[i] = -1e30f; l_i[i] = 0.0f; }

    const float* basek = present + ((size_t)(b * HH + h)) * TT * DHH;
    const float* basev = basek + (size_t)PRESENT_HALF;

    const int ntiles = qt + 1;
    for (int kt = 0; kt < ntiles; kt++) {
        const int k0 = kt * 64;
        __syncthreads();

#pragma unroll
        for (int it = 0; it < 4; it++) {
            int r = lr + it * 16;
            float4 kv = *(const float4*)(basek + (size_t)(k0 + r) * DHH + lc * 4);
            Kt[(lc * 4 + 0) * QP + r] = kv.x;
            Kt[(lc * 4 + 1) * QP + r] = kv.y;
            Kt[(lc * 4 + 2) * QP + r] = kv.z;
            Kt[(lc * 4 + 3) * QP + r] = kv.w;
            float4 vv = *(const float4*)(basev + (size_t)(k0 + r) * DHH + lc * 4);
            *(float4*)(&Vs[r * 64 + lc * 4]) = vv;
        }
        __syncthreads();

        float s[4][4];
#pragma unroll
        for (int i = 0; i < 4; i++)
#pragma unroll
            for (int j = 0; j < 4; j++) s[i][j] = 0.0f;

#pragma unroll 16
        for (int kk = 0; kk < 64; kk++) {
            float4 qv = *(const float4*)(&Qt[kk * QP + ty * 4]);
            float4 kv = *(const float4*)(&Kt[kk * QP + tx * 4]);
            float qa[4] = {qv.x, qv.y, qv.z, qv.w};
            float ka[4] = {kv.x, kv.y, kv.z, kv.w};
#pragma unroll
            for (int i = 0; i < 4; i++)
#pragma unroll
                for (int j = 0; j < 4; j++)
                    s[i][j] = fmaf(qa[i], ka[j], s[i][j]);
        }

        const bool diag = (k0 == q0);
#pragma unroll
        for (int i = 0; i < 4; i++) {
#pragma unroll
            for (int j = 0; j < 4; j++) {
                float sv = s[i][j] * 0.25f;
                if (diag && (k0 + tx * 4 + j) > (q0 + ty * 4 + i)) sv = -1e30f;
                s[i][j] = sv;
            }
        }

        float p[4][4];
#pragma unroll
        for (int i = 0; i < 4; i++) {
            float rm = fmaxf(fmaxf(s[i][0], s[i][1]), fmaxf(s[i][2], s[i][3]));
#pragma unroll
            for (int off = 8; off >= 1; off >>= 1)
                rm = fmaxf(rm, __shfl_xor_sync(0xffffffffu, rm, off));
            float mn = fmaxf(m_i[i], rm);
            float alpha = fast_exp(m_i[i] - mn);
            float rs = 0.0f;
#pragma unroll
            for (int j = 0; j < 4; j++) {
                float pv = fast_exp(s[i][j] - mn);
                p[i][j] = pv;
                rs += pv;
            }
#pragma unroll
            for (int off = 8; off >= 1; off >>= 1)
                rs += __shfl_xor_sync(0xffffffffu, rs, off);
            l_i[i] = l_i[i] * alpha + rs;
            m_i[i] = mn;
#pragma unroll
            for (int j = 0; j < 4; j++) acc_o[i][j] *= alpha;
        }

        __syncthreads();
#pragma unroll
        for (int i = 0; i < 4; i++)
#pragma unroll
            for (int j = 0; j < 4; j++)
                Kt[(tx * 4 + j) * QP + (ty * 4 + i)] = p[i][j];
        __syncthreads();

#pragma unroll 16
        for (int kk = 0; kk < 64; kk++) {
            float4 pv = *(const float4*)(&Kt[kk * QP + ty * 4]);
            float4 vv = *(const float4*)(&Vs[kk * 64 + tx * 4]);
            float pa[4] = {pv.x, pv.y, pv.z, pv.w};
            float va[4] = {vv.x, vv.y, vv.z, vv.w};
#pragma unroll
            for (int i = 0; i < 4; i++)
#pragma unroll
                for (int j = 0; j < 4; j++)
                    acc_o[i][j] = fmaf(pa[i], va[j], acc_o[i][j]);
        }
    }

    // epilogue: normalize, write packed-split bf16 (4 elems = 16B)
#pragma unroll
    for (int i = 0; i < 4; i++) {
        float inv = 1.0f / l_i[i];
        int qg = q0 + ty * 4 + i;
        int m = b * TT + qg;
        int col = h * DHH + tx * 4;
        float o0 = acc_o[i][0] * inv, o1 = acc_o[i][1] * inv;
        float o2 = acc_o[i][2] * inv, o3 = acc_o[i][3] * inv;
        uint4 w;
        split_pair(o0, o1, w.x, w.y);
        split_pair(o2, o3, w.z, w.w);
        *(uint4*)(atts + (size_t)m * DD * 4 + (size_t)col * 4) = w;
    }
}

// ---------------------------------------------------------------------------
extern "C" void kernel_launch(void* const* d_in, const int* in_sizes, int n_in,
                              void* d_out, int out_size)
{
    const float* x      = (const float*)d_in[0];
    const float* w_attn = (const float*)d_in[1];
    const float* b_attn = (const float*)d_in[2];
    const float* w_proj = (const float*)d_in[3];
    const float* b_proj = (const float*)d_in[4];

    float* out = (float*)d_out;
    float* a_out = out;
    float* present = out + (size_t)M_TOT * DD;

    unsigned char *xs, *bta, *btp, *atts;
    float *qp;
    cudaGetSymbolAddress((void**)&xs,   g_xs);
    cudaGetSymbolAddress((void**)&bta,  g_bta);
    cudaGetSymbolAddress((void**)&btp,  g_btp);
    cudaGetSymbolAddress((void**)&qp,   g_q);
    cudaGetSymbolAddress((void**)&atts, g_atts);

    const int smem_attn = (2 * 64 * QP + 64 * 64) * 4;  // 51200
    cudaFuncSetAttribute(attn_kernel,
                         cudaFuncAttributeMaxDynamicSharedMemorySize, smem_attn);
    cudaFuncSetAttribute(bf16_gemm_kernel,
                         cudaFuncAttributeMaxDynamicSharedMemorySize, GSMEM);

    // Prepasses
    split_kernel<<<(M_TOT * DD / 4 + 255) / 256, 256>>>(
        (const float4*)x, (uint4*)xs, M_TOT * DD / 4);
    transpose_split_kernel<<<dim3(3 * DD / 32, DD / 32), dim3(32, 8)>>>(
        w_attn, bta, DD, 3 * DD);
    transpose_split_kernel<<<dim3(DD / 32, DD / 32), dim3(32, 8)>>>(
        w_proj, btp, DD, DD);

    // QKV GEMM -> g_q + present
    bf16_gemm_kernel<<<dim3(3 * DD / 128, M_TOT / 128), 256, GSMEM>>>(
        xs, bta, b_attn, nullptr, qp, present, DD, 3 * DD, 0);

    // Attention -> g_atts (packed split)
    attn_kernel<<<dim3(TT / 64, HH, BB), 256, smem_attn>>>(qp, present, atts);

    // Projection GEMM -> a_out
    bf16_gemm_kernel<<<dim3(DD / 128, M_TOT / 128), 256, GSMEM>>>(
        atts, btp, b_proj, a_out, nullptr, nullptr, DD, DD, 1);
}

// round 5
// speedup vs baseline: 2.0539x; 1.4922x over previous
#include <cuda_runtime.h>
#include <cuda_bf16.h>
#include <cstdint>

// Problem constants
#define BB 2
#define TT 2048
#define DD 1024
#define HH 16
#define DHH 64
#define M_TOT (BB*TT)                 // 4096
#define PRESENT_HALF (BB*HH*TT*DHH)   // 4194304
#define PLANE ((size_t)BB*HH*TT*DHH)  // elements per hi/lo plane

// ---------------------------------------------------------------------------
// Device-global scratch.
// Packed-split GEMM layout: per k-pair 8B: [hi(2k),hi(2k+1),lo(2k),lo(2k+1)]
// Head-major split planes: [hi plane | lo plane], each [B][H][T][64] bf16
// ---------------------------------------------------------------------------
__device__ unsigned char g_xs[(size_t)M_TOT * DD * 4];
__device__ unsigned char g_bta[(size_t)3 * DD * DD * 4];
__device__ unsigned char g_btp[(size_t)DD * DD * 4];
__device__ __nv_bfloat16 g_qs[2 * PLANE];
__device__ __nv_bfloat16 g_ks[2 * PLANE];
__device__ __nv_bfloat16 g_vs[2 * PLANE];
__device__ unsigned char g_atts[(size_t)M_TOT * DD * 4];

// ---------------------------------------------------------------------------
// Helpers
// ---------------------------------------------------------------------------
__device__ __forceinline__ uint32_t smem_to_u32(const void* smem_ptr) {
    uint32_t addr;
    asm("{ .reg .u64 tmp; cvta.to.shared.u64 tmp, %1; cvt.u32.u64 %0, tmp; }"
        : "=r"(addr) : "l"(smem_ptr));
    return addr;
}

__device__ __forceinline__ uint32_t pack2bf(float a, float b) {
    __nv_bfloat162 t = __floats2bfloat162_rn(a, b);
    return *reinterpret_cast<uint32_t*>(&t);
}

__device__ __forceinline__ void split_pair(float a, float b,
                                           uint32_t& wh, uint32_t& wl) {
    __nv_bfloat16 ha = __float2bfloat16_rn(a);
    __nv_bfloat16 hb = __float2bfloat16_rn(b);
    float la = a - __bfloat162float(ha);
    float lb = b - __bfloat162float(hb);
    wh = ((uint32_t)__bfloat16_as_ushort(hb) << 16) | __bfloat16_as_ushort(ha);
    wl = pack2bf(la, lb);
}

__device__ __forceinline__ float fast_exp(float x) {
    x = fmaxf(x, -87.0f);
    float t = fmaf(x, 1.4426950408889634f, 12582912.0f);
    int   ni = __float_as_int(t);
    float n = t - 12582912.0f;
    float f = fmaf(x, 1.4426950408889634f, -n);
    float p = 1.3333558146e-3f;
    p = fmaf(p, f, 9.6181291076e-3f);
    p = fmaf(p, f, 5.5504108665e-2f);
    p = fmaf(p, f, 2.4022650696e-1f);
    p = fmaf(p, f, 6.9314718056e-1f);
    p = fmaf(p, f, 1.0f);
    return __int_as_float(__float_as_int(p) + (int)((unsigned)ni << 23));
}

#define CP16(s, g) \
    asm volatile("cp.async.cg.shared.global [%0], [%1], 16;" :: "r"(s), "l"(g))
#define CP_COMMIT() asm volatile("cp.async.commit_group;" ::: "memory")
#define CP_WAIT1()  asm volatile("cp.async.wait_group 1;" ::: "memory")
#define CP_WAIT2()  asm volatile("cp.async.wait_group 2;" ::: "memory")

#define MMA_BF16(c, a, b) \
    asm volatile("mma.sync.aligned.m16n8k16.row.col.f32.bf16.bf16.f32 " \
        "{%0,%1,%2,%3},{%4,%5,%6,%7},{%8,%9},{%0,%1,%2,%3};" \
        : "+f"((c)[0]), "+f"((c)[1]), "+f"((c)[2]), "+f"((c)[3]) \
        : "r"((a)[0]), "r"((a)[1]), "r"((a)[2]), "r"((a)[3]), \
          "r"((b)[0]), "r"((b)[1]))

#define LDMX4(R, addr) \
    asm volatile("ldmatrix.sync.aligned.m8n8.x4.shared.b16 {%0,%1,%2,%3}, [%4];" \
        : "=r"((R)[0]), "=r"((R)[1]), "=r"((R)[2]), "=r"((R)[3]) : "r"(addr))

#define LDMX4T(R, addr) \
    asm volatile("ldmatrix.sync.aligned.m8n8.x4.trans.shared.b16 {%0,%1,%2,%3}, [%4];" \
        : "=r"((R)[0]), "=r"((R)[1]), "=r"((R)[2]), "=r"((R)[3]) : "r"(addr))

// ---------------------------------------------------------------------------
// Prepass 1: x -> packed-split
// ---------------------------------------------------------------------------
__global__ void split_kernel(const float4* __restrict__ src,
                             uint4* __restrict__ dst, int n4)
{
    int i = blockIdx.x * blockDim.x + threadIdx.x;
    if (i < n4) {
        float4 v = src[i];
        uint4 o;
        split_pair(v.x, v.y, o.x, o.y);
        split_pair(v.z, v.w, o.z, o.w);
        dst[i] = o;
    }
}

// ---------------------------------------------------------------------------
// Prepass 2: W[K,N] -> Bt[N][K] packed-split
// ---------------------------------------------------------------------------
__global__ void transpose_split_kernel(const float* __restrict__ w,
                                       unsigned char* __restrict__ bt,
                                       int Kd, int Nd)
{
    __shared__ float t[32][33];
    int n0 = blockIdx.x * 32, k0 = blockIdx.y * 32;
    int tx = threadIdx.x, ty = threadIdx.y;
#pragma unroll
    for (int i = 0; i < 32; i += 8)
        t[ty + i][tx] = w[(size_t)(k0 + ty + i) * Nd + n0 + tx];
    __syncthreads();
    int tid = ty * 32 + tx;
    int po = tid & 15;
    int nl = tid >> 4;
#pragma unroll
    for (int half = 0; half < 2; half++) {
        int n_loc = nl + half * 16;
        float v0 = t[2 * po][n_loc];
        float v1 = t[2 * po + 1][n_loc];
        uint2 o;
        split_pair(v0, v1, o.x, o.y);
        *(uint2*)(bt + (size_t)(n0 + n_loc) * Kd * 4 + (size_t)(k0 / 2 + po) * 8) = o;
    }
}

// ---------------------------------------------------------------------------
// bf16 3-term mma.sync GEMM (as R4, with uint2 fragment loads)
// mode 0: QKV -> split planes (q,k,v) + fp32 present. mode 1: plain C.
// ---------------------------------------------------------------------------
#define GSTAGE 20480
#define GSMEM  (4 * GSTAGE)

__global__ __launch_bounds__(256, 1) void bf16_gemm_kernel(
    const unsigned char* __restrict__ Ag, const unsigned char* __restrict__ Bg,
    const float* __restrict__ bias,
    float* __restrict__ Cout,
    __nv_bfloat16* __restrict__ qsp, __nv_bfloat16* __restrict__ ksp,
    __nv_bfloat16* __restrict__ vsp,
    float* __restrict__ present, int K, int N, int mode)
{
    extern __shared__ char smem[];
    const uint32_t smem_u = smem_to_u32(smem);
    const int tid = threadIdx.x;
    const int lane = tid & 31, wid = tid >> 5;
    const int wm = wid & 1, wn = wid >> 1;
    const int rowBase = blockIdx.y * 128, colBase = blockIdx.x * 128;
    const size_t Arow = (size_t)K * 4, Brow = (size_t)K * 4;
    const int NCH = K >> 4;

    const int ldr = tid >> 1;
    const int ldp = (tid & 1) * 2;
    const unsigned char* gA = Ag + (size_t)(rowBase + ldr) * Arow + ldp * 16;
    const unsigned char* gB = Bg + (size_t)(colBase + ldr) * Brow + ldp * 16;
    const uint32_t sA = smem_u + ldr * 80 + ldp * 16;
    const uint32_t sB = smem_u + 10240 + ldr * 80 + ldp * 16;

#define LOAD_STAGE(chunk, stg) do {                        \
        size_t go = (size_t)(chunk) * 64;                  \
        uint32_t so = (uint32_t)(stg) * GSTAGE;            \
        CP16(sA + so,      gA + go);                       \
        CP16(sA + so + 16, gA + go + 16);                  \
        CP16(sB + so,      gB + go);                       \
        CP16(sB + so + 16, gB + go + 16);                  \
    } while (0)

    float c[4][4][4];
#pragma unroll
    for (int i = 0; i < 4; i++)
#pragma unroll
        for (int j = 0; j < 4; j++)
#pragma unroll
            for (int r = 0; r < 4; r++) c[i][j][r] = 0.0f;

    LOAD_STAGE(0, 0); CP_COMMIT();
    LOAD_STAGE(1, 1); CP_COMMIT();
    LOAD_STAGE(2, 2); CP_COMMIT();

    const char* smem_c = smem;
    for (int ch = 0; ch < NCH; ch++) {
        CP_WAIT2();
        __syncthreads();
        const int s = ch & 3;
        const char* As = smem_c + s * GSTAGE;
        const char* Bs = As + 10240;

        uint32_t ah[4][4], al[4][4];
#pragma unroll
        for (int mf = 0; mf < 4; mf++) {
            int r = wm * 64 + mf * 16 + (lane >> 2);
            const char* p = As + r * 80 + (lane & 3) * 8;
            uint2 t0 = *(const uint2*)(p);
            uint2 t1 = *(const uint2*)(p + 8 * 80);
            uint2 t2 = *(const uint2*)(p + 32);
            uint2 t3 = *(const uint2*)(p + 8 * 80 + 32);
            ah[mf][0] = t0.x; al[mf][0] = t0.y;
            ah[mf][1] = t1.x; al[mf][1] = t1.y;
            ah[mf][2] = t2.x; al[mf][2] = t2.y;
            ah[mf][3] = t3.x; al[mf][3] = t3.y;
        }
        uint32_t bh[4][2], bl[4][2];
#pragma unroll
        for (int nf = 0; nf < 4; nf++) {
            int n = wn * 32 + nf * 8 + (lane >> 2);
            const char* p = Bs + n * 80 + (lane & 3) * 8;
            uint2 t0 = *(const uint2*)(p);
            uint2 t1 = *(const uint2*)(p + 32);
            bh[nf][0] = t0.x; bl[nf][0] = t0.y;
            bh[nf][1] = t1.x; bl[nf][1] = t1.y;
        }
#pragma unroll
        for (int mf = 0; mf < 4; mf++)
#pragma unroll
            for (int nf = 0; nf < 4; nf++) {
                MMA_BF16(c[mf][nf], ah[mf], bh[nf]);
                MMA_BF16(c[mf][nf], ah[mf], bl[nf]);
                MMA_BF16(c[mf][nf], al[mf], bh[nf]);
            }
        __syncthreads();
        if (ch + 3 < NCH) LOAD_STAGE(ch + 3, (ch + 3) & 3);
        CP_COMMIT();
    }

    // Epilogue
#pragma unroll
    for (int mf = 0; mf < 4; mf++) {
#pragma unroll
        for (int nf = 0; nf < 4; nf++) {
            int m0 = rowBase + wm * 64 + mf * 16 + (lane >> 2);
            int n  = colBase + wn * 32 + nf * 8 + (lane & 3) * 2;
            float b0 = bias[n], b1 = bias[n + 1];
#pragma unroll
            for (int half = 0; half < 2; half++) {
                int m = m0 + half * 8;
                float2 v;
                v.x = c[mf][nf][half * 2 + 0] + b0;
                v.y = c[mf][nf][half * 2 + 1] + b1;
                if (mode == 1) {
                    *(float2*)&Cout[(size_t)m * N + n] = v;
                } else {
                    int seg = n >> 10, nn = n & 1023;
                    int hh = nn >> 6, d = nn & 63;
                    int bb = m >> 11, t = m & 2047;
                    size_t idx = (((size_t)(bb * HH + hh)) * TT + t) * DHH + d;
                    uint32_t wh, wl;
                    split_pair(v.x, v.y, wh, wl);
                    if (seg == 0) {
                        *(uint32_t*)&qsp[idx] = wh;
                        *(uint32_t*)&qsp[PLANE + idx] = wl;
                    } else if (seg == 1) {
                        *(float2*)&present[idx] = v;
                        *(uint32_t*)&ksp[idx] = wh;
                        *(uint32_t*)&ksp[PLANE + idx] = wl;
                    } else {
                        *(float2*)&present[PRESENT_HALF + idx] = v;
                        *(uint32_t*)&vsp[idx] = wh;
                        *(uint32_t*)&vsp[PLANE + idx] = wl;
                    }
                }
            }
        }
    }
}

// ---------------------------------------------------------------------------
// Flash attention on tensor cores (bf16 3-term mma).
// Block: 64 q-rows x 64 k-cols, 4 warps, 128 threads.
// smem row stride 72 bf16 (144 B) -> conflict-free ldmatrix.
// ---------------------------------------------------------------------------
#define ASTRIDE 144              // bytes per smem row
#define ABYTES  (64 * ASTRIDE)   // 9216 B per plane
#define ATT_SMEM (2 * ABYTES + 2 * 4 * ABYTES)  // Q(2) + 2 stages x 4 planes

__device__ __forceinline__ void att_load_stage(
    uint32_t dst, const __nv_bfloat16* kh_g, const __nv_bfloat16* kl_g,
    const __nv_bfloat16* vh_g, const __nv_bfloat16* vl_g, int k0, int tid)
{
    int r = tid >> 1;
    int cb = (tid & 1) * 64;
    const char* skh = (const char*)(kh_g + (size_t)(k0 + r) * DHH) + cb;
    const char* skl = (const char*)(kl_g + (size_t)(k0 + r) * DHH) + cb;
    const char* svh = (const char*)(vh_g + (size_t)(k0 + r) * DHH) + cb;
    const char* svl = (const char*)(vl_g + (size_t)(k0 + r) * DHH) + cb;
    uint32_t d0 = dst + r * ASTRIDE + cb;
#pragma unroll
    for (int i = 0; i < 4; i++) {
        CP16(d0 + i * 16,              skh + i * 16);
        CP16(d0 + ABYTES + i * 16,     skl + i * 16);
        CP16(d0 + 2 * ABYTES + i * 16, svh + i * 16);
        CP16(d0 + 3 * ABYTES + i * 16, svl + i * 16);
    }
}

__global__ __launch_bounds__(128) void attn_mma_kernel(
    const __nv_bfloat16* __restrict__ qs, const __nv_bfloat16* __restrict__ ks,
    const __nv_bfloat16* __restrict__ vs, unsigned char* __restrict__ atts)
{
    extern __shared__ char sm[];
    const uint32_t su = smem_to_u32(sm);
    const int tid = threadIdx.x, lane = tid & 31, w = tid >> 5;
    const int qt = blockIdx.x, h = blockIdx.y, b = blockIdx.z;
    const int q0 = qt * 64;
    const size_t headoff = ((size_t)(b * HH + h)) * TT * DHH;

    const uint32_t sQh = su;
    const uint32_t sQl = su + ABYTES;
    const uint32_t sStg = su + 2 * ABYTES;

    const __nv_bfloat16* qh_g = qs + headoff;
    const __nv_bfloat16* ql_g = qs + PLANE + headoff;
    const __nv_bfloat16* kh_g = ks + headoff;
    const __nv_bfloat16* kl_g = ks + PLANE + headoff;
    const __nv_bfloat16* vh_g = vs + headoff;
    const __nv_bfloat16* vl_g = vs + PLANE + headoff;

    // preload Q + stage 0
    {
        int r = tid >> 1;
        int cb = (tid & 1) * 64;
        const char* sh = (const char*)(qh_g + (size_t)(q0 + r) * DHH) + cb;
        const char* sl = (const char*)(ql_g + (size_t)(q0 + r) * DHH) + cb;
        uint32_t dh_ = sQh + r * ASTRIDE + cb;
        uint32_t dl_ = sQl + r * ASTRIDE + cb;
#pragma unroll
        for (int i = 0; i < 4; i++) {
            CP16(dh_ + i * 16, sh + i * 16);
            CP16(dl_ + i * 16, sl + i * 16);
        }
        att_load_stage(sStg, kh_g, kl_g, vh_g, vl_g, 0, tid);
    }
    CP_COMMIT();

    uint32_t qfh[4][4], qfl[4][4];
    float co[8][4];
#pragma unroll
    for (int j = 0; j < 8; j++)
#pragma unroll
        for (int e = 0; e < 4; e++) co[j][e] = 0.0f;
    float mi[2] = {-1e30f, -1e30f}, li[2] = {0.0f, 0.0f};

    const int r0 = lane >> 2;
    const int cbase = 2 * (lane & 3);

    for (int kt = 0; kt <= qt; kt++) {
        const int s = kt & 1;
        if (kt < qt)
            att_load_stage(sStg + (s ^ 1) * 4 * ABYTES, kh_g, kl_g, vh_g, vl_g,
                           (kt + 1) * 64, tid);
        CP_COMMIT();
        CP_WAIT1();
        __syncthreads();

        if (kt == 0) {
            // Q fragments (A operand, 4 ksteps over d)
            int row = (w << 4) + (lane & 15);
            int colb = ((lane >> 4) << 3);
#pragma unroll
            for (int t = 0; t < 4; t++) {
                LDMX4(qfh[t], sQh + row * ASTRIDE + (t * 16 + colb) * 2);
                LDMX4(qfl[t], sQl + row * ASTRIDE + (t * 16 + colb) * 2);
            }
        }

        const uint32_t bKh = sStg + s * 4 * ABYTES;
        const uint32_t bKl = bKh + ABYTES;
        const uint32_t bVh = bKh + 2 * ABYTES;
        const uint32_t bVl = bKh + 3 * ABYTES;

        // ---- S = Q K^T (3-term) ----
        float cs[8][4];
#pragma unroll
        for (int j = 0; j < 8; j++)
#pragma unroll
            for (int e = 0; e < 4; e++) cs[j][e] = 0.0f;

#pragma unroll
        for (int j = 0; j < 8; j++) {
            int rowa = j * 8 + (lane & 7);
#pragma unroll
            for (int u = 0; u < 2; u++) {
                int cola = u * 32 + ((lane >> 3) << 3);
                uint32_t kh[4], kl[4];
                LDMX4(kh, bKh + rowa * ASTRIDE + cola * 2);
                LDMX4(kl, bKl + rowa * ASTRIDE + cola * 2);
                MMA_BF16(cs[j], qfh[2 * u],     kh);
                MMA_BF16(cs[j], qfh[2 * u],     kl);
                MMA_BF16(cs[j], qfl[2 * u],     kh);
                MMA_BF16(cs[j], qfh[2 * u + 1], kh + 2);
                MMA_BF16(cs[j], qfh[2 * u + 1], kl + 2);
                MMA_BF16(cs[j], qfl[2 * u + 1], kh + 2);
            }
        }

        // ---- scale + causal mask ----
        if (kt == qt) {
#pragma unroll
            for (int j = 0; j < 8; j++)
#pragma unroll
                for (int e = 0; e < 4; e++) {
                    int col = j * 8 + cbase + (e & 1);
                    int row = (w << 4) + r0 + 8 * (e >> 1);
                    float sv = cs[j][e] * 0.25f;
                    cs[j][e] = (col > row) ? -1e30f : sv;
                }
        } else {
#pragma unroll
            for (int j = 0; j < 8; j++)
#pragma unroll
                for (int e = 0; e < 4; e++) cs[j][e] *= 0.25f;
        }

        // ---- online softmax ----
#pragma unroll
        for (int half = 0; half < 2; half++) {
            float mx = -1e30f;
#pragma unroll
            for (int j = 0; j < 8; j++)
                mx = fmaxf(mx, fmaxf(cs[j][2 * half], cs[j][2 * half + 1]));
            mx = fmaxf(mx, __shfl_xor_sync(0xffffffffu, mx, 1));
            mx = fmaxf(mx, __shfl_xor_sync(0xffffffffu, mx, 2));
            float mn = fmaxf(mi[half], mx);
            float alpha = fast_exp(mi[half] - mn);
            mi[half] = mn;
            float rs = 0.0f;
#pragma unroll
            for (int j = 0; j < 8; j++) {
                float p0 = fast_exp(cs[j][2 * half]     - mn);
                float p1 = fast_exp(cs[j][2 * half + 1] - mn);
                cs[j][2 * half] = p0;
                cs[j][2 * half + 1] = p1;
                rs += p0 + p1;
            }
            rs += __shfl_xor_sync(0xffffffffu, rs, 1);
            rs += __shfl_xor_sync(0xffffffffu, rs, 2);
            li[half] = li[half] * alpha + rs;
#pragma unroll
            for (int j = 0; j < 8; j++) {
                co[j][2 * half]     *= alpha;
                co[j][2 * half + 1] *= alpha;
            }
        }

        // ---- pack P into A-fragments (hi/lo) ----
        uint32_t pfh[4][4], pfl[4][4];
#pragma unroll
        for (int t = 0; t < 4; t++)
#pragma unroll
            for (int sub = 0; sub < 2; sub++) {
                int j = 2 * t + sub;
                split_pair(cs[j][0], cs[j][1], pfh[t][sub * 2 + 0], pfl[t][sub * 2 + 0]);
                split_pair(cs[j][2], cs[j][3], pfh[t][sub * 2 + 1], pfl[t][sub * 2 + 1]);
            }

        // ---- O += P V (3-term) ----
#pragma unroll
        for (int t = 0; t < 4; t++) {
            int rowv = t * 16 + (lane & 7) + ((lane >> 3) & 1) * 8;
#pragma unroll
            for (int np = 0; np < 4; np++) {
                int colv = np * 16 + ((lane >> 4) << 3);
                uint32_t vh[4], vl[4];
                LDMX4T(vh, bVh + rowv * ASTRIDE + colv * 2);
                LDMX4T(vl, bVl + rowv * ASTRIDE + colv * 2);
                MMA_BF16(co[2 * np],     pfh[t], vh);
                MMA_BF16(co[2 * np],     pfh[t], vl);
                MMA_BF16(co[2 * np],     pfl[t], vh);
                MMA_BF16(co[2 * np + 1], pfh[t], vh + 2);
                MMA_BF16(co[2 * np + 1], pfh[t], vl + 2);
                MMA_BF16(co[2 * np + 1], pfl[t], vh + 2);
            }
        }
        __syncthreads();
    }

    // ---- epilogue: normalize, write packed-split for proj GEMM ----
    float inv0 = 1.0f / li[0], inv1 = 1.0f / li[1];
#pragma unroll
    for (int j = 0; j < 8; j++) {
#pragma unroll
        for (int half = 0; half < 2; half++) {
            float inv = half ? inv1 : inv0;
            int row = (w << 4) + r0 + 8 * half;
            int m = b * TT + q0 + row;
            int col = h * DHH + j * 8 + cbase;
            uint2 o;
            split_pair(co[j][2 * half] * inv, co[j][2 * half + 1] * inv, o.x, o.y);
            *(uint2*)(atts + (size_t)m * DD * 4 + (size_t)col * 4) = o;
        }
    }
}

// ---------------------------------------------------------------------------
extern "C" void kernel_launch(void* const* d_in, const int* in_sizes, int n_in,
                              void* d_out, int out_size)
{
    const float* x      = (const float*)d_in[0];
    const float* w_attn = (const float*)d_in[1];
    const float* b_attn = (const float*)d_in[2];
    const float* w_proj = (const float*)d_in[3];
    const float* b_proj = (const float*)d_in[4];

    float* out = (float*)d_out;
    float* a_out = out;
    float* present = out + (size_t)M_TOT * DD;

    unsigned char *xs, *bta, *btp, *atts;
    __nv_bfloat16 *qsp, *ksp, *vsp;
    cudaGetSymbolAddress((void**)&xs,   g_xs);
    cudaGetSymbolAddress((void**)&bta,  g_bta);
    cudaGetSymbolAddress((void**)&btp,  g_btp);
    cudaGetSymbolAddress((void**)&atts, g_atts);
    cudaGetSymbolAddress((void**)&qsp,  g_qs);
    cudaGetSymbolAddress((void**)&ksp,  g_ks);
    cudaGetSymbolAddress((void**)&vsp,  g_vs);

    cudaFuncSetAttribute(bf16_gemm_kernel,
                         cudaFuncAttributeMaxDynamicSharedMemorySize, GSMEM);
    cudaFuncSetAttribute(attn_mma_kernel,
                         cudaFuncAttributeMaxDynamicSharedMemorySize, ATT_SMEM);

    // Prepasses
    split_kernel<<<(M_TOT * DD / 4 + 255) / 256, 256>>>(
        (const float4*)x, (uint4*)xs, M_TOT * DD / 4);
    transpose_split_kernel<<<dim3(3 * DD / 32, DD / 32), dim3(32, 8)>>>(
        w_attn, bta, DD, 3 * DD);
    transpose_split_kernel<<<dim3(DD / 32, DD / 32), dim3(32, 8)>>>(
        w_proj, btp, DD, DD);

    // QKV GEMM -> split planes + fp32 present
    bf16_gemm_kernel<<<dim3(3 * DD / 128, M_TOT / 128), 256, GSMEM>>>(
        xs, bta, b_attn, nullptr, qsp, ksp, vsp, present, DD, 3 * DD, 0);

    // Tensor-core flash attention -> g_atts (packed split)
    attn_mma_kernel<<<dim3(TT / 64, HH, BB), 128, ATT_SMEM>>>(
        qsp, ksp, vsp, atts);

    // Projection GEMM -> a_out
    bf16_gemm_kernel<<<dim3(DD / 128, M_TOT / 128), 256, GSMEM>>>(
        atts, btp, b_proj, a_out, nullptr, nullptr, nullptr, nullptr,
        DD, DD, 1);
}

// round 6
// speedup vs baseline: 2.3940x; 1.1656x over previous
#include <cuda_runtime.h>
#include <cuda_bf16.h>
#include <cstdint>

// Problem constants
#define BB 2
#define TT 2048
#define DD 1024
#define HH 16
#define DHH 64
#define M_TOT (BB*TT)                 // 4096
#define PRESENT_HALF (BB*HH*TT*DHH)   // 4194304
#define PLANE ((size_t)BB*HH*TT*DHH)  // elements per hi/lo plane

// ---------------------------------------------------------------------------
// Device-global scratch.
// GEMM operand layout ("interleaved packed-split"):
//   row-major [rows][K], row = K/16 chunks of 64B.
//   chunk = 8 k-pairs p0..p7 (pair = 2 k), stored [p0,p4,p1,p5,p2,p6,p3,p7],
//   each pair = 8B: [hi(2k),hi(2k+1) bf16 | lo(2k),lo(2k+1) bf16]
// Head-major split planes (attention operands): [hi|lo], each [B][H][T][64] bf16
// ---------------------------------------------------------------------------
__device__ unsigned char g_xs[(size_t)M_TOT * DD * 4];
__device__ unsigned char g_bta[(size_t)3 * DD * DD * 4];
__device__ unsigned char g_btp[(size_t)DD * DD * 4];
__device__ __nv_bfloat16 g_qs[2 * PLANE];
__device__ __nv_bfloat16 g_ks[2 * PLANE];
__device__ __nv_bfloat16 g_vs[2 * PLANE];
__device__ unsigned char g_atts[(size_t)M_TOT * DD * 4];

// ---------------------------------------------------------------------------
// Helpers
// ---------------------------------------------------------------------------
__device__ __forceinline__ uint32_t smem_to_u32(const void* smem_ptr) {
    uint32_t addr;
    asm("{ .reg .u64 tmp; cvta.to.shared.u64 tmp, %1; cvt.u32.u64 %0, tmp; }"
        : "=r"(addr) : "l"(smem_ptr));
    return addr;
}

__device__ __forceinline__ uint32_t pack2bf(float a, float b) {
    __nv_bfloat162 t = __floats2bfloat162_rn(a, b);
    return *reinterpret_cast<uint32_t*>(&t);
}

__device__ __forceinline__ void split_pair(float a, float b,
                                           uint32_t& wh, uint32_t& wl) {
    __nv_bfloat16 ha = __float2bfloat16_rn(a);
    __nv_bfloat16 hb = __float2bfloat16_rn(b);
    float la = a - __bfloat162float(ha);
    float lb = b - __bfloat162float(hb);
    wh = ((uint32_t)__bfloat16_as_ushort(hb) << 16) | __bfloat16_as_ushort(ha);
    wl = pack2bf(la, lb);
}

// byte offset of k-pair P within a row of the interleaved packed-split layout
__device__ __forceinline__ int pairoff(int P) {
    int ch = P >> 3, p = P & 7;
    return ch * 64 + (p & 3) * 16 + (p >> 2) * 8;
}

__device__ __forceinline__ float fast_exp(float x) {
    x = fmaxf(x, -87.0f);
    float t = fmaf(x, 1.4426950408889634f, 12582912.0f);
    int   ni = __float_as_int(t);
    float n = t - 12582912.0f;
    float f = fmaf(x, 1.4426950408889634f, -n);
    float p = 1.3333558146e-3f;
    p = fmaf(p, f, 9.6181291076e-3f);
    p = fmaf(p, f, 5.5504108665e-2f);
    p = fmaf(p, f, 2.4022650696e-1f);
    p = fmaf(p, f, 6.9314718056e-1f);
    p = fmaf(p, f, 1.0f);
    return __int_as_float(__float_as_int(p) + (int)((unsigned)ni << 23));
}

#define CP16(s, g) \
    asm volatile("cp.async.cg.shared.global [%0], [%1], 16;" :: "r"(s), "l"(g))
#define CP_COMMIT() asm volatile("cp.async.commit_group;" ::: "memory")
#define CP_WAIT1()  asm volatile("cp.async.wait_group 1;" ::: "memory")
#define CP_WAIT2()  asm volatile("cp.async.wait_group 2;" ::: "memory")

#define MMA_BF16(c, a, b) \
    asm volatile("mma.sync.aligned.m16n8k16.row.col.f32.bf16.bf16.f32 " \
        "{%0,%1,%2,%3},{%4,%5,%6,%7},{%8,%9},{%0,%1,%2,%3};" \
        : "+f"((c)[0]), "+f"((c)[1]), "+f"((c)[2]), "+f"((c)[3]) \
        : "r"((a)[0]), "r"((a)[1]), "r"((a)[2]), "r"((a)[3]), \
          "r"((b)[0]), "r"((b)[1]))

#define LDMX4(R, addr) \
    asm volatile("ldmatrix.sync.aligned.m8n8.x4.shared.b16 {%0,%1,%2,%3}, [%4];" \
        : "=r"((R)[0]), "=r"((R)[1]), "=r"((R)[2]), "=r"((R)[3]) : "r"(addr))

#define LDMX4T(R, addr) \
    asm volatile("ldmatrix.sync.aligned.m8n8.x4.trans.shared.b16 {%0,%1,%2,%3}, [%4];" \
        : "=r"((R)[0]), "=r"((R)[1]), "=r"((R)[2]), "=r"((R)[3]) : "r"(addr))

// ---------------------------------------------------------------------------
// Prepass 1: x -> interleaved packed-split (K = 1024 fixed)
// ---------------------------------------------------------------------------
__global__ void split_kernel(const float4* __restrict__ src,
                             unsigned char* __restrict__ dst, int n4)
{
    int i = blockIdx.x * blockDim.x + threadIdx.x;
    if (i < n4) {
        float4 v = src[i];
        int e = 4 * i;
        int row = e >> 10;
        int P0 = (e & 1023) >> 1;
        uint2 a, b;
        split_pair(v.x, v.y, a.x, a.y);
        split_pair(v.z, v.w, b.x, b.y);
        unsigned char* base = dst + (size_t)row * 4096 + pairoff(P0);
        *(uint2*)base = a;
        *(uint2*)(base + 16) = b;   // pair P0+1 (P0 even -> +16)
    }
}

// ---------------------------------------------------------------------------
// Prepass 2: W[K,N] -> Bt[N][K] interleaved packed-split
// ---------------------------------------------------------------------------
__global__ void transpose_split_kernel(const float* __restrict__ w,
                                       unsigned char* __restrict__ bt,
                                       int Kd, int Nd)
{
    __shared__ float t[32][33];
    int n0 = blockIdx.x * 32, k0 = blockIdx.y * 32;
    int tx = threadIdx.x, ty = threadIdx.y;
#pragma unroll
    for (int i = 0; i < 32; i += 8)
        t[ty + i][tx] = w[(size_t)(k0 + ty + i) * Nd + n0 + tx];
    __syncthreads();
    int tid = ty * 32 + tx;
    int po = tid & 15;
    int nl = tid >> 4;
#pragma unroll
    for (int half = 0; half < 2; half++) {
        int n_loc = nl + half * 16;
        float v0 = t[2 * po][n_loc];
        float v1 = t[2 * po + 1][n_loc];
        uint2 o;
        split_pair(v0, v1, o.x, o.y);
        *(uint2*)(bt + (size_t)(n0 + n_loc) * Kd * 4
                     + pairoff((k0 >> 1) + po)) = o;
    }
}

// ---------------------------------------------------------------------------
// bf16 3-term mma.sync GEMM. CTA 128x128, 256 thr, chunk 16k, 4-stage.
// Conflict-free LDS.128 fragment loads via interleaved layout, 64B rows.
// mode 0: QKV -> split planes + fp32 present. mode 1: plain C.
// ---------------------------------------------------------------------------
#define GSTAGE 16384      // A 128*64 + B 128*64
#define GSMEM  (4 * GSTAGE)

__global__ __launch_bounds__(256, 2) void bf16_gemm_kernel(
    const unsigned char* __restrict__ Ag, const unsigned char* __restrict__ Bg,
    const float* __restrict__ bias,
    float* __restrict__ Cout,
    __nv_bfloat16* __restrict__ qsp, __nv_bfloat16* __restrict__ ksp,
    __nv_bfloat16* __restrict__ vsp,
    float* __restrict__ present, int K, int N, int mode)
{
    extern __shared__ char smem[];
    const uint32_t smem_u = smem_to_u32(smem);
    const int tid = threadIdx.x;
    const int lane = tid & 31, wid = tid >> 5;
    const int wm = wid & 1, wn = wid >> 1;
    const int rowBase = blockIdx.y * 128, colBase = blockIdx.x * 128;
    const size_t Arow = (size_t)K * 4;
    const int NCH = K >> 4;

    const int ldr = tid >> 1;
    const int ldp = (tid & 1) * 2;
    const unsigned char* gA = Ag + (size_t)(rowBase + ldr) * Arow + ldp * 16;
    const unsigned char* gB = Bg + (size_t)(colBase + ldr) * Arow + ldp * 16;
    const uint32_t sA = smem_u + ldr * 64 + ldp * 16;
    const uint32_t sB = smem_u + 8192 + ldr * 64 + ldp * 16;

#define LOAD_STAGE(chunk, stg) do {                        \
        size_t go = (size_t)(chunk) * 64;                  \
        uint32_t so = (uint32_t)(stg) * GSTAGE;            \
        CP16(sA + so,      gA + go);                       \
        CP16(sA + so + 16, gA + go + 16);                  \
        CP16(sB + so,      gB + go);                       \
        CP16(sB + so + 16, gB + go + 16);                  \
    } while (0)

    float c[4][4][4];
#pragma unroll
    for (int i = 0; i < 4; i++)
#pragma unroll
        for (int j = 0; j < 4; j++)
#pragma unroll
            for (int r = 0; r < 4; r++) c[i][j][r] = 0.0f;

    LOAD_STAGE(0, 0); CP_COMMIT();
    LOAD_STAGE(1, 1); CP_COMMIT();
    LOAD_STAGE(2, 2); CP_COMMIT();

    const char* smem_c = smem;
    for (int ch = 0; ch < NCH; ch++) {
        CP_WAIT2();
        __syncthreads();
        const int s = ch & 3;
        const char* As = smem_c + s * GSTAGE;
        const char* Bs = As + 8192;

        uint32_t ah[4][4], al[4][4];
#pragma unroll
        for (int mf = 0; mf < 4; mf++) {
            int r = wm * 64 + mf * 16 + (lane >> 2);
            const char* p = As + r * 64 + (lane & 3) * 16;
            uint4 U0 = *(const uint4*)(p);
            uint4 U1 = *(const uint4*)(p + 512);   // +8 rows
            ah[mf][0] = U0.x; al[mf][0] = U0.y;
            ah[mf][1] = U1.x; al[mf][1] = U1.y;
            ah[mf][2] = U0.z; al[mf][2] = U0.w;
            ah[mf][3] = U1.z; al[mf][3] = U1.w;
        }
        uint32_t bh[4][2], bl[4][2];
#pragma unroll
        for (int nf = 0; nf < 4; nf++) {
            int n = wn * 32 + nf * 8 + (lane >> 2);
            uint4 V = *(const uint4*)(Bs + n * 64 + (lane & 3) * 16);
            bh[nf][0] = V.x; bl[nf][0] = V.y;
            bh[nf][1] = V.z; bl[nf][1] = V.w;
        }
#pragma unroll
        for (int mf = 0; mf < 4; mf++)
#pragma unroll
            for (int nf = 0; nf < 4; nf++) {
                MMA_BF16(c[mf][nf], ah[mf], bh[nf]);
                MMA_BF16(c[mf][nf], ah[mf], bl[nf]);
                MMA_BF16(c[mf][nf], al[mf], bh[nf]);
            }
        __syncthreads();
        if (ch + 3 < NCH) LOAD_STAGE(ch + 3, (ch + 3) & 3);
        CP_COMMIT();
    }

    // Epilogue
#pragma unroll
    for (int mf = 0; mf < 4; mf++) {
#pragma unroll
        for (int nf = 0; nf < 4; nf++) {
            int m0 = rowBase + wm * 64 + mf * 16 + (lane >> 2);
            int n  = colBase + wn * 32 + nf * 8 + (lane & 3) * 2;
            float b0 = bias[n], b1 = bias[n + 1];
#pragma unroll
            for (int half = 0; half < 2; half++) {
                int m = m0 + half * 8;
                float2 v;
                v.x = c[mf][nf][half * 2 + 0] + b0;
                v.y = c[mf][nf][half * 2 + 1] + b1;
                if (mode == 1) {
                    *(float2*)&Cout[(size_t)m * N + n] = v;
                } else {
                    int seg = n >> 10, nn = n & 1023;
                    int hh = nn >> 6, d = nn & 63;
                    int bb = m >> 11, t = m & 2047;
                    size_t idx = (((size_t)(bb * HH + hh)) * TT + t) * DHH + d;
                    uint32_t wh, wl;
                    split_pair(v.x, v.y, wh, wl);
                    if (seg == 0) {
                        *(uint32_t*)&qsp[idx] = wh;
                        *(uint32_t*)&qsp[PLANE + idx] = wl;
                    } else if (seg == 1) {
                        *(float2*)&present[idx] = v;
                        *(uint32_t*)&ksp[idx] = wh;
                        *(uint32_t*)&ksp[PLANE + idx] = wl;
                    } else {
                        *(float2*)&present[PRESENT_HALF + idx] = v;
                        *(uint32_t*)&vsp[idx] = wh;
                        *(uint32_t*)&vsp[PLANE + idx] = wl;
                    }
                }
            }
        }
    }
}

// ---------------------------------------------------------------------------
// Flash attention on tensor cores (bf16 3-term mma).
// Block: 128 q-rows x 64 k-cols, 8 warps (256 thr).
// smem rows stride 144B (ldmatrix-friendly, as validated in R5).
// ---------------------------------------------------------------------------
#define ASTRIDE 144
#define ABYTES  (64 * ASTRIDE)       // 9216 per K/V plane
#define QBYTES  (128 * ASTRIDE)      // 18432 per Q plane
#define ATT_SMEM (2 * QBYTES + 2 * 4 * ABYTES)   // 110592

__device__ __forceinline__ void att_load_stage(
    uint32_t dst, const __nv_bfloat16* kh_g, const __nv_bfloat16* kl_g,
    const __nv_bfloat16* vh_g, const __nv_bfloat16* vl_g, int k0, int tid)
{
    int r = tid >> 2;               // 0..63
    int qo = (tid & 3) * 32;        // byte quarter of 128B row
    const char* skh = (const char*)(kh_g + (size_t)(k0 + r) * DHH) + qo;
    const char* skl = (const char*)(kl_g + (size_t)(k0 + r) * DHH) + qo;
    const char* svh = (const char*)(vh_g + (size_t)(k0 + r) * DHH) + qo;
    const char* svl = (const char*)(vl_g + (size_t)(k0 + r) * DHH) + qo;
    uint32_t d0 = dst + r * ASTRIDE + qo;
#pragma unroll
    for (int i = 0; i < 2; i++) {
        CP16(d0 + i * 16,              skh + i * 16);
        CP16(d0 + ABYTES + i * 16,     skl + i * 16);
        CP16(d0 + 2 * ABYTES + i * 16, svh + i * 16);
        CP16(d0 + 3 * ABYTES + i * 16, svl + i * 16);
    }
}

__global__ __launch_bounds__(256) void attn_mma_kernel(
    const __nv_bfloat16* __restrict__ qs, const __nv_bfloat16* __restrict__ ks,
    const __nv_bfloat16* __restrict__ vs, unsigned char* __restrict__ atts)
{
    extern __shared__ char sm[];
    const uint32_t su = smem_to_u32(sm);
    const int tid = threadIdx.x, lane = tid & 31, w = tid >> 5;
    const int qt = blockIdx.x, h = blockIdx.y, b = blockIdx.z;
    const int q0 = qt * 128;
    const size_t headoff = ((size_t)(b * HH + h)) * TT * DHH;

    const uint32_t sQh = su;
    const uint32_t sQl = su + QBYTES;
    const uint32_t sStg = su + 2 * QBYTES;

    const __nv_bfloat16* qh_g = qs + headoff;
    const __nv_bfloat16* ql_g = qs + PLANE + headoff;
    const __nv_bfloat16* kh_g = ks + headoff;
    const __nv_bfloat16* kl_g = ks + PLANE + headoff;
    const __nv_bfloat16* vh_g = vs + headoff;
    const __nv_bfloat16* vl_g = vs + PLANE + headoff;

    // preload Q (128 rows) + stage 0
    {
        int r = tid >> 1;            // 0..127
        int cb = (tid & 1) * 64;
        const char* sh = (const char*)(qh_g + (size_t)(q0 + r) * DHH) + cb;
        const char* sl = (const char*)(ql_g + (size_t)(q0 + r) * DHH) + cb;
        uint32_t dh_ = sQh + r * ASTRIDE + cb;
        uint32_t dl_ = sQl + r * ASTRIDE + cb;
#pragma unroll
        for (int i = 0; i < 4; i++) {
            CP16(dh_ + i * 16, sh + i * 16);
            CP16(dl_ + i * 16, sl + i * 16);
        }
        att_load_stage(sStg, kh_g, kl_g, vh_g, vl_g, 0, tid);
    }
    CP_COMMIT();

    uint32_t qfh[4][4], qfl[4][4];
    float co[8][4];
#pragma unroll
    for (int j = 0; j < 8; j++)
#pragma unroll
        for (int e = 0; e < 4; e++) co[j][e] = 0.0f;
    float mi[2] = {-1e30f, -1e30f}, li[2] = {0.0f, 0.0f};

    const int r0 = lane >> 2;
    const int cbase = 2 * (lane & 3);
    const int ntiles = 2 * qt + 2;

    for (int kt = 0; kt < ntiles; kt++) {
        const int s = kt & 1;
        const int k0 = kt * 64;
        if (kt + 1 < ntiles)
            att_load_stage(sStg + (s ^ 1) * 4 * ABYTES, kh_g, kl_g, vh_g, vl_g,
                           (kt + 1) * 64, tid);
        CP_COMMIT();
        CP_WAIT1();
        __syncthreads();

        if (kt == 0) {
            int row = (w << 4) + (lane & 15);
            int colb = ((lane >> 4) << 3);
#pragma unroll
            for (int t = 0; t < 4; t++) {
                LDMX4(qfh[t], sQh + row * ASTRIDE + (t * 16 + colb) * 2);
                LDMX4(qfl[t], sQl + row * ASTRIDE + (t * 16 + colb) * 2);
            }
        }

        const uint32_t bKh = sStg + s * 4 * ABYTES;
        const uint32_t bKl = bKh + ABYTES;
        const uint32_t bVh = bKh + 2 * ABYTES;
        const uint32_t bVl = bKh + 3 * ABYTES;

        // ---- S = Q K^T (3-term) ----
        float cs[8][4];
#pragma unroll
        for (int j = 0; j < 8; j++)
#pragma unroll
            for (int e = 0; e < 4; e++) cs[j][e] = 0.0f;

#pragma unroll
        for (int j = 0; j < 8; j++) {
            int rowa = j * 8 + (lane & 7);
#pragma unroll
            for (int u = 0; u < 2; u++) {
                int cola = u * 32 + ((lane >> 3) << 3);
                uint32_t kh[4], kl[4];
                LDMX4(kh, bKh + rowa * ASTRIDE + cola * 2);
                LDMX4(kl, bKl + rowa * ASTRIDE + cola * 2);
                MMA_BF16(cs[j], qfh[2 * u],     kh);
                MMA_BF16(cs[j], qfh[2 * u],     kl);
                MMA_BF16(cs[j], qfl[2 * u],     kh);
                MMA_BF16(cs[j], qfh[2 * u + 1], kh + 2);
                MMA_BF16(cs[j], qfh[2 * u + 1], kl + 2);
                MMA_BF16(cs[j], qfl[2 * u + 1], kh + 2);
            }
        }

        // ---- scale + causal mask (only tiles overlapping the diagonal) ----
        if (k0 >= q0) {
#pragma unroll
            for (int j = 0; j < 8; j++)
#pragma unroll
                for (int e = 0; e < 4; e++) {
                    int gcol = k0 + j * 8 + cbase + (e & 1);
                    int grow = q0 + (w << 4) + r0 + 8 * (e >> 1);
                    float sv = cs[j][e] * 0.25f;
                    cs[j][e] = (gcol > grow) ? -1e30f : sv;
                }
        } else {
#pragma unroll
            for (int j = 0; j < 8; j++)
#pragma unroll
                for (int e = 0; e < 4; e++) cs[j][e] *= 0.25f;
        }

        // ---- online softmax ----
#pragma unroll
        for (int half = 0; half < 2; half++) {
            float mx = -1e30f;
#pragma unroll
            for (int j = 0; j < 8; j++)
                mx = fmaxf(mx, fmaxf(cs[j][2 * half], cs[j][2 * half + 1]));
            mx = fmaxf(mx, __shfl_xor_sync(0xffffffffu, mx, 1));
            mx = fmaxf(mx, __shfl_xor_sync(0xffffffffu, mx, 2));
            float mn = fmaxf(mi[half], mx);
            float alpha = fast_exp(mi[half] - mn);
            mi[half] = mn;
            float rs = 0.0f;
#pragma unroll
            for (int j = 0; j < 8; j++) {
                float p0 = fast_exp(cs[j][2 * half]     - mn);
                float p1 = fast_exp(cs[j][2 * half + 1] - mn);
                cs[j][2 * half] = p0;
                cs[j][2 * half + 1] = p1;
                rs += p0 + p1;
            }
            rs += __shfl_xor_sync(0xffffffffu, rs, 1);
            rs += __shfl_xor_sync(0xffffffffu, rs, 2);
            li[half] = li[half] * alpha + rs;
#pragma unroll
            for (int j = 0; j < 8; j++) {
                co[j][2 * half]     *= alpha;
                co[j][2 * half + 1] *= alpha;
            }
        }

        // ---- pack P into A-fragments (hi/lo) ----
        uint32_t pfh[4][4], pfl[4][4];
#pragma unroll
        for (int t = 0; t < 4; t++)
#pragma unroll
            for (int sub = 0; sub < 2; sub++) {
                int j = 2 * t + sub;
                split_pair(cs[j][0], cs[j][1], pfh[t][sub * 2 + 0], pfl[t][sub * 2 + 0]);
                split_pair(cs[j][2], cs[j][3], pfh[t][sub * 2 + 1], pfl[t][sub * 2 + 1]);
            }

        // ---- O += P V (3-term) ----
#pragma unroll
        for (int t = 0; t < 4; t++) {
            int rowv = t * 16 + (lane & 7) + ((lane >> 3) & 1) * 8;
#pragma unroll
            for (int np = 0; np < 4; np++) {
                int colv = np * 16 + ((lane >> 4) << 3);
                uint32_t vh[4], vl[4];
                LDMX4T(vh, bVh + rowv * ASTRIDE + colv * 2);
                LDMX4T(vl, bVl + rowv * ASTRIDE + colv * 2);
                MMA_BF16(co[2 * np],     pfh[t], vh);
                MMA_BF16(co[2 * np],     pfh[t], vl);
                MMA_BF16(co[2 * np],     pfl[t], vh);
                MMA_BF16(co[2 * np + 1], pfh[t], vh + 2);
                MMA_BF16(co[2 * np + 1], pfh[t], vl + 2);
                MMA_BF16(co[2 * np + 1], pfl[t], vh + 2);
            }
        }
        __syncthreads();
    }

    // ---- epilogue: normalize, write interleaved packed-split for proj ----
    float inv0 = 1.0f / li[0], inv1 = 1.0f / li[1];
#pragma unroll
    for (int j = 0; j < 8; j++) {
#pragma unroll
        for (int half = 0; half < 2; half++) {
            float inv = half ? inv1 : inv0;
            int row = (w << 4) + r0 + 8 * half;
            int m = b * TT + q0 + row;
            int Pidx = h * 32 + j * 4 + (lane & 3);
            uint2 o;
            split_pair(co[j][2 * half] * inv, co[j][2 * half + 1] * inv, o.x, o.y);
            *(uint2*)(atts + (size_t)m * 4096 + pairoff(Pidx)) = o;
        }
    }
}

// ---------------------------------------------------------------------------
extern "C" void kernel_launch(void* const* d_in, const int* in_sizes, int n_in,
                              void* d_out, int out_size)
{
    const float* x      = (const float*)d_in[0];
    const float* w_attn = (const float*)d_in[1];
    const float* b_attn = (const float*)d_in[2];
    const float* w_proj = (const float*)d_in[3];
    const float* b_proj = (const float*)d_in[4];

    float* out = (float*)d_out;
    float* a_out = out;
    float* present = out + (size_t)M_TOT * DD;

    unsigned char *xs, *bta, *btp, *atts;
    __nv_bfloat16 *qsp, *ksp, *vsp;
    cudaGetSymbolAddress((void**)&xs,   g_xs);
    cudaGetSymbolAddress((void**)&bta,  g_bta);
    cudaGetSymbolAddress((void**)&btp,  g_btp);
    cudaGetSymbolAddress((void**)&atts, g_atts);
    cudaGetSymbolAddress((void**)&qsp,  g_qs);
    cudaGetSymbolAddress((void**)&ksp,  g_ks);
    cudaGetSymbolAddress((void**)&vsp,  g_vs);

    cudaFuncSetAttribute(bf16_gemm_kernel,
                         cudaFuncAttributeMaxDynamicSharedMemorySize, GSMEM);
    cudaFuncSetAttribute(attn_mma_kernel,
                         cudaFuncAttributeMaxDynamicSharedMemorySize, ATT_SMEM);

    // Prepasses
    split_kernel<<<(M_TOT * DD / 4 + 255) / 256, 256>>>(
        (const float4*)x, xs, M_TOT * DD / 4);
    transpose_split_kernel<<<dim3(3 * DD / 32, DD / 32), dim3(32, 8)>>>(
        w_attn, bta, DD, 3 * DD);
    transpose_split_kernel<<<dim3(DD / 32, DD / 32), dim3(32, 8)>>>(
        w_proj, btp, DD, DD);

    // QKV GEMM -> split planes + fp32 present
    bf16_gemm_kernel<<<dim3(3 * DD / 128, M_TOT / 128), 256, GSMEM>>>(
        xs, bta, b_attn, nullptr, qsp, ksp, vsp, present, DD, 3 * DD, 0);

    // Tensor-core flash attention -> g_atts
    attn_mma_kernel<<<dim3(TT / 128, HH, BB), 256, ATT_SMEM>>>(
        qsp, ksp, vsp, atts);

    // Projection GEMM -> a_out
    bf16_gemm_kernel<<<dim3(DD / 128, M_TOT / 128), 256, GSMEM>>>(
        atts, btp, b_proj, a_out, nullptr, nullptr, nullptr, nullptr,
        DD, DD, 1);
}

// round 7
// speedup vs baseline: 2.6691x; 1.1149x over previous
#include <cuda_runtime.h>
#include <cuda_fp16.h>
#include <cstdint>

// Problem constants
#define BB 2
#define TT 2048
#define DD 1024
#define HH 16
#define DHH 64
#define M_TOT (BB*TT)                 // 4096
#define PRESENT_HALF (BB*HH*TT*DHH)   // 4194304
#define PLANE ((size_t)BB*HH*TT*DHH)  // elements per hi/lo plane

// ---------------------------------------------------------------------------
// Device-global scratch.
// GEMM operand layout ("interleaved packed-split", fp16):
//   row-major [rows][K], row = K/16 chunks of 64B.
//   chunk = 8 k-pairs p0..p7 (pair = 2 k), stored [p0,p4,p1,p5,p2,p6,p3,p7],
//   pair = 8B: [hi(2k),hi(2k+1) fp16 | lo(2k),lo(2k+1) fp16]
// Head-major split planes (attention): [hi|lo], each [B][H][T][64] fp16
// ---------------------------------------------------------------------------
__device__ unsigned char g_xs[(size_t)M_TOT * DD * 4];
__device__ unsigned char g_bta[(size_t)3 * DD * DD * 4];
__device__ unsigned char g_btp[(size_t)DD * DD * 4];
__device__ __half g_qs[2 * PLANE];
__device__ __half g_ks[2 * PLANE];
__device__ __half g_vs[2 * PLANE];
__device__ unsigned char g_atts[(size_t)M_TOT * DD * 4];

// ---------------------------------------------------------------------------
// Helpers
// ---------------------------------------------------------------------------
__device__ __forceinline__ uint32_t smem_to_u32(const void* smem_ptr) {
    uint32_t addr;
    asm("{ .reg .u64 tmp; cvta.to.shared.u64 tmp, %1; cvt.u32.u64 %0, tmp; }"
        : "=r"(addr) : "l"(smem_ptr));
    return addr;
}

// pack 2 consecutive fp32 into (hi-pair, lo-pair) fp16 words
__device__ __forceinline__ void split_pair(float a, float b,
                                           uint32_t& wh, uint32_t& wl) {
    __half ha = __float2half_rn(a);
    __half hb = __float2half_rn(b);
    float la = a - __half2float(ha);
    float lb = b - __half2float(hb);
    __half2 h = __halves2half2(ha, hb);
    __half2 l = __floats2half2_rn(la, lb);
    wh = *reinterpret_cast<uint32_t*>(&h);
    wl = *reinterpret_cast<uint32_t*>(&l);
}

// byte offset of k-pair P within a row of the interleaved packed-split layout
__device__ __forceinline__ int pairoff(int P) {
    int ch = P >> 3, p = P & 7;
    return ch * 64 + (p & 3) * 16 + (p >> 2) * 8;
}

__device__ __forceinline__ float fast_exp(float x) {
    x = fmaxf(x, -87.0f);
    float t = fmaf(x, 1.4426950408889634f, 12582912.0f);
    int   ni = __float_as_int(t);
    float n = t - 12582912.0f;
    float f = fmaf(x, 1.4426950408889634f, -n);
    float p = 1.3333558146e-3f;
    p = fmaf(p, f, 9.6181291076e-3f);
    p = fmaf(p, f, 5.5504108665e-2f);
    p = fmaf(p, f, 2.4022650696e-1f);
    p = fmaf(p, f, 6.9314718056e-1f);
    p = fmaf(p, f, 1.0f);
    return __int_as_float(__float_as_int(p) + (int)((unsigned)ni << 23));
}

#define CP16(s, g) \
    asm volatile("cp.async.cg.shared.global [%0], [%1], 16;" :: "r"(s), "l"(g))
#define CP_COMMIT() asm volatile("cp.async.commit_group;" ::: "memory")
#define CP_WAIT1()  asm volatile("cp.async.wait_group 1;" ::: "memory")
#define CP_WAIT2()  asm volatile("cp.async.wait_group 2;" ::: "memory")

#define MMA_F16(c, a, b) \
    asm volatile("mma.sync.aligned.m16n8k16.row.col.f32.f16.f16.f32 " \
        "{%0,%1,%2,%3},{%4,%5,%6,%7},{%8,%9},{%0,%1,%2,%3};" \
        : "+f"((c)[0]), "+f"((c)[1]), "+f"((c)[2]), "+f"((c)[3]) \
        : "r"((a)[0]), "r"((a)[1]), "r"((a)[2]), "r"((a)[3]), \
          "r"((b)[0]), "r"((b)[1]))

#define LDMX4(R, addr) \
    asm volatile("ldmatrix.sync.aligned.m8n8.x4.shared.b16 {%0,%1,%2,%3}, [%4];" \
        : "=r"((R)[0]), "=r"((R)[1]), "=r"((R)[2]), "=r"((R)[3]) : "r"(addr))

#define LDMX4T(R, addr) \
    asm volatile("ldmatrix.sync.aligned.m8n8.x4.trans.shared.b16 {%0,%1,%2,%3}, [%4];" \
        : "=r"((R)[0]), "=r"((R)[1]), "=r"((R)[2]), "=r"((R)[3]) : "r"(addr))

// ---------------------------------------------------------------------------
// Prepass 1: x -> interleaved packed-split (K = 1024 fixed)
// ---------------------------------------------------------------------------
__global__ void split_kernel(const float4* __restrict__ src,
                             unsigned char* __restrict__ dst, int n4)
{
    int i = blockIdx.x * blockDim.x + threadIdx.x;
    if (i < n4) {
        float4 v = src[i];
        int e = 4 * i;
        int row = e >> 10;
        int P0 = (e & 1023) >> 1;
        uint2 a, b;
        split_pair(v.x, v.y, a.x, a.y);
        split_pair(v.z, v.w, b.x, b.y);
        unsigned char* base = dst + (size_t)row * 4096 + pairoff(P0);
        *(uint2*)base = a;
        *(uint2*)(base + 16) = b;
    }
}

// ---------------------------------------------------------------------------
// Prepass 2: W[K,N] -> Bt[N][K] interleaved packed-split
// ---------------------------------------------------------------------------
__global__ void transpose_split_kernel(const float* __restrict__ w,
                                       unsigned char* __restrict__ bt,
                                       int Kd, int Nd)
{
    __shared__ float t[32][33];
    int n0 = blockIdx.x * 32, k0 = blockIdx.y * 32;
    int tx = threadIdx.x, ty = threadIdx.y;
#pragma unroll
    for (int i = 0; i < 32; i += 8)
        t[ty + i][tx] = w[(size_t)(k0 + ty + i) * Nd + n0 + tx];
    __syncthreads();
    int tid = ty * 32 + tx;
    int po = tid & 15;
    int nl = tid >> 4;
#pragma unroll
    for (int half = 0; half < 2; half++) {
        int n_loc = nl + half * 16;
        float v0 = t[2 * po][n_loc];
        float v1 = t[2 * po + 1][n_loc];
        uint2 o;
        split_pair(v0, v1, o.x, o.y);
        *(uint2*)(bt + (size_t)(n0 + n_loc) * Kd * 4
                     + pairoff((k0 >> 1) + po)) = o;
    }
}

// ---------------------------------------------------------------------------
// fp16 split mma.sync GEMM. CTA 128x128, 256 thr, chunk 16k, 4-stage.
// mode 0: QKV (3-term) -> split planes + fp32 present.
// mode 1: proj (2-term) -> plain C.
// ---------------------------------------------------------------------------
#define GSTAGE 16384
#define GSMEM  (4 * GSTAGE)

__global__ __launch_bounds__(256, 2) void f16_gemm_kernel(
    const unsigned char* __restrict__ Ag, const unsigned char* __restrict__ Bg,
    const float* __restrict__ bias,
    float* __restrict__ Cout,
    __half* __restrict__ qsp, __half* __restrict__ ksp,
    __half* __restrict__ vsp,
    float* __restrict__ present, int K, int N, int mode)
{
    extern __shared__ char smem[];
    const uint32_t smem_u = smem_to_u32(smem);
    const int tid = threadIdx.x;
    const int lane = tid & 31, wid = tid >> 5;
    const int wm = wid & 1, wn = wid >> 1;
    const int rowBase = blockIdx.y * 128, colBase = blockIdx.x * 128;
    const size_t Arow = (size_t)K * 4;
    const int NCH = K >> 4;

    const int ldr = tid >> 1;
    const int ldp = (tid & 1) * 2;
    const unsigned char* gA = Ag + (size_t)(rowBase + ldr) * Arow + ldp * 16;
    const unsigned char* gB = Bg + (size_t)(colBase + ldr) * Arow + ldp * 16;
    const uint32_t sA = smem_u + ldr * 64 + ldp * 16;
    const uint32_t sB = smem_u + 8192 + ldr * 64 + ldp * 16;

#define LOAD_STAGE(chunk, stg) do {                        \
        size_t go = (size_t)(chunk) * 64;                  \
        uint32_t so = (uint32_t)(stg) * GSTAGE;            \
        CP16(sA + so,      gA + go);                       \
        CP16(sA + so + 16, gA + go + 16);                  \
        CP16(sB + so,      gB + go);                       \
        CP16(sB + so + 16, gB + go + 16);                  \
    } while (0)

    float c[4][4][4];
#pragma unroll
    for (int i = 0; i < 4; i++)
#pragma unroll
        for (int j = 0; j < 4; j++)
#pragma unroll
            for (int r = 0; r < 4; r++) c[i][j][r] = 0.0f;

    LOAD_STAGE(0, 0); CP_COMMIT();
    LOAD_STAGE(1, 1); CP_COMMIT();
    LOAD_STAGE(2, 2); CP_COMMIT();

    const char* smem_c = smem;
    for (int ch = 0; ch < NCH; ch++) {
        CP_WAIT2();
        __syncthreads();
        const int s = ch & 3;
        const char* As = smem_c + s * GSTAGE;
        const char* Bs = As + 8192;

        uint32_t ah[4][4], al[4][4];
#pragma unroll
        for (int mf = 0; mf < 4; mf++) {
            int r = wm * 64 + mf * 16 + (lane >> 2);
            const char* p = As + r * 64 + (lane & 3) * 16;
            uint4 U0 = *(const uint4*)(p);
            uint4 U1 = *(const uint4*)(p + 512);
            ah[mf][0] = U0.x; al[mf][0] = U0.y;
            ah[mf][1] = U1.x; al[mf][1] = U1.y;
            ah[mf][2] = U0.z; al[mf][2] = U0.w;
            ah[mf][3] = U1.z; al[mf][3] = U1.w;
        }
        uint32_t bh[4][2], bl[4][2];
#pragma unroll
        for (int nf = 0; nf < 4; nf++) {
            int n = wn * 32 + nf * 8 + (lane >> 2);
            uint4 V = *(const uint4*)(Bs + n * 64 + (lane & 3) * 16);
            bh[nf][0] = V.x; bl[nf][0] = V.y;
            bh[nf][1] = V.z; bl[nf][1] = V.w;
        }
        if (mode == 0) {
#pragma unroll
            for (int mf = 0; mf < 4; mf++)
#pragma unroll
                for (int nf = 0; nf < 4; nf++) {
                    MMA_F16(c[mf][nf], ah[mf], bh[nf]);
                    MMA_F16(c[mf][nf], ah[mf], bl[nf]);
                    MMA_F16(c[mf][nf], al[mf], bh[nf]);
                }
        } else {
#pragma unroll
            for (int mf = 0; mf < 4; mf++)
#pragma unroll
                for (int nf = 0; nf < 4; nf++) {
                    MMA_F16(c[mf][nf], ah[mf], bh[nf]);
                    MMA_F16(c[mf][nf], ah[mf], bl[nf]);
                }
        }
        __syncthreads();
        if (ch + 3 < NCH) LOAD_STAGE(ch + 3, (ch + 3) & 3);
        CP_COMMIT();
    }

    // Epilogue
#pragma unroll
    for (int mf = 0; mf < 4; mf++) {
#pragma unroll
        for (int nf = 0; nf < 4; nf++) {
            int m0 = rowBase + wm * 64 + mf * 16 + (lane >> 2);
            int n  = colBase + wn * 32 + nf * 8 + (lane & 3) * 2;
            float b0 = bias[n], b1 = bias[n + 1];
#pragma unroll
            for (int half = 0; half < 2; half++) {
                int m = m0 + half * 8;
                float2 v;
                v.x = c[mf][nf][half * 2 + 0] + b0;
                v.y = c[mf][nf][half * 2 + 1] + b1;
                if (mode == 1) {
                    *(float2*)&Cout[(size_t)m * N + n] = v;
                } else {
                    int seg = n >> 10, nn = n & 1023;
                    int hh = nn >> 6, d = nn & 63;
                    int bb = m >> 11, t = m & 2047;
                    size_t idx = (((size_t)(bb * HH + hh)) * TT + t) * DHH + d;
                    uint32_t wh, wl;
                    split_pair(v.x, v.y, wh, wl);
                    if (seg == 0) {
                        *(uint32_t*)&qsp[idx] = wh;
                        *(uint32_t*)&qsp[PLANE + idx] = wl;
                    } else if (seg == 1) {
                        *(float2*)&present[idx] = v;
                        *(uint32_t*)&ksp[idx] = wh;
                        *(uint32_t*)&ksp[PLANE + idx] = wl;
                    } else {
                        *(float2*)&present[PRESENT_HALF + idx] = v;
                        *(uint32_t*)&vsp[idx] = wh;
                        *(uint32_t*)&vsp[PLANE + idx] = wl;
                    }
                }
            }
        }
    }
}

// ---------------------------------------------------------------------------
// Flash attention on tensor cores (fp16 3-term mma).
// Block: 128 q-rows x 64 k-cols, 8 warps. qt order reversed for load balance.
// ---------------------------------------------------------------------------
#define ASTRIDE 144
#define ABYTES  (64 * ASTRIDE)
#define QBYTES  (128 * ASTRIDE)
#define ATT_SMEM (2 * QBYTES + 2 * 4 * ABYTES)   // 110592

__device__ __forceinline__ void att_load_stage(
    uint32_t dst, const __half* kh_g, const __half* kl_g,
    const __half* vh_g, const __half* vl_g, int k0, int tid)
{
    int r = tid >> 2;
    int qo = (tid & 3) * 32;
    const char* skh = (const char*)(kh_g + (size_t)(k0 + r) * DHH) + qo;
    const char* skl = (const char*)(kl_g + (size_t)(k0 + r) * DHH) + qo;
    const char* svh = (const char*)(vh_g + (size_t)(k0 + r) * DHH) + qo;
    const char* svl = (const char*)(vl_g + (size_t)(k0 + r) * DHH) + qo;
    uint32_t d0 = dst + r * ASTRIDE + qo;
#pragma unroll
    for (int i = 0; i < 2; i++) {
        CP16(d0 + i * 16,              skh + i * 16);
        CP16(d0 + ABYTES + i * 16,     skl + i * 16);
        CP16(d0 + 2 * ABYTES + i * 16, svh + i * 16);
        CP16(d0 + 3 * ABYTES + i * 16, svl + i * 16);
    }
}

__global__ __launch_bounds__(256) void attn_mma_kernel(
    const __half* __restrict__ qs, const __half* __restrict__ ks,
    const __half* __restrict__ vs, unsigned char* __restrict__ atts)
{
    extern __shared__ char sm[];
    const uint32_t su = smem_to_u32(sm);
    const int tid = threadIdx.x, lane = tid & 31, w = tid >> 5;
    const int qt = gridDim.x - 1 - blockIdx.x;   // long CTAs first
    const int h = blockIdx.y, b = blockIdx.z;
    const int q0 = qt * 128;
    const size_t headoff = ((size_t)(b * HH + h)) * TT * DHH;

    const uint32_t sQh = su;
    const uint32_t sQl = su + QBYTES;
    const uint32_t sStg = su + 2 * QBYTES;

    const __half* qh_g = qs + headoff;
    const __half* ql_g = qs + PLANE + headoff;
    const __half* kh_g = ks + headoff;
    const __half* kl_g = ks + PLANE + headoff;
    const __half* vh_g = vs + headoff;
    const __half* vl_g = vs + PLANE + headoff;

    // preload Q (128 rows) + stage 0
    {
        int r = tid >> 1;
        int cb = (tid & 1) * 64;
        const char* sh = (const char*)(qh_g + (size_t)(q0 + r) * DHH) + cb;
        const char* sl = (const char*)(ql_g + (size_t)(q0 + r) * DHH) + cb;
        uint32_t dh_ = sQh + r * ASTRIDE + cb;
        uint32_t dl_ = sQl + r * ASTRIDE + cb;
#pragma unroll
        for (int i = 0; i < 4; i++) {
            CP16(dh_ + i * 16, sh + i * 16);
            CP16(dl_ + i * 16, sl + i * 16);
        }
        att_load_stage(sStg, kh_g, kl_g, vh_g, vl_g, 0, tid);
    }
    CP_COMMIT();

    uint32_t qfh[4][4], qfl[4][4];
    float co[8][4];
#pragma unroll
    for (int j = 0; j < 8; j++)
#pragma unroll
        for (int e = 0; e < 4; e++) co[j][e] = 0.0f;
    float mi[2] = {-1e30f, -1e30f}, li[2] = {0.0f, 0.0f};

    const int r0 = lane >> 2;
    const int cbase = 2 * (lane & 3);
    const int ntiles = 2 * qt + 2;

    for (int kt = 0; kt < ntiles; kt++) {
        const int s = kt & 1;
        const int k0 = kt * 64;
        if (kt + 1 < ntiles)
            att_load_stage(sStg + (s ^ 1) * 4 * ABYTES, kh_g, kl_g, vh_g, vl_g,
                           (kt + 1) * 64, tid);
        CP_COMMIT();
        CP_WAIT1();
        __syncthreads();

        if (kt == 0) {
            int row = (w << 4) + (lane & 15);
            int colb = ((lane >> 4) << 3);
#pragma unroll
            for (int t = 0; t < 4; t++) {
                LDMX4(qfh[t], sQh + row * ASTRIDE + (t * 16 + colb) * 2);
                LDMX4(qfl[t], sQl + row * ASTRIDE + (t * 16 + colb) * 2);
            }
        }

        const uint32_t bKh = sStg + s * 4 * ABYTES;
        const uint32_t bKl = bKh + ABYTES;
        const uint32_t bVh = bKh + 2 * ABYTES;
        const uint32_t bVl = bKh + 3 * ABYTES;

        // ---- S = Q K^T (3-term) ----
        float cs[8][4];
#pragma unroll
        for (int j = 0; j < 8; j++)
#pragma unroll
            for (int e = 0; e < 4; e++) cs[j][e] = 0.0f;

#pragma unroll
        for (int j = 0; j < 8; j++) {
            int rowa = j * 8 + (lane & 7);
#pragma unroll
            for (int u = 0; u < 2; u++) {
                int cola = u * 32 + ((lane >> 3) << 3);
                uint32_t kh[4], kl[4];
                LDMX4(kh, bKh + rowa * ASTRIDE + cola * 2);
                LDMX4(kl, bKl + rowa * ASTRIDE + cola * 2);
                MMA_F16(cs[j], qfh[2 * u],     kh);
                MMA_F16(cs[j], qfh[2 * u],     kl);
                MMA_F16(cs[j], qfl[2 * u],     kh);
                MMA_F16(cs[j], qfh[2 * u + 1], kh + 2);
                MMA_F16(cs[j], qfh[2 * u + 1], kl + 2);
                MMA_F16(cs[j], qfl[2 * u + 1], kh + 2);
            }
        }

        // ---- scale + causal mask ----
        if (k0 >= q0) {
#pragma unroll
            for (int j = 0; j < 8; j++)
#pragma unroll
                for (int e = 0; e < 4; e++) {
                    int gcol = k0 + j * 8 + cbase + (e & 1);
                    int grow = q0 + (w << 4) + r0 + 8 * (e >> 1);
                    float sv = cs[j][e] * 0.25f;
                    cs[j][e] = (gcol > grow) ? -1e30f : sv;
                }
        } else {
#pragma unroll
            for (int j = 0; j < 8; j++)
#pragma unroll
                for (int e = 0; e < 4; e++) cs[j][e] *= 0.25f;
        }

        // ---- online softmax ----
#pragma unroll
        for (int half = 0; half < 2; half++) {
            float mx = -1e30f;
#pragma unroll
            for (int j = 0; j < 8; j++)
                mx = fmaxf(mx, fmaxf(cs[j][2 * half], cs[j][2 * half + 1]));
            mx = fmaxf(mx, __shfl_xor_sync(0xffffffffu, mx, 1));
            mx = fmaxf(mx, __shfl_xor_sync(0xffffffffu, mx, 2));
            float mn = fmaxf(mi[half], mx);
            float alpha = fast_exp(mi[half] - mn);
            mi[half] = mn;
            float rs = 0.0f;
#pragma unroll
            for (int j = 0; j < 8; j++) {
                float p0 = fast_exp(cs[j][2 * half]     - mn);
                float p1 = fast_exp(cs[j][2 * half + 1] - mn);
                cs[j][2 * half] = p0;
                cs[j][2 * half + 1] = p1;
                rs += p0 + p1;
            }
            rs += __shfl_xor_sync(0xffffffffu, rs, 1);
            rs += __shfl_xor_sync(0xffffffffu, rs, 2);
            li[half] = li[half] * alpha + rs;
#pragma unroll
            for (int j = 0; j < 8; j++) {
                co[j][2 * half]     *= alpha;
                co[j][2 * half + 1] *= alpha;
            }
        }

        // ---- pack P into A-fragments (hi/lo) ----
        uint32_t pfh[4][4], pfl[4][4];
#pragma unroll
        for (int t = 0; t < 4; t++)
#pragma unroll
            for (int sub = 0; sub < 2; sub++) {
                int j = 2 * t + sub;
                split_pair(cs[j][0], cs[j][1], pfh[t][sub * 2 + 0], pfl[t][sub * 2 + 0]);
                split_pair(cs[j][2], cs[j][3], pfh[t][sub * 2 + 1], pfl[t][sub * 2 + 1]);
            }

        // ---- O += P V (3-term) ----
#pragma unroll
        for (int t = 0; t < 4; t++) {
            int rowv = t * 16 + (lane & 7) + ((lane >> 3) & 1) * 8;
#pragma unroll
            for (int np = 0; np < 4; np++) {
                int colv = np * 16 + ((lane >> 4) << 3);
                uint32_t vh[4], vl[4];
                LDMX4T(vh, bVh + rowv * ASTRIDE + colv * 2);
                LDMX4T(vl, bVl + rowv * ASTRIDE + colv * 2);
                MMA_F16(co[2 * np],     pfh[t], vh);
                MMA_F16(co[2 * np],     pfh[t], vl);
                MMA_F16(co[2 * np],     pfl[t], vh);
                MMA_F16(co[2 * np + 1], pfh[t], vh + 2);
                MMA_F16(co[2 * np + 1], pfh[t], vl + 2);
                MMA_F16(co[2 * np + 1], pfl[t], vh + 2);
            }
        }
        __syncthreads();
    }

    // ---- epilogue ----
    float inv0 = 1.0f / li[0], inv1 = 1.0f / li[1];
#pragma unroll
    for (int j = 0; j < 8; j++) {
#pragma unroll
        for (int half = 0; half < 2; half++) {
            float inv = half ? inv1 : inv0;
            int row = (w << 4) + r0 + 8 * half;
            int m = b * TT + q0 + row;
            int Pidx = h * 32 + j * 4 + (lane & 3);
            uint2 o;
            split_pair(co[j][2 * half] * inv, co[j][2 * half + 1] * inv, o.x, o.y);
            *(uint2*)(atts + (size_t)m * 4096 + pairoff(Pidx)) = o;
        }
    }
}

// ---------------------------------------------------------------------------
extern "C" void kernel_launch(void* const* d_in, const int* in_sizes, int n_in,
                              void* d_out, int out_size)
{
    const float* x      = (const float*)d_in[0];
    const float* w_attn = (const float*)d_in[1];
    const float* b_attn = (const float*)d_in[2];
    const float* w_proj = (const float*)d_in[3];
    const float* b_proj = (const float*)d_in[4];

    float* out = (float*)d_out;
    float* a_out = out;
    float* present = out + (size_t)M_TOT * DD;

    unsigned char *xs, *bta, *btp, *atts;
    __half *qsp, *ksp, *vsp;
    cudaGetSymbolAddress((void**)&xs,   g_xs);
    cudaGetSymbolAddress((void**)&bta,  g_bta);
    cudaGetSymbolAddress((void**)&btp,  g_btp);
    cudaGetSymbolAddress((void**)&atts, g_atts);
    cudaGetSymbolAddress((void**)&qsp,  g_qs);
    cudaGetSymbolAddress((void**)&ksp,  g_ks);
    cudaGetSymbolAddress((void**)&vsp,  g_vs);

    cudaFuncSetAttribute(f16_gemm_kernel,
                         cudaFuncAttributeMaxDynamicSharedMemorySize, GSMEM);
    cudaFuncSetAttribute(attn_mma_kernel,
                         cudaFuncAttributeMaxDynamicSharedMemorySize, ATT_SMEM);

    // Prepasses
    split_kernel<<<(M_TOT * DD / 4 + 255) / 256, 256>>>(
        (const float4*)x, xs, M_TOT * DD / 4);
    transpose_split_kernel<<<dim3(3 * DD / 32, DD / 32), dim3(32, 8)>>>(
        w_attn, bta, DD, 3 * DD);
    transpose_split_kernel<<<dim3(DD / 32, DD / 32), dim3(32, 8)>>>(
        w_proj, btp, DD, DD);

    // QKV GEMM (3-term) -> split planes + fp32 present
    f16_gemm_kernel<<<dim3(3 * DD / 128, M_TOT / 128), 256, GSMEM>>>(
        xs, bta, b_attn, nullptr, qsp, ksp, vsp, present, DD, 3 * DD, 0);

    // Tensor-core flash attention -> g_atts
    attn_mma_kernel<<<dim3(TT / 128, HH, BB), 256, ATT_SMEM>>>(
        qsp, ksp, vsp, atts);

    // Projection GEMM (2-term) -> a_out
    f16_gemm_kernel<<<dim3(DD / 128, M_TOT / 128), 256, GSMEM>>>(
        atts, btp, b_proj, a_out, nullptr, nullptr, nullptr, nullptr,
        DD, DD, 1);
}

// round 8
// speedup vs baseline: 2.7759x; 1.0400x over previous
#include <cuda_runtime.h>
#include <cuda_fp16.h>
#include <cstdint>

// Problem constants
#define BB 2
#define TT 2048
#define DD 1024
#define HH 16
#define DHH 64
#define M_TOT (BB*TT)                 // 4096
#define PRESENT_HALF (BB*HH*TT*DHH)   // 4194304
#define PLANE ((size_t)BB*HH*TT*DHH)  // elements per hi/lo plane

// ---------------------------------------------------------------------------
// Device-global scratch.
// GEMM operand layout ("interleaved packed-split", fp16):
//   row-major [rows][K], row = K/16 chunks of 64B.
//   chunk = 8 k-pairs p0..p7 (pair = 2 k), stored [p0,p4,p1,p5,p2,p6,p3,p7],
//   pair = 8B: [hi(2k),hi(2k+1) fp16 | lo(2k),lo(2k+1) fp16]
// Attention planes: Q = [hi|lo] (2 planes), K/V = hi only. [B][H][T][64] fp16.
// ---------------------------------------------------------------------------
__device__ unsigned char g_xs[(size_t)M_TOT * DD * 4];
__device__ unsigned char g_bta[(size_t)3 * DD * DD * 4];
__device__ unsigned char g_btp[(size_t)DD * DD * 4];
__device__ __half g_qs[2 * PLANE];
__device__ __half g_ks[PLANE];
__device__ __half g_vs[PLANE];
__device__ unsigned char g_atts[(size_t)M_TOT * DD * 4];

// ---------------------------------------------------------------------------
// Helpers
// ---------------------------------------------------------------------------
__device__ __forceinline__ uint32_t smem_to_u32(const void* smem_ptr) {
    uint32_t addr;
    asm("{ .reg .u64 tmp; cvta.to.shared.u64 tmp, %1; cvt.u32.u64 %0, tmp; }"
        : "=r"(addr) : "l"(smem_ptr));
    return addr;
}

__device__ __forceinline__ void split_pair(float a, float b,
                                           uint32_t& wh, uint32_t& wl) {
    __half ha = __float2half_rn(a);
    __half hb = __float2half_rn(b);
    float la = a - __half2float(ha);
    float lb = b - __half2float(hb);
    __half2 h = __halves2half2(ha, hb);
    __half2 l = __floats2half2_rn(la, lb);
    wh = *reinterpret_cast<uint32_t*>(&h);
    wl = *reinterpret_cast<uint32_t*>(&l);
}

__device__ __forceinline__ int pairoff(int P) {
    int ch = P >> 3, p = P & 7;
    return ch * 64 + (p & 3) * 16 + (p >> 2) * 8;
}

__device__ __forceinline__ float fast_exp(float x) {
    x = fmaxf(x, -87.0f);
    float t = fmaf(x, 1.4426950408889634f, 12582912.0f);
    int   ni = __float_as_int(t);
    float n = t - 12582912.0f;
    float f = fmaf(x, 1.4426950408889634f, -n);
    float p = 1.3333558146e-3f;
    p = fmaf(p, f, 9.6181291076e-3f);
    p = fmaf(p, f, 5.5504108665e-2f);
    p = fmaf(p, f, 2.4022650696e-1f);
    p = fmaf(p, f, 6.9314718056e-1f);
    p = fmaf(p, f, 1.0f);
    return __int_as_float(__float_as_int(p) + (int)((unsigned)ni << 23));
}

#define CP16(s, g) \
    asm volatile("cp.async.cg.shared.global [%0], [%1], 16;" :: "r"(s), "l"(g))
#define CP_COMMIT() asm volatile("cp.async.commit_group;" ::: "memory")
#define CP_WAIT1()  asm volatile("cp.async.wait_group 1;" ::: "memory")
#define CP_WAIT2()  asm volatile("cp.async.wait_group 2;" ::: "memory")

#define MMA_F16(c, a, b) \
    asm volatile("mma.sync.aligned.m16n8k16.row.col.f32.f16.f16.f32 " \
        "{%0,%1,%2,%3},{%4,%5,%6,%7},{%8,%9},{%0,%1,%2,%3};" \
        : "+f"((c)[0]), "+f"((c)[1]), "+f"((c)[2]), "+f"((c)[3]) \
        : "r"((a)[0]), "r"((a)[1]), "r"((a)[2]), "r"((a)[3]), \
          "r"((b)[0]), "r"((b)[1]))

#define LDMX4(R, addr) \
    asm volatile("ldmatrix.sync.aligned.m8n8.x4.shared.b16 {%0,%1,%2,%3}, [%4];" \
        : "=r"((R)[0]), "=r"((R)[1]), "=r"((R)[2]), "=r"((R)[3]) : "r"(addr))

#define LDMX4T(R, addr) \
    asm volatile("ldmatrix.sync.aligned.m8n8.x4.trans.shared.b16 {%0,%1,%2,%3}, [%4];" \
        : "=r"((R)[0]), "=r"((R)[1]), "=r"((R)[2]), "=r"((R)[3]) : "r"(addr))

// ---------------------------------------------------------------------------
// Prepass 1: x -> interleaved packed-split (K = 1024 fixed)
// ---------------------------------------------------------------------------
__global__ void split_kernel(const float4* __restrict__ src,
                             unsigned char* __restrict__ dst, int n4)
{
    int i = blockIdx.x * blockDim.x + threadIdx.x;
    if (i < n4) {
        float4 v = src[i];
        int e = 4 * i;
        int row = e >> 10;
        int P0 = (e & 1023) >> 1;
        uint2 a, b;
        split_pair(v.x, v.y, a.x, a.y);
        split_pair(v.z, v.w, b.x, b.y);
        unsigned char* base = dst + (size_t)row * 4096 + pairoff(P0);
        *(uint2*)base = a;
        *(uint2*)(base + 16) = b;
    }
}

// ---------------------------------------------------------------------------
// Prepass 2: W[K,N] -> Bt[N][K] interleaved packed-split
// ---------------------------------------------------------------------------
__global__ void transpose_split_kernel(const float* __restrict__ w,
                                       unsigned char* __restrict__ bt,
                                       int Kd, int Nd)
{
    __shared__ float t[32][33];
    int n0 = blockIdx.x * 32, k0 = blockIdx.y * 32;
    int tx = threadIdx.x, ty = threadIdx.y;
#pragma unroll
    for (int i = 0; i < 32; i += 8)
        t[ty + i][tx] = w[(size_t)(k0 + ty + i) * Nd + n0 + tx];
    __syncthreads();
    int tid = ty * 32 + tx;
    int po = tid & 15;
    int nl = tid >> 4;
#pragma unroll
    for (int half = 0; half < 2; half++) {
        int n_loc = nl + half * 16;
        float v0 = t[2 * po][n_loc];
        float v1 = t[2 * po + 1][n_loc];
        uint2 o;
        split_pair(v0, v1, o.x, o.y);
        *(uint2*)(bt + (size_t)(n0 + n_loc) * Kd * 4
                     + pairoff((k0 >> 1) + po)) = o;
    }
}

// ---------------------------------------------------------------------------
// fp16 split mma.sync GEMM. CTA 128x128, 256 thr, chunk 16k, 4-stage.
// mode 0: QKV (3-term) -> q hi/lo, k/v hi-only planes + fp32 present.
// mode 1: proj (2-term) -> plain C.
// ---------------------------------------------------------------------------
#define GSTAGE 16384
#define GSMEM  (4 * GSTAGE)

__global__ __launch_bounds__(256, 2) void f16_gemm_kernel(
    const unsigned char* __restrict__ Ag, const unsigned char* __restrict__ Bg,
    const float* __restrict__ bias,
    float* __restrict__ Cout,
    __half* __restrict__ qsp, __half* __restrict__ ksp,
    __half* __restrict__ vsp,
    float* __restrict__ present, int K, int N, int mode)
{
    extern __shared__ char smem[];
    const uint32_t smem_u = smem_to_u32(smem);
    const int tid = threadIdx.x;
    const int lane = tid & 31, wid = tid >> 5;
    const int wm = wid & 1, wn = wid >> 1;
    const int rowBase = blockIdx.y * 128, colBase = blockIdx.x * 128;
    const size_t Arow = (size_t)K * 4;
    const int NCH = K >> 4;

    const int ldr = tid >> 1;
    const int ldp = (tid & 1) * 2;
    const unsigned char* gA = Ag + (size_t)(rowBase + ldr) * Arow + ldp * 16;
    const unsigned char* gB = Bg + (size_t)(colBase + ldr) * Arow + ldp * 16;
    const uint32_t sA = smem_u + ldr * 64 + ldp * 16;
    const uint32_t sB = smem_u + 8192 + ldr * 64 + ldp * 16;

#define LOAD_STAGE(chunk, stg) do {                        \
        size_t go = (size_t)(chunk) * 64;                  \
        uint32_t so = (uint32_t)(stg) * GSTAGE;            \
        CP16(sA + so,      gA + go);                       \
        CP16(sA + so + 16, gA + go + 16);                  \
        CP16(sB + so,      gB + go);                       \
        CP16(sB + so + 16, gB + go + 16);                  \
    } while (0)

    float c[4][4][4];
#pragma unroll
    for (int i = 0; i < 4; i++)
#pragma unroll
        for (int j = 0; j < 4; j++)
#pragma unroll
            for (int r = 0; r < 4; r++) c[i][j][r] = 0.0f;

    LOAD_STAGE(0, 0); CP_COMMIT();
    LOAD_STAGE(1, 1); CP_COMMIT();
    LOAD_STAGE(2, 2); CP_COMMIT();

    const char* smem_c = smem;
    for (int ch = 0; ch < NCH; ch++) {
        CP_WAIT2();
        __syncthreads();
        const int s = ch & 3;
        const char* As = smem_c + s * GSTAGE;
        const char* Bs = As + 8192;

        uint32_t ah[4][4], al[4][4];
#pragma unroll
        for (int mf = 0; mf < 4; mf++) {
            int r = wm * 64 + mf * 16 + (lane >> 2);
            const char* p = As + r * 64 + (lane & 3) * 16;
            uint4 U0 = *(const uint4*)(p);
            uint4 U1 = *(const uint4*)(p + 512);
            ah[mf][0] = U0.x; al[mf][0] = U0.y;
            ah[mf][1] = U1.x; al[mf][1] = U1.y;
            ah[mf][2] = U0.z; al[mf][2] = U0.w;
            ah[mf][3] = U1.z; al[mf][3] = U1.w;
        }
        uint32_t bh[4][2], bl[4][2];
#pragma unroll
        for (int nf = 0; nf < 4; nf++) {
            int n = wn * 32 + nf * 8 + (lane >> 2);
            uint4 V = *(const uint4*)(Bs + n * 64 + (lane & 3) * 16);
            bh[nf][0] = V.x; bl[nf][0] = V.y;
            bh[nf][1] = V.z; bl[nf][1] = V.w;
        }
        if (mode == 0) {
#pragma unroll
            for (int mf = 0; mf < 4; mf++)
#pragma unroll
                for (int nf = 0; nf < 4; nf++) {
                    MMA_F16(c[mf][nf], ah[mf], bh[nf]);
                    MMA_F16(c[mf][nf], ah[mf], bl[nf]);
                    MMA_F16(c[mf][nf], al[mf], bh[nf]);
                }
        } else {
#pragma unroll
            for (int mf = 0; mf < 4; mf++)
#pragma unroll
                for (int nf = 0; nf < 4; nf++) {
                    MMA_F16(c[mf][nf], ah[mf], bh[nf]);
                    MMA_F16(c[mf][nf], ah[mf], bl[nf]);
                }
        }
        __syncthreads();
        if (ch + 3 < NCH) LOAD_STAGE(ch + 3, (ch + 3) & 3);
        CP_COMMIT();
    }

    // Epilogue
#pragma unroll
    for (int mf = 0; mf < 4; mf++) {
#pragma unroll
        for (int nf = 0; nf < 4; nf++) {
            int m0 = rowBase + wm * 64 + mf * 16 + (lane >> 2);
            int n  = colBase + wn * 32 + nf * 8 + (lane & 3) * 2;
            float b0 = bias[n], b1 = bias[n + 1];
#pragma unroll
            for (int half = 0; half < 2; half++) {
                int m = m0 + half * 8;
                float2 v;
                v.x = c[mf][nf][half * 2 + 0] + b0;
                v.y = c[mf][nf][half * 2 + 1] + b1;
                if (mode == 1) {
                    *(float2*)&Cout[(size_t)m * N + n] = v;
                } else {
                    int seg = n >> 10, nn = n & 1023;
                    int hh = nn >> 6, d = nn & 63;
                    int bb = m >> 11, t = m & 2047;
                    size_t idx = (((size_t)(bb * HH + hh)) * TT + t) * DHH + d;
                    uint32_t wh, wl;
                    split_pair(v.x, v.y, wh, wl);
                    if (seg == 0) {
                        *(uint32_t*)&qsp[idx] = wh;
                        *(uint32_t*)&qsp[PLANE + idx] = wl;
                    } else if (seg == 1) {
                        *(float2*)&present[idx] = v;
                        *(uint32_t*)&ksp[idx] = wh;     // hi only
                    } else {
                        *(float2*)&present[PRESENT_HALF + idx] = v;
                        *(uint32_t*)&vsp[idx] = wh;     // hi only
                    }
                }
            }
        }
    }
}

// ---------------------------------------------------------------------------
// Flash attention on tensor cores (fp16, 2-term: full Q/P vs hi-only K/V).
// Block: 128 q-rows x 64 k-cols, 8 warps, reversed qt for load balance.
// Stage = K hi + V hi planes only.
// ---------------------------------------------------------------------------
#define ASTRIDE 144
#define ABYTES  (64 * ASTRIDE)
#define QBYTES  (128 * ASTRIDE)
#define ATT_SMEM (2 * QBYTES + 2 * 2 * ABYTES)   // 73728

__device__ __forceinline__ void att_load_stage(
    uint32_t dst, const __half* kh_g, const __half* vh_g, int k0, int tid)
{
    int r = tid >> 2;
    int qo = (tid & 3) * 32;
    const char* skh = (const char*)(kh_g + (size_t)(k0 + r) * DHH) + qo;
    const char* svh = (const char*)(vh_g + (size_t)(k0 + r) * DHH) + qo;
    uint32_t d0 = dst + r * ASTRIDE + qo;
#pragma unroll
    for (int i = 0; i < 2; i++) {
        CP16(d0 + i * 16,          skh + i * 16);
        CP16(d0 + ABYTES + i * 16, svh + i * 16);
    }
}

__global__ __launch_bounds__(256) void attn_mma_kernel(
    const __half* __restrict__ qs, const __half* __restrict__ ks,
    const __half* __restrict__ vs, unsigned char* __restrict__ atts)
{
    extern __shared__ char sm[];
    const uint32_t su = smem_to_u32(sm);
    const int tid = threadIdx.x, lane = tid & 31, w = tid >> 5;
    const int qt = gridDim.x - 1 - blockIdx.x;
    const int h = blockIdx.y, b = blockIdx.z;
    const int q0 = qt * 128;
    const size_t headoff = ((size_t)(b * HH + h)) * TT * DHH;

    const uint32_t sQh = su;
    const uint32_t sQl = su + QBYTES;
    const uint32_t sStg = su + 2 * QBYTES;

    const __half* qh_g = qs + headoff;
    const __half* ql_g = qs + PLANE + headoff;
    const __half* kh_g = ks + headoff;
    const __half* vh_g = vs + headoff;

    // preload Q (hi+lo, 128 rows) + stage 0
    {
        int r = tid >> 1;
        int cb = (tid & 1) * 64;
        const char* sh = (const char*)(qh_g + (size_t)(q0 + r) * DHH) + cb;
        const char* sl = (const char*)(ql_g + (size_t)(q0 + r) * DHH) + cb;
        uint32_t dh_ = sQh + r * ASTRIDE + cb;
        uint32_t dl_ = sQl + r * ASTRIDE + cb;
#pragma unroll
        for (int i = 0; i < 4; i++) {
            CP16(dh_ + i * 16, sh + i * 16);
            CP16(dl_ + i * 16, sl + i * 16);
        }
        att_load_stage(sStg, kh_g, vh_g, 0, tid);
    }
    CP_COMMIT();

    uint32_t qfh[4][4], qfl[4][4];
    float co[8][4];
#pragma unroll
    for (int j = 0; j < 8; j++)
#pragma unroll
        for (int e = 0; e < 4; e++) co[j][e] = 0.0f;
    float mi[2] = {-1e30f, -1e30f}, li[2] = {0.0f, 0.0f};

    const int r0 = lane >> 2;
    const int cbase = 2 * (lane & 3);
    const int ntiles = 2 * qt + 2;

    for (int kt = 0; kt < ntiles; kt++) {
        const int s = kt & 1;
        const int k0 = kt * 64;
        if (kt + 1 < ntiles)
            att_load_stage(sStg + (s ^ 1) * 2 * ABYTES, kh_g, vh_g,
                           (kt + 1) * 64, tid);
        CP_COMMIT();
        CP_WAIT1();
        __syncthreads();

        if (kt == 0) {
            int row = (w << 4) + (lane & 15);
            int colb = ((lane >> 4) << 3);
#pragma unroll
            for (int t = 0; t < 4; t++) {
                LDMX4(qfh[t], sQh + row * ASTRIDE + (t * 16 + colb) * 2);
                LDMX4(qfl[t], sQl + row * ASTRIDE + (t * 16 + colb) * 2);
            }
        }

        // Fully-masked tile for this warp? (all rows < all cols)
        const bool active = (k0 <= q0 + (w << 4) + 15);

        if (active) {
            const uint32_t bKh = sStg + s * 2 * ABYTES;
            const uint32_t bVh = bKh + ABYTES;

            // ---- S = (Qh+Ql) Kh^T ----
            float cs[8][4];
#pragma unroll
            for (int j = 0; j < 8; j++)
#pragma unroll
                for (int e = 0; e < 4; e++) cs[j][e] = 0.0f;

#pragma unroll
            for (int j = 0; j < 8; j++) {
                int rowa = j * 8 + (lane & 7);
#pragma unroll
                for (int u = 0; u < 2; u++) {
                    int cola = u * 32 + ((lane >> 3) << 3);
                    uint32_t kh[4];
                    LDMX4(kh, bKh + rowa * ASTRIDE + cola * 2);
                    MMA_F16(cs[j], qfh[2 * u],     kh);
                    MMA_F16(cs[j], qfl[2 * u],     kh);
                    MMA_F16(cs[j], qfh[2 * u + 1], kh + 2);
                    MMA_F16(cs[j], qfl[2 * u + 1], kh + 2);
                }
            }

            // ---- scale + causal mask ----
            if (k0 + 63 >= q0 + (w << 4)) {
#pragma unroll
                for (int j = 0; j < 8; j++)
#pragma unroll
                    for (int e = 0; e < 4; e++) {
                        int gcol = k0 + j * 8 + cbase + (e & 1);
                        int grow = q0 + (w << 4) + r0 + 8 * (e >> 1);
                        float sv = cs[j][e] * 0.25f;
                        cs[j][e] = (gcol > grow) ? -1e30f : sv;
                    }
            } else {
#pragma unroll
                for (int j = 0; j < 8; j++)
#pragma unroll
                    for (int e = 0; e < 4; e++) cs[j][e] *= 0.25f;
            }

            // ---- online softmax ----
#pragma unroll
            for (int half = 0; half < 2; half++) {
                float mx = -1e30f;
#pragma unroll
                for (int j = 0; j < 8; j++)
                    mx = fmaxf(mx, fmaxf(cs[j][2 * half], cs[j][2 * half + 1]));
                mx = fmaxf(mx, __shfl_xor_sync(0xffffffffu, mx, 1));
                mx = fmaxf(mx, __shfl_xor_sync(0xffffffffu, mx, 2));
                float mn = fmaxf(mi[half], mx);
                float alpha = fast_exp(mi[half] - mn);
                mi[half] = mn;
                float rs = 0.0f;
#pragma unroll
                for (int j = 0; j < 8; j++) {
                    float p0 = fast_exp(cs[j][2 * half]     - mn);
                    float p1 = fast_exp(cs[j][2 * half + 1] - mn);
                    cs[j][2 * half] = p0;
                    cs[j][2 * half + 1] = p1;
                    rs += p0 + p1;
                }
                rs += __shfl_xor_sync(0xffffffffu, rs, 1);
                rs += __shfl_xor_sync(0xffffffffu, rs, 2);
                li[half] = li[half] * alpha + rs;
#pragma unroll
                for (int j = 0; j < 8; j++) {
                    co[j][2 * half]     *= alpha;
                    co[j][2 * half + 1] *= alpha;
                }
            }

            // ---- pack P (hi/lo) ----
            uint32_t pfh[4][4], pfl[4][4];
#pragma unroll
            for (int t = 0; t < 4; t++)
#pragma unroll
                for (int sub = 0; sub < 2; sub++) {
                    int j = 2 * t + sub;
                    split_pair(cs[j][0], cs[j][1],
                               pfh[t][sub * 2 + 0], pfl[t][sub * 2 + 0]);
                    split_pair(cs[j][2], cs[j][3],
                               pfh[t][sub * 2 + 1], pfl[t][sub * 2 + 1]);
                }

            // ---- O += (Ph+Pl) Vh ----
#pragma unroll
            for (int t = 0; t < 4; t++) {
                int rowv = t * 16 + (lane & 7) + ((lane >> 3) & 1) * 8;
#pragma unroll
                for (int np = 0; np < 4; np++) {
                    int colv = np * 16 + ((lane >> 4) << 3);
                    uint32_t vh[4];
                    LDMX4T(vh, bVh + rowv * ASTRIDE + colv * 2);
                    MMA_F16(co[2 * np],     pfh[t], vh);
                    MMA_F16(co[2 * np],     pfl[t], vh);
                    MMA_F16(co[2 * np + 1], pfh[t], vh + 2);
                    MMA_F16(co[2 * np + 1], pfl[t], vh + 2);
                }
            }
        }
        __syncthreads();
    }

    // ---- epilogue ----
    float inv0 = 1.0f / li[0], inv1 = 1.0f / li[1];
#pragma unroll
    for (int j = 0; j < 8; j++) {
#pragma unroll
        for (int half = 0; half < 2; half++) {
            float inv = half ? inv1 : inv0;
            int row = (w << 4) + r0 + 8 * half;
            int m = b * TT + q0 + row;
            int Pidx = h * 32 + j * 4 + (lane & 3);
            uint2 o;
            split_pair(co[j][2 * half] * inv, co[j][2 * half + 1] * inv,
                       o.x, o.y);
            *(uint2*)(atts + (size_t)m * 4096 + pairoff(Pidx)) = o;
        }
    }
}

// ---------------------------------------------------------------------------
extern "C" void kernel_launch(void* const* d_in, const int* in_sizes, int n_in,
                              void* d_out, int out_size)
{
    const float* x      = (const float*)d_in[0];
    const float* w_attn = (const float*)d_in[1];
    const float* b_attn = (const float*)d_in[2];
    const float* w_proj = (const float*)d_in[3];
    const float* b_proj = (const float*)d_in[4];

    float* out = (float*)d_out;
    float* a_out = out;
    float* present = out + (size_t)M_TOT * DD;

    unsigned char *xs, *bta, *btp, *atts;
    __half *qsp, *ksp, *vsp;
    cudaGetSymbolAddress((void**)&xs,   g_xs);
    cudaGetSymbolAddress((void**)&bta,  g_bta);
    cudaGetSymbolAddress((void**)&btp,  g_btp);
    cudaGetSymbolAddress((void**)&atts, g_atts);
    cudaGetSymbolAddress((void**)&qsp,  g_qs);
    cudaGetSymbolAddress((void**)&ksp,  g_ks);
    cudaGetSymbolAddress((void**)&vsp,  g_vs);

    cudaFuncSetAttribute(f16_gemm_kernel,
                         cudaFuncAttributeMaxDynamicSharedMemorySize, GSMEM);
    cudaFuncSetAttribute(attn_mma_kernel,
                         cudaFuncAttributeMaxDynamicSharedMemorySize, ATT_SMEM);

    // Prepasses
    split_kernel<<<(M_TOT * DD / 4 + 255) / 256, 256>>>(
        (const float4*)x, xs, M_TOT * DD / 4);
    transpose_split_kernel<<<dim3(3 * DD / 32, DD / 32), dim3(32, 8)>>>(
        w_attn, bta, DD, 3 * DD);
    transpose_split_kernel<<<dim3(DD / 32, DD / 32), dim3(32, 8)>>>(
        w_proj, btp, DD, DD);

    // QKV GEMM (3-term) -> q hi/lo, k/v hi + fp32 present
    f16_gemm_kernel<<<dim3(3 * DD / 128, M_TOT / 128), 256, GSMEM>>>(
        xs, bta, b_attn, nullptr, qsp, ksp, vsp, present, DD, 3 * DD, 0);

    // Tensor-core flash attention (2-term) -> g_atts
    attn_mma_kernel<<<dim3(TT / 128, HH, BB), 256, ATT_SMEM>>>(
        qsp, ksp, vsp, atts);

    // Projection GEMM (2-term) -> a_out
    f16_gemm_kernel<<<dim3(DD / 128, M_TOT / 128), 256, GSMEM>>>(
        atts, btp, b_proj, a_out, nullptr, nullptr, nullptr, nullptr,
        DD, DD, 1);
}

// round 9
// speedup vs baseline: 3.3676x; 1.2132x over previous
#include <cuda_runtime.h>
#include <cuda_fp16.h>
#include <cstdint>

// Problem constants
#define BB 2
#define TT 2048
#define DD 1024
#define HH 16
#define DHH 64
#define M_TOT (BB*TT)                 // 4096
#define PRESENT_HALF (BB*HH*TT*DHH)   // 4194304
#define PLANE ((size_t)BB*HH*TT*DHH)  // elements per hi/lo plane

// ---------------------------------------------------------------------------
// Device-global scratch.
// B-operand layout (weights, hi+lo interleaved): row [K], K/16 chunks of 64B,
//   chunk = pairs [p0,p4,p1,p5,p2,p6,p3,p7], pair = 8B [hi2|lo2] fp16.
// A-operand layout (x, attn-out; hi only): row [K], K/16 chunks of 32B,
//   chunk = pairs [p0,p4,p1,p5,p2,p6,p3,p7], pair = 4B [hi(2k),hi(2k+1)].
// Attention planes: Q = [hi|lo], K/V = hi only. [B][H][T][64] fp16.
// ---------------------------------------------------------------------------
__device__ unsigned char g_xs[(size_t)M_TOT * DD * 2];
__device__ unsigned char g_bta[(size_t)3 * DD * DD * 4];
__device__ unsigned char g_btp[(size_t)DD * DD * 4];
__device__ __half g_qs[2 * PLANE];
__device__ __half g_ks[PLANE];
__device__ __half g_vs[PLANE];
__device__ unsigned char g_atts[(size_t)M_TOT * DD * 2];

// ---------------------------------------------------------------------------
// Helpers
// ---------------------------------------------------------------------------
__device__ __forceinline__ uint32_t smem_to_u32(const void* smem_ptr) {
    uint32_t addr;
    asm("{ .reg .u64 tmp; cvta.to.shared.u64 tmp, %1; cvt.u32.u64 %0, tmp; }"
        : "=r"(addr) : "l"(smem_ptr));
    return addr;
}

__device__ __forceinline__ uint32_t pack2h(float a, float b) {
    __half2 h = __floats2half2_rn(a, b);
    return *reinterpret_cast<uint32_t*>(&h);
}

__device__ __forceinline__ void split_pair(float a, float b,
                                           uint32_t& wh, uint32_t& wl) {
    __half ha = __float2half_rn(a);
    __half hb = __float2half_rn(b);
    float la = a - __half2float(ha);
    float lb = b - __half2float(hb);
    __half2 h = __halves2half2(ha, hb);
    __half2 l = __floats2half2_rn(la, lb);
    wh = *reinterpret_cast<uint32_t*>(&h);
    wl = *reinterpret_cast<uint32_t*>(&l);
}

// byte offset of k-pair P: B layout (8B pairs) and A layout (4B pairs)
__device__ __forceinline__ int pairoffB(int P) {
    int ch = P >> 3, p = P & 7;
    return ch * 64 + (p & 3) * 16 + (p >> 2) * 8;
}
__device__ __forceinline__ int pairoffA(int P) {
    int ch = P >> 3, p = P & 7;
    return ch * 32 + (p & 3) * 8 + (p >> 2) * 4;
}

__device__ __forceinline__ float fast_exp(float x) {
    x = fmaxf(x, -87.0f);
    float t = fmaf(x, 1.4426950408889634f, 12582912.0f);
    int   ni = __float_as_int(t);
    float n = t - 12582912.0f;
    float f = fmaf(x, 1.4426950408889634f, -n);
    float p = 1.3333558146e-3f;
    p = fmaf(p, f, 9.6181291076e-3f);
    p = fmaf(p, f, 5.5504108665e-2f);
    p = fmaf(p, f, 2.4022650696e-1f);
    p = fmaf(p, f, 6.9314718056e-1f);
    p = fmaf(p, f, 1.0f);
    return __int_as_float(__float_as_int(p) + (int)((unsigned)ni << 23));
}

#define CP16(s, g) \
    asm volatile("cp.async.cg.shared.global [%0], [%1], 16;" :: "r"(s), "l"(g))
#define CP_COMMIT() asm volatile("cp.async.commit_group;" ::: "memory")
#define CP_WAIT1()  asm volatile("cp.async.wait_group 1;" ::: "memory")
#define CP_WAIT2()  asm volatile("cp.async.wait_group 2;" ::: "memory")

#define MMA_F16(c, a, b) \
    asm volatile("mma.sync.aligned.m16n8k16.row.col.f32.f16.f16.f32 " \
        "{%0,%1,%2,%3},{%4,%5,%6,%7},{%8,%9},{%0,%1,%2,%3};" \
        : "+f"((c)[0]), "+f"((c)[1]), "+f"((c)[2]), "+f"((c)[3]) \
        : "r"((a)[0]), "r"((a)[1]), "r"((a)[2]), "r"((a)[3]), \
          "r"((b)[0]), "r"((b)[1]))

#define LDMX4(R, addr) \
    asm volatile("ldmatrix.sync.aligned.m8n8.x4.shared.b16 {%0,%1,%2,%3}, [%4];" \
        : "=r"((R)[0]), "=r"((R)[1]), "=r"((R)[2]), "=r"((R)[3]) : "r"(addr))

#define LDMX4T(R, addr) \
    asm volatile("ldmatrix.sync.aligned.m8n8.x4.trans.shared.b16 {%0,%1,%2,%3}, [%4];" \
        : "=r"((R)[0]), "=r"((R)[1]), "=r"((R)[2]), "=r"((R)[3]) : "r"(addr))

// ---------------------------------------------------------------------------
// Prepass 1: x -> hi-only interleaved A layout (K = 1024 fixed, row = 2048B)
// ---------------------------------------------------------------------------
__global__ void split_kernel(const float4* __restrict__ src,
                             unsigned char* __restrict__ dst, int n4)
{
    int i = blockIdx.x * blockDim.x + threadIdx.x;
    if (i < n4) {
        float4 v = src[i];
        int e = 4 * i;
        int row = e >> 10;
        int P0 = (e & 1023) >> 1;
        unsigned char* base = dst + (size_t)row * 2048;
        *(uint32_t*)(base + pairoffA(P0))     = pack2h(v.x, v.y);
        *(uint32_t*)(base + pairoffA(P0 + 1)) = pack2h(v.z, v.w);
    }
}

// ---------------------------------------------------------------------------
// Prepass 2: W[K,N] -> Bt[N][K] interleaved packed-split (hi+lo)
// ---------------------------------------------------------------------------
__global__ void transpose_split_kernel(const float* __restrict__ w,
                                       unsigned char* __restrict__ bt,
                                       int Kd, int Nd)
{
    __shared__ float t[32][33];
    int n0 = blockIdx.x * 32, k0 = blockIdx.y * 32;
    int tx = threadIdx.x, ty = threadIdx.y;
#pragma unroll
    for (int i = 0; i < 32; i += 8)
        t[ty + i][tx] = w[(size_t)(k0 + ty + i) * Nd + n0 + tx];
    __syncthreads();
    int tid = ty * 32 + tx;
    int po = tid & 15;
    int nl = tid >> 4;
#pragma unroll
    for (int half = 0; half < 2; half++) {
        int n_loc = nl + half * 16;
        float v0 = t[2 * po][n_loc];
        float v1 = t[2 * po + 1][n_loc];
        uint2 o;
        split_pair(v0, v1, o.x, o.y);
        *(uint2*)(bt + (size_t)(n0 + n_loc) * Kd * 4
                     + pairoffB((k0 >> 1) + po)) = o;
    }
}

// ---------------------------------------------------------------------------
// fp16 2-term mma.sync GEMM: C = Ahi @ (Bhi+Blo)^T + bias
// CTA 128x128, 256 thr, chunk 16k, 4-stage (stage = A 4KB + B 8KB).
// Term-major MMA issue for accumulator ILP.
// mode 0: QKV -> q hi/lo, k/v hi planes + fp32 present. mode 1: plain C.
// ---------------------------------------------------------------------------
#define GSTAGE 12288
#define GSMEM  (4 * GSTAGE)

__global__ __launch_bounds__(256, 2) void f16_gemm_kernel(
    const unsigned char* __restrict__ Ag, const unsigned char* __restrict__ Bg,
    const float* __restrict__ bias,
    float* __restrict__ Cout,
    __half* __restrict__ qsp, __half* __restrict__ ksp,
    __half* __restrict__ vsp,
    float* __restrict__ present, int K, int N, int mode)
{
    extern __shared__ char smem[];
    const uint32_t smem_u = smem_to_u32(smem);
    const int tid = threadIdx.x;
    const int lane = tid & 31, wid = tid >> 5;
    const int wm = wid & 1, wn = wid >> 1;
    const int rowBase = blockIdx.y * 128, colBase = blockIdx.x * 128;
    const int NCH = K >> 4;

    const int ldr = tid >> 1;
    const unsigned char* gA = Ag + (size_t)(rowBase + ldr) * (K * 2)
                                 + (tid & 1) * 16;
    const unsigned char* gB = Bg + (size_t)(colBase + ldr) * (K * 4)
                                 + (tid & 1) * 32;
    const uint32_t sA = smem_u + ldr * 32 + (tid & 1) * 16;
    const uint32_t sB = smem_u + 4096 + ldr * 64 + (tid & 1) * 32;

#define LOAD_STAGE(chunk, stg) do {                        \
        uint32_t so = (uint32_t)(stg) * GSTAGE;            \
        CP16(sA + so,      gA + (size_t)(chunk) * 32);     \
        CP16(sB + so,      gB + (size_t)(chunk) * 64);     \
        CP16(sB + so + 16, gB + (size_t)(chunk) * 64 + 16);\
    } while (0)

    float c[4][4][4];
#pragma unroll
    for (int i = 0; i < 4; i++)
#pragma unroll
        for (int j = 0; j < 4; j++)
#pragma unroll
            for (int r = 0; r < 4; r++) c[i][j][r] = 0.0f;

    LOAD_STAGE(0, 0); CP_COMMIT();
    LOAD_STAGE(1, 1); CP_COMMIT();
    LOAD_STAGE(2, 2); CP_COMMIT();

    const char* smem_c = smem;
    for (int ch = 0; ch < NCH; ch++) {
        CP_WAIT2();
        __syncthreads();
        const int s = ch & 3;
        const char* As = smem_c + s * GSTAGE;
        const char* Bs = As + 4096;

        uint32_t ah[4][4];
#pragma unroll
        for (int mf = 0; mf < 4; mf++) {
            int r = wm * 64 + mf * 16 + (lane >> 2);
            const char* p = As + r * 32 + (lane & 3) * 8;
            uint2 t0 = *(const uint2*)(p);
            uint2 t1 = *(const uint2*)(p + 256);   // +8 rows
            ah[mf][0] = t0.x; ah[mf][2] = t0.y;
            ah[mf][1] = t1.x; ah[mf][3] = t1.y;
        }
        uint32_t bh[4][2], bl[4][2];
#pragma unroll
        for (int nf = 0; nf < 4; nf++) {
            int n = wn * 32 + nf * 8 + (lane >> 2);
            uint4 V = *(const uint4*)(Bs + n * 64 + (lane & 3) * 16);
            bh[nf][0] = V.x; bl[nf][0] = V.y;
            bh[nf][1] = V.z; bl[nf][1] = V.w;
        }
        // term-major: accumulator revisit distance = 16 MMAs
#pragma unroll
        for (int mf = 0; mf < 4; mf++)
#pragma unroll
            for (int nf = 0; nf < 4; nf++)
                MMA_F16(c[mf][nf], ah[mf], bh[nf]);
#pragma unroll
        for (int mf = 0; mf < 4; mf++)
#pragma unroll
            for (int nf = 0; nf < 4; nf++)
                MMA_F16(c[mf][nf], ah[mf], bl[nf]);
        __syncthreads();
        if (ch + 3 < NCH) LOAD_STAGE(ch + 3, (ch + 3) & 3);
        CP_COMMIT();
    }

    // Epilogue
#pragma unroll
    for (int mf = 0; mf < 4; mf++) {
#pragma unroll
        for (int nf = 0; nf < 4; nf++) {
            int m0 = rowBase + wm * 64 + mf * 16 + (lane >> 2);
            int n  = colBase + wn * 32 + nf * 8 + (lane & 3) * 2;
            float b0 = bias[n], b1 = bias[n + 1];
#pragma unroll
            for (int half = 0; half < 2; half++) {
                int m = m0 + half * 8;
                float2 v;
                v.x = c[mf][nf][half * 2 + 0] + b0;
                v.y = c[mf][nf][half * 2 + 1] + b1;
                if (mode == 1) {
                    *(float2*)&Cout[(size_t)m * N + n] = v;
                } else {
                    int seg = n >> 10, nn = n & 1023;
                    int hh = nn >> 6, d = nn & 63;
                    int bb = m >> 11, t = m & 2047;
                    size_t idx = (((size_t)(bb * HH + hh)) * TT + t) * DHH + d;
                    if (seg == 0) {
                        uint32_t wh, wl;
                        split_pair(v.x, v.y, wh, wl);
                        *(uint32_t*)&qsp[idx] = wh;
                        *(uint32_t*)&qsp[PLANE + idx] = wl;
                    } else if (seg == 1) {
                        *(float2*)&present[idx] = v;
                        *(uint32_t*)&ksp[idx] = pack2h(v.x, v.y);
                    } else {
                        *(float2*)&present[PRESENT_HALF + idx] = v;
                        *(uint32_t*)&vsp[idx] = pack2h(v.x, v.y);
                    }
                }
            }
        }
    }
}

// ---------------------------------------------------------------------------
// Flash attention on tensor cores (fp16, 2-term Q/P vs hi-only K/V).
// Block: 128 q-rows x 64 k-cols, 8 warps, reversed qt for load balance.
// Fragment-batched MMA issue for accumulator ILP.
// ---------------------------------------------------------------------------
#define ASTRIDE 144
#define ABYTES  (64 * ASTRIDE)
#define QBYTES  (128 * ASTRIDE)
#define ATT_SMEM (2 * QBYTES + 2 * 2 * ABYTES)   // 73728

__device__ __forceinline__ void att_load_stage(
    uint32_t dst, const __half* kh_g, const __half* vh_g, int k0, int tid)
{
    int r = tid >> 2;
    int qo = (tid & 3) * 32;
    const char* skh = (const char*)(kh_g + (size_t)(k0 + r) * DHH) + qo;
    const char* svh = (const char*)(vh_g + (size_t)(k0 + r) * DHH) + qo;
    uint32_t d0 = dst + r * ASTRIDE + qo;
#pragma unroll
    for (int i = 0; i < 2; i++) {
        CP16(d0 + i * 16,          skh + i * 16);
        CP16(d0 + ABYTES + i * 16, svh + i * 16);
    }
}

__global__ __launch_bounds__(256) void attn_mma_kernel(
    const __half* __restrict__ qs, const __half* __restrict__ ks,
    const __half* __restrict__ vs, unsigned char* __restrict__ atts)
{
    extern __shared__ char sm[];
    const uint32_t su = smem_to_u32(sm);
    const int tid = threadIdx.x, lane = tid & 31, w = tid >> 5;
    const int qt = gridDim.x - 1 - blockIdx.x;
    const int h = blockIdx.y, b = blockIdx.z;
    const int q0 = qt * 128;
    const size_t headoff = ((size_t)(b * HH + h)) * TT * DHH;

    const uint32_t sQh = su;
    const uint32_t sQl = su + QBYTES;
    const uint32_t sStg = su + 2 * QBYTES;

    const __half* qh_g = qs + headoff;
    const __half* ql_g = qs + PLANE + headoff;
    const __half* kh_g = ks + headoff;
    const __half* vh_g = vs + headoff;

    // preload Q (hi+lo, 128 rows) + stage 0
    {
        int r = tid >> 1;
        int cb = (tid & 1) * 64;
        const char* sh = (const char*)(qh_g + (size_t)(q0 + r) * DHH) + cb;
        const char* sl = (const char*)(ql_g + (size_t)(q0 + r) * DHH) + cb;
        uint32_t dh_ = sQh + r * ASTRIDE + cb;
        uint32_t dl_ = sQl + r * ASTRIDE + cb;
#pragma unroll
        for (int i = 0; i < 4; i++) {
            CP16(dh_ + i * 16, sh + i * 16);
            CP16(dl_ + i * 16, sl + i * 16);
        }
        att_load_stage(sStg, kh_g, vh_g, 0, tid);
    }
    CP_COMMIT();

    uint32_t qfh[4][4], qfl[4][4];
    float co[8][4];
#pragma unroll
    for (int j = 0; j < 8; j++)
#pragma unroll
        for (int e = 0; e < 4; e++) co[j][e] = 0.0f;
    float mi[2] = {-1e30f, -1e30f}, li[2] = {0.0f, 0.0f};

    const int r0 = lane >> 2;
    const int cbase = 2 * (lane & 3);
    const int ntiles = 2 * qt + 2;

    for (int kt = 0; kt < ntiles; kt++) {
        const int s = kt & 1;
        const int k0 = kt * 64;
        if (kt + 1 < ntiles)
            att_load_stage(sStg + (s ^ 1) * 2 * ABYTES, kh_g, vh_g,
                           (kt + 1) * 64, tid);
        CP_COMMIT();
        CP_WAIT1();
        __syncthreads();

        if (kt == 0) {
            int row = (w << 4) + (lane & 15);
            int colb = ((lane >> 4) << 3);
#pragma unroll
            for (int t = 0; t < 4; t++) {
                LDMX4(qfh[t], sQh + row * ASTRIDE + (t * 16 + colb) * 2);
                LDMX4(qfl[t], sQl + row * ASTRIDE + (t * 16 + colb) * 2);
            }
        }

        const bool active = (k0 <= q0 + (w << 4) + 15);

        if (active) {
            const uint32_t bKh = sStg + s * 2 * ABYTES;
            const uint32_t bVh = bKh + ABYTES;

            // ---- S = (Qh+Ql) Kh^T : fragment-batched, j-major MMA issue ----
            float cs[8][4];
#pragma unroll
            for (int j = 0; j < 8; j++)
#pragma unroll
                for (int e = 0; e < 4; e++) cs[j][e] = 0.0f;

#pragma unroll
            for (int u = 0; u < 2; u++) {
                uint32_t kf[8][4];
                int cola = u * 32 + ((lane >> 3) << 3);
#pragma unroll
                for (int j = 0; j < 8; j++) {
                    int rowa = j * 8 + (lane & 7);
                    LDMX4(kf[j], bKh + rowa * ASTRIDE + cola * 2);
                }
#pragma unroll
                for (int j = 0; j < 8; j++) MMA_F16(cs[j], qfh[2 * u], kf[j]);
#pragma unroll
                for (int j = 0; j < 8; j++) MMA_F16(cs[j], qfl[2 * u], kf[j]);
#pragma unroll
                for (int j = 0; j < 8; j++) MMA_F16(cs[j], qfh[2 * u + 1], kf[j] + 2);
#pragma unroll
                for (int j = 0; j < 8; j++) MMA_F16(cs[j], qfl[2 * u + 1], kf[j] + 2);
            }

            // ---- scale + causal mask ----
            if (k0 + 63 >= q0 + (w << 4)) {
#pragma unroll
                for (int j = 0; j < 8; j++)
#pragma unroll
                    for (int e = 0; e < 4; e++) {
                        int gcol = k0 + j * 8 + cbase + (e & 1);
                        int grow = q0 + (w << 4) + r0 + 8 * (e >> 1);
                        float sv = cs[j][e] * 0.25f;
                        cs[j][e] = (gcol > grow) ? -1e30f : sv;
                    }
            } else {
#pragma unroll
                for (int j = 0; j < 8; j++)
#pragma unroll
                    for (int e = 0; e < 4; e++) cs[j][e] *= 0.25f;
            }

            // ---- online softmax ----
#pragma unroll
            for (int half = 0; half < 2; half++) {
                float mx = -1e30f;
#pragma unroll
                for (int j = 0; j < 8; j++)
                    mx = fmaxf(mx, fmaxf(cs[j][2 * half], cs[j][2 * half + 1]));
                mx = fmaxf(mx, __shfl_xor_sync(0xffffffffu, mx, 1));
                mx = fmaxf(mx, __shfl_xor_sync(0xffffffffu, mx, 2));
                float mn = fmaxf(mi[half], mx);
                float alpha = fast_exp(mi[half] - mn);
                mi[half] = mn;
                float rs = 0.0f;
#pragma unroll
                for (int j = 0; j < 8; j++) {
                    float p0 = fast_exp(cs[j][2 * half]     - mn);
                    float p1 = fast_exp(cs[j][2 * half + 1] - mn);
                    cs[j][2 * half] = p0;
                    cs[j][2 * half + 1] = p1;
                    rs += p0 + p1;
                }
                rs += __shfl_xor_sync(0xffffffffu, rs, 1);
                rs += __shfl_xor_sync(0xffffffffu, rs, 2);
                li[half] = li[half] * alpha + rs;
#pragma unroll
                for (int j = 0; j < 8; j++) {
                    co[j][2 * half]     *= alpha;
                    co[j][2 * half + 1] *= alpha;
                }
            }

            // ---- pack P (hi/lo) ----
            uint32_t pfh[4][4], pfl[4][4];
#pragma unroll
            for (int t = 0; t < 4; t++)
#pragma unroll
                for (int sub = 0; sub < 2; sub++) {
                    int j = 2 * t + sub;
                    split_pair(cs[j][0], cs[j][1],
                               pfh[t][sub * 2 + 0], pfl[t][sub * 2 + 0]);
                    split_pair(cs[j][2], cs[j][3],
                               pfh[t][sub * 2 + 1], pfl[t][sub * 2 + 1]);
                }

            // ---- O += (Ph+Pl) Vh : fragment-batched, np-major issue ----
#pragma unroll
            for (int t = 0; t < 4; t++) {
                uint32_t vf[4][4];
                int rowv = t * 16 + (lane & 7) + ((lane >> 3) & 1) * 8;
#pragma unroll
                for (int np = 0; np < 4; np++) {
                    int colv = np * 16 + ((lane >> 4) << 3);
                    LDMX4T(vf[np], bVh + rowv * ASTRIDE + colv * 2);
                }
#pragma unroll
                for (int np = 0; np < 4; np++) {
                    MMA_F16(co[2 * np],     pfh[t], vf[np]);
                    MMA_F16(co[2 * np + 1], pfh[t], vf[np] + 2);
                }
#pragma unroll
                for (int np = 0; np < 4; np++) {
                    MMA_F16(co[2 * np],     pfl[t], vf[np]);
                    MMA_F16(co[2 * np + 1], pfl[t], vf[np] + 2);
                }
            }
        }
        __syncthreads();
    }

    // ---- epilogue: normalize, write hi-only A layout for proj ----
    float inv0 = 1.0f / li[0], inv1 = 1.0f / li[1];
#pragma unroll
    for (int j = 0; j < 8; j++) {
#pragma unroll
        for (int half = 0; half < 2; half++) {
            float inv = half ? inv1 : inv0;
            int row = (w << 4) + r0 + 8 * half;
            int m = b * TT + q0 + row;
            int Pidx = h * 32 + j * 4 + (lane & 3);
            *(uint32_t*)(atts + (size_t)m * 2048 + pairoffA(Pidx)) =
                pack2h(co[j][2 * half] * inv, co[j][2 * half + 1] * inv);
        }
    }
}

// ---------------------------------------------------------------------------
extern "C" void kernel_launch(void* const* d_in, const int* in_sizes, int n_in,
                              void* d_out, int out_size)
{
    const float* x      = (const float*)d_in[0];
    const float* w_attn = (const float*)d_in[1];
    const float* b_attn = (const float*)d_in[2];
    const float* w_proj = (const float*)d_in[3];
    const float* b_proj = (const float*)d_in[4];

    float* out = (float*)d_out;
    float* a_out = out;
    float* present = out + (size_t)M_TOT * DD;

    unsigned char *xs, *bta, *btp, *atts;
    __half *qsp, *ksp, *vsp;
    cudaGetSymbolAddress((void**)&xs,   g_xs);
    cudaGetSymbolAddress((void**)&bta,  g_bta);
    cudaGetSymbolAddress((void**)&btp,  g_btp);
    cudaGetSymbolAddress((void**)&atts, g_atts);
    cudaGetSymbolAddress((void**)&qsp,  g_qs);
    cudaGetSymbolAddress((void**)&ksp,  g_ks);
    cudaGetSymbolAddress((void**)&vsp,  g_vs);

    cudaFuncSetAttribute(f16_gemm_kernel,
                         cudaFuncAttributeMaxDynamicSharedMemorySize, GSMEM);
    cudaFuncSetAttribute(attn_mma_kernel,
                         cudaFuncAttributeMaxDynamicSharedMemorySize, ATT_SMEM);

    // Prepasses
    split_kernel<<<(M_TOT * DD / 4 + 255) / 256, 256>>>(
        (const float4*)x, xs, M_TOT * DD / 4);
    transpose_split_kernel<<<dim3(3 * DD / 32, DD / 32), dim3(32, 8)>>>(
        w_attn, bta, DD, 3 * DD);
    transpose_split_kernel<<<dim3(DD / 32, DD / 32), dim3(32, 8)>>>(
        w_proj, btp, DD, DD);

    // QKV GEMM (2-term) -> q hi/lo, k/v hi + fp32 present
    f16_gemm_kernel<<<dim3(3 * DD / 128, M_TOT / 128), 256, GSMEM>>>(
        xs, bta, b_attn, nullptr, qsp, ksp, vsp, present, DD, 3 * DD, 0);

    // Tensor-core flash attention (2-term) -> g_atts (hi-only)
    attn_mma_kernel<<<dim3(TT / 128, HH, BB), 256, ATT_SMEM>>>(
        qsp, ksp, vsp, atts);

    // Projection GEMM (2-term) -> a_out
    f16_gemm_kernel<<<dim3(DD / 128, M_TOT / 128), 256, GSMEM>>>(
        atts, btp, b_proj, a_out, nullptr, nullptr, nullptr, nullptr,
        DD, DD, 1);
}

// round 11
// speedup vs baseline: 3.5879x; 1.0654x over previous
#include <cuda_runtime.h>
#include <cuda_fp16.h>
#include <cstdint>

// Problem constants
#define BB 2
#define TT 2048
#define DD 1024
#define HH 16
#define DHH 64
#define M_TOT (BB*TT)                 // 4096
#define PRESENT_HALF (BB*HH*TT*DHH)   // 4194304
#define PLANE ((size_t)BB*HH*TT*DHH)  // elements per hi/lo plane
#define GK 1024                       // GEMM K (compile-time)
#define NCH 64                        // GK/16 chunks

// ---------------------------------------------------------------------------
// Device-global scratch.
// B-operand layout (weights, hi+lo interleaved): row [K], K/16 chunks of 64B,
//   chunk = pairs [p0,p4,p1,p5,p2,p6,p3,p7], pair = 8B [hi2|lo2] fp16.
// A-operand layout (x, attn-out; hi only): row [K], K/16 chunks of 32B,
//   chunk = pairs [p0,p4,p1,p5,p2,p6,p3,p7], pair = 4B [hi(2k),hi(2k+1)].
// Attention planes: Q = [hi|lo], K/V = hi only. [B][H][T][64] fp16.
// ---------------------------------------------------------------------------
__device__ unsigned char g_xs[(size_t)M_TOT * DD * 2];
__device__ unsigned char g_bta[(size_t)3 * DD * DD * 4];
__device__ unsigned char g_btp[(size_t)DD * DD * 4];
__device__ __half g_qs[2 * PLANE];
__device__ __half g_ks[PLANE];
__device__ __half g_vs[PLANE];
__device__ unsigned char g_atts[(size_t)M_TOT * DD * 2];

// ---------------------------------------------------------------------------
// Helpers
// ---------------------------------------------------------------------------
__device__ __forceinline__ uint32_t smem_to_u32(const void* smem_ptr) {
    uint32_t addr;
    asm("{ .reg .u64 tmp; cvta.to.shared.u64 tmp, %1; cvt.u32.u64 %0, tmp; }"
        : "=r"(addr) : "l"(smem_ptr));
    return addr;
}

__device__ __forceinline__ uint32_t pack2h(float a, float b) {
    __half2 h = __floats2half2_rn(a, b);
    return *reinterpret_cast<uint32_t*>(&h);
}

__device__ __forceinline__ void split_pair(float a, float b,
                                           uint32_t& wh, uint32_t& wl) {
    __half ha = __float2half_rn(a);
    __half hb = __float2half_rn(b);
    float la = a - __half2float(ha);
    float lb = b - __half2float(hb);
    __half2 h = __halves2half2(ha, hb);
    __half2 l = __floats2half2_rn(la, lb);
    wh = *reinterpret_cast<uint32_t*>(&h);
    wl = *reinterpret_cast<uint32_t*>(&l);
}

__device__ __forceinline__ int pairoffB(int P) {
    int ch = P >> 3, p = P & 7;
    return ch * 64 + (p & 3) * 16 + (p >> 2) * 8;
}
__device__ __forceinline__ int pairoffA(int P) {
    int ch = P >> 3, p = P & 7;
    return ch * 32 + (p & 3) * 8 + (p >> 2) * 4;
}

__device__ __forceinline__ float fast_exp(float x) {
    x = fmaxf(x, -87.0f);
    float t = fmaf(x, 1.4426950408889634f, 12582912.0f);
    int   ni = __float_as_int(t);
    float n = t - 12582912.0f;
    float f = fmaf(x, 1.4426950408889634f, -n);
    float p = 1.3333558146e-3f;
    p = fmaf(p, f, 9.6181291076e-3f);
    p = fmaf(p, f, 5.5504108665e-2f);
    p = fmaf(p, f, 2.4022650696e-1f);
    p = fmaf(p, f, 6.9314718056e-1f);
    p = fmaf(p, f, 1.0f);
    return __int_as_float(__float_as_int(p) + (int)((unsigned)ni << 23));
}

#define CP16(s, g) \
    asm volatile("cp.async.cg.shared.global [%0], [%1], 16;" :: "r"(s), "l"(g))
#define CP_COMMIT() asm volatile("cp.async.commit_group;" ::: "memory")
#define CP_WAIT1()  asm volatile("cp.async.wait_group 1;" ::: "memory")
#define CP_WAIT2()  asm volatile("cp.async.wait_group 2;" ::: "memory")

#define MMA_F16(c, a, b) \
    asm volatile("mma.sync.aligned.m16n8k16.row.col.f32.f16.f16.f32 " \
        "{%0,%1,%2,%3},{%4,%5,%6,%7},{%8,%9},{%0,%1,%2,%3};" \
        : "+f"((c)[0]), "+f"((c)[1]), "+f"((c)[2]), "+f"((c)[3]) \
        : "r"((a)[0]), "r"((a)[1]), "r"((a)[2]), "r"((a)[3]), \
          "r"((b)[0]), "r"((b)[1]))

#define LDMX4(R, addr) \
    asm volatile("ldmatrix.sync.aligned.m8n8.x4.shared.b16 {%0,%1,%2,%3}, [%4];" \
        : "=r"((R)[0]), "=r"((R)[1]), "=r"((R)[2]), "=r"((R)[3]) : "r"(addr))

#define LDMX4T(R, addr) \
    asm volatile("ldmatrix.sync.aligned.m8n8.x4.trans.shared.b16 {%0,%1,%2,%3}, [%4];" \
        : "=r"((R)[0]), "=r"((R)[1]), "=r"((R)[2]), "=r"((R)[3]) : "r"(addr))

// ---------------------------------------------------------------------------
// Prepass 1: x -> hi-only interleaved A layout
// ---------------------------------------------------------------------------
__global__ void split_kernel(const float4* __restrict__ src,
                             unsigned char* __restrict__ dst, int n4)
{
    int i = blockIdx.x * blockDim.x + threadIdx.x;
    if (i < n4) {
        float4 v = src[i];
        int e = 4 * i;
        int row = e >> 10;
        int P0 = (e & 1023) >> 1;
        unsigned char* base = dst + (size_t)row * 2048;
        *(uint32_t*)(base + pairoffA(P0))     = pack2h(v.x, v.y);
        *(uint32_t*)(base + pairoffA(P0 + 1)) = pack2h(v.z, v.w);
    }
}

// ---------------------------------------------------------------------------
// Prepass 2: W[K,N] -> Bt[N][K] interleaved packed-split (hi+lo)
// ---------------------------------------------------------------------------
__global__ void transpose_split_kernel(const float* __restrict__ w,
                                       unsigned char* __restrict__ bt,
                                       int Kd, int Nd)
{
    __shared__ float t[32][33];
    int n0 = blockIdx.x * 32, k0 = blockIdx.y * 32;
    int tx = threadIdx.x, ty = threadIdx.y;
#pragma unroll
    for (int i = 0; i < 32; i += 8)
        t[ty + i][tx] = w[(size_t)(k0 + ty + i) * Nd + n0 + tx];
    __syncthreads();
    int tid = ty * 32 + tx;
    int po = tid & 15;
    int nl = tid >> 4;
#pragma unroll
    for (int half = 0; half < 2; half++) {
        int n_loc = nl + half * 16;
        float v0 = t[2 * po][n_loc];
        float v1 = t[2 * po + 1][n_loc];
        uint2 o;
        split_pair(v0, v1, o.x, o.y);
        *(uint2*)(bt + (size_t)(n0 + n_loc) * Kd * 4
                     + pairoffB((k0 >> 1) + po)) = o;
    }
}

// ---------------------------------------------------------------------------
// fp16 2-term mma.sync GEMM: C = Ahi @ (Bhi+Blo)^T + bias.  K = GK (1024).
// CTA 128x128, 256 thr, chunk 16k, 4-stage, loop unrolled x4 so all stage
// addressing constant-folds.
// ---------------------------------------------------------------------------
#define GSTAGE 12288
#define GSMEM  (4 * GSTAGE)

__global__ __launch_bounds__(256, 2) void f16_gemm_kernel(
    const unsigned char* __restrict__ Ag, const unsigned char* __restrict__ Bg,
    const float* __restrict__ bias,
    float* __restrict__ Cout,
    __half* __restrict__ qsp, __half* __restrict__ ksp,
    __half* __restrict__ vsp,
    float* __restrict__ present, int N, int mode)
{
    extern __shared__ char smem[];
    const uint32_t smem_u = smem_to_u32(smem);
    const int tid = threadIdx.x;
    const int lane = tid & 31, wid = tid >> 5;
    const int wm = wid & 1, wn = wid >> 1;
    const int rowBase = blockIdx.y * 128, colBase = blockIdx.x * 128;

    const int ldr = tid >> 1;
    const unsigned char* gA = Ag + (size_t)(rowBase + ldr) * (GK * 2)
                                 + (tid & 1) * 16;
    const unsigned char* gB = Bg + (size_t)(colBase + ldr) * (GK * 4)
                                 + (tid & 1) * 32;
    const uint32_t sA = smem_u + ldr * 32 + (tid & 1) * 16;
    const uint32_t sB = smem_u + 4096 + ldr * 64 + (tid & 1) * 32;

#define LOAD_STAGE(chunk, stg) do {                        \
        uint32_t so = (uint32_t)(stg) * GSTAGE;            \
        CP16(sA + so,      gA + (size_t)(chunk) * 32);     \
        CP16(sB + so,      gB + (size_t)(chunk) * 64);     \
        CP16(sB + so + 16, gB + (size_t)(chunk) * 64 + 16);\
    } while (0)

    float c[4][4][4];
#pragma unroll
    for (int i = 0; i < 4; i++)
#pragma unroll
        for (int j = 0; j < 4; j++)
#pragma unroll
            for (int r = 0; r < 4; r++) c[i][j][r] = 0.0f;

    LOAD_STAGE(0, 0); CP_COMMIT();
    LOAD_STAGE(1, 1); CP_COMMIT();
    LOAD_STAGE(2, 2); CP_COMMIT();

    // per-thread invariant smem offsets
    const uint32_t aoff = (uint32_t)((wm * 64 + (lane >> 2)) * 32
                                     + (lane & 3) * 8);
    const uint32_t boff = (uint32_t)(4096 + (wn * 32 + (lane >> 2)) * 64
                                     + (lane & 3) * 16);

    const char* smem_c = smem;
#pragma unroll 4
    for (int ch = 0; ch < NCH; ch++) {
        CP_WAIT2();
        __syncthreads();
        const uint32_t sbase = (uint32_t)((ch & 3) * GSTAGE);

        uint32_t ah[4][4];
#pragma unroll
        for (int mf = 0; mf < 4; mf++) {
            const char* p = smem_c + aoff + sbase + mf * 512;
            uint2 t0 = *(const uint2*)(p);
            uint2 t1 = *(const uint2*)(p + 256);
            ah[mf][0] = t0.x; ah[mf][2] = t0.y;
            ah[mf][1] = t1.x; ah[mf][3] = t1.y;
        }
        uint32_t bh[4][2], bl[4][2];
#pragma unroll
        for (int nf = 0; nf < 4; nf++) {
            uint4 V = *(const uint4*)(smem_c + boff + sbase + nf * 512);
            bh[nf][0] = V.x; bl[nf][0] = V.y;
            bh[nf][1] = V.z; bl[nf][1] = V.w;
        }
        // term-major: accumulator revisit distance = 16 MMAs
#pragma unroll
        for (int mf = 0; mf < 4; mf++)
#pragma unroll
            for (int nf = 0; nf < 4; nf++)
                MMA_F16(c[mf][nf], ah[mf], bh[nf]);
#pragma unroll
        for (int mf = 0; mf < 4; mf++)
#pragma unroll
            for (int nf = 0; nf < 4; nf++)
                MMA_F16(c[mf][nf], ah[mf], bl[nf]);
        __syncthreads();
        if (ch + 3 < NCH) LOAD_STAGE(ch + 3, (ch + 3) & 3);
        CP_COMMIT();
    }

    // Epilogue
#pragma unroll
    for (int mf = 0; mf < 4; mf++) {
#pragma unroll
        for (int nf = 0; nf < 4; nf++) {
            int m0 = rowBase + wm * 64 + mf * 16 + (lane >> 2);
            int n  = colBase + wn * 32 + nf * 8 + (lane & 3) * 2;
            float b0 = bias[n], b1 = bias[n + 1];
#pragma unroll
            for (int half = 0; half < 2; half++) {
                int m = m0 + half * 8;
                float2 v;
                v.x = c[mf][nf][half * 2 + 0] + b0;
                v.y = c[mf][nf][half * 2 + 1] + b1;
                if (mode == 1) {
                    *(float2*)&Cout[(size_t)m * N + n] = v;
                } else {
                    int seg = n >> 10, nn = n & 1023;
                    int hh = nn >> 6, d = nn & 63;
                    int bb = m >> 11, t = m & 2047;
                    size_t idx = (((size_t)(bb * HH + hh)) * TT + t) * DHH + d;
                    if (seg == 0) {
                        uint32_t wh, wl;
                        split_pair(v.x, v.y, wh, wl);
                        *(uint32_t*)&qsp[idx] = wh;
                        *(uint32_t*)&qsp[PLANE + idx] = wl;
                    } else if (seg == 1) {
                        *(float2*)&present[idx] = v;
                        *(uint32_t*)&ksp[idx] = pack2h(v.x, v.y);
                    } else {
                        *(float2*)&present[PRESENT_HALF + idx] = v;
                        *(uint32_t*)&vsp[idx] = pack2h(v.x, v.y);
                    }
                }
            }
        }
    }
}

// ---------------------------------------------------------------------------
// Flash attention on tensor cores (fp16, 2-term Q/P vs hi-only K/V).
// Block: 128 q-rows x 64 k-cols, 8 warps, reversed qt. kt loop manually
// unrolled x2 so stage addressing constant-folds (ntiles always even).
// ---------------------------------------------------------------------------
#define ASTRIDE 144
#define ABYTES  (64 * ASTRIDE)
#define QBYTES  (128 * ASTRIDE)
#define ATT_SMEM (2 * QBYTES + 2 * 2 * ABYTES)   // 73728

__device__ __forceinline__ void att_load_stage(
    uint32_t dst, const __half* kh_g, const __half* vh_g, int k0, int tid)
{
    int r = tid >> 2;
    int qo = (tid & 3) * 32;
    const char* skh = (const char*)(kh_g + (size_t)(k0 + r) * DHH) + qo;
    const char* svh = (const char*)(vh_g + (size_t)(k0 + r) * DHH) + qo;
    uint32_t d0 = dst + r * ASTRIDE + qo;
#pragma unroll
    for (int i = 0; i < 2; i++) {
        CP16(d0 + i * 16,          skh + i * 16);
        CP16(d0 + ABYTES + i * 16, svh + i * 16);
    }
}

__global__ __launch_bounds__(256) void attn_mma_kernel(
    const __half* __restrict__ qs, const __half* __restrict__ ks,
    const __half* __restrict__ vs, unsigned char* __restrict__ atts)
{
    extern __shared__ char sm[];
    const uint32_t su = smem_to_u32(sm);
    const int tid = threadIdx.x, lane = tid & 31, w = tid >> 5;
    const int qt = gridDim.x - 1 - blockIdx.x;
    const int h = blockIdx.y, b = blockIdx.z;
    const int q0 = qt * 128;
    const size_t headoff = ((size_t)(b * HH + h)) * TT * DHH;

    const uint32_t sQh = su;
    const uint32_t sQl = su + QBYTES;
    const uint32_t sStg = su + 2 * QBYTES;

    const __half* qh_g = qs + headoff;
    const __half* ql_g = qs + PLANE + headoff;
    const __half* kh_g = ks + headoff;
    const __half* vh_g = vs + headoff;

    // preload Q (hi+lo, 128 rows) + stage 0
    {
        int r = tid >> 1;
        int cb = (tid & 1) * 64;
        const char* sh = (const char*)(qh_g + (size_t)(q0 + r) * DHH) + cb;
        const char* sl = (const char*)(ql_g + (size_t)(q0 + r) * DHH) + cb;
        uint32_t dh_ = sQh + r * ASTRIDE + cb;
        uint32_t dl_ = sQl + r * ASTRIDE + cb;
#pragma unroll
        for (int i = 0; i < 4; i++) {
            CP16(dh_ + i * 16, sh + i * 16);
            CP16(dl_ + i * 16, sl + i * 16);
        }
        att_load_stage(sStg, kh_g, vh_g, 0, tid);
    }
    CP_COMMIT();

    uint32_t qfh[4][4], qfl[4][4];
    float co[8][4];
#pragma unroll
    for (int j = 0; j < 8; j++)
#pragma unroll
        for (int e = 0; e < 4; e++) co[j][e] = 0.0f;
    float mi[2] = {-1e30f, -1e30f}, li[2] = {0.0f, 0.0f};

    const int r0 = lane >> 2;
    const int cbase = 2 * (lane & 3);
    const int ntiles = 2 * qt + 2;   // always even
    const int wrow = q0 + (w << 4);

    auto tile_body = [&](int kt, uint32_t bKh, uint32_t ldst) {
        const int k0 = kt * 64;
        if (kt + 1 < ntiles)
            att_load_stage(ldst, kh_g, vh_g, (kt + 1) * 64, tid);
        CP_COMMIT();
        CP_WAIT1();
        __syncthreads();

        if (kt == 0) {
            int row = (w << 4) + (lane & 15);
            int colb = ((lane >> 4) << 3);
#pragma unroll
            for (int t = 0; t < 4; t++) {
                LDMX4(qfh[t], sQh + row * ASTRIDE + (t * 16 + colb) * 2);
                LDMX4(qfl[t], sQl + row * ASTRIDE + (t * 16 + colb) * 2);
            }
        }

        const bool active = (k0 <= wrow + 15);
        if (active) {
            const uint32_t bVh = bKh + ABYTES;

            // ---- S = (Qh+Ql) Kh^T : fragment-batched ----
            float cs[8][4];
#pragma unroll
            for (int j = 0; j < 8; j++)
#pragma unroll
                for (int e = 0; e < 4; e++) cs[j][e] = 0.0f;

#pragma unroll
            for (int u = 0; u < 2; u++) {
                uint32_t kf[8][4];
                int cola = u * 32 + ((lane >> 3) << 3);
#pragma unroll
                for (int j = 0; j < 8; j++) {
                    int rowa = j * 8 + (lane & 7);
                    LDMX4(kf[j], bKh + rowa * ASTRIDE + cola * 2);
                }
#pragma unroll
                for (int j = 0; j < 8; j++) MMA_F16(cs[j], qfh[2 * u], kf[j]);
#pragma unroll
                for (int j = 0; j < 8; j++) MMA_F16(cs[j], qfl[2 * u], kf[j]);
#pragma unroll
                for (int j = 0; j < 8; j++) MMA_F16(cs[j], qfh[2 * u + 1], kf[j] + 2);
#pragma unroll
                for (int j = 0; j < 8; j++) MMA_F16(cs[j], qfl[2 * u + 1], kf[j] + 2);
            }

            // ---- scale + causal mask ----
            if (k0 + 63 >= wrow) {
#pragma unroll
                for (int j = 0; j < 8; j++)
#pragma unroll
                    for (int e = 0; e < 4; e++) {
                        int gcol = k0 + j * 8 + cbase + (e & 1);
                        int grow = wrow + r0 + 8 * (e >> 1);
                        float sv = cs[j][e] * 0.25f;
                        cs[j][e] = (gcol > grow) ? -1e30f : sv;
                    }
            } else {
#pragma unroll
                for (int j = 0; j < 8; j++)
#pragma unroll
                    for (int e = 0; e < 4; e++) cs[j][e] *= 0.25f;
            }

            // ---- online softmax ----
#pragma unroll
            for (int half = 0; half < 2; half++) {
                float mx = -1e30f;
#pragma unroll
                for (int j = 0; j < 8; j++)
                    mx = fmaxf(mx, fmaxf(cs[j][2 * half], cs[j][2 * half + 1]));
                mx = fmaxf(mx, __shfl_xor_sync(0xffffffffu, mx, 1));
                mx = fmaxf(mx, __shfl_xor_sync(0xffffffffu, mx, 2));
                float mn = fmaxf(mi[half], mx);
                float alpha = fast_exp(mi[half] - mn);
                mi[half] = mn;
                float rs = 0.0f;
#pragma unroll
                for (int j = 0; j < 8; j++) {
                    float p0 = fast_exp(cs[j][2 * half]     - mn);
                    float p1 = fast_exp(cs[j][2 * half + 1] - mn);
                    cs[j][2 * half] = p0;
                    cs[j][2 * half + 1] = p1;
                    rs += p0 + p1;
                }
                rs += __shfl_xor_sync(0xffffffffu, rs, 1);
                rs += __shfl_xor_sync(0xffffffffu, rs, 2);
                li[half] = li[half] * alpha + rs;
#pragma unroll
                for (int j = 0; j < 8; j++) {
                    co[j][2 * half]     *= alpha;
                    co[j][2 * half + 1] *= alpha;
                }
            }

            // ---- pack P (hi/lo) ----
            uint32_t pfh[4][4], pfl[4][4];
#pragma unroll
            for (int t = 0; t < 4; t++)
#pragma unroll
                for (int sub = 0; sub < 2; sub++) {
                    int j = 2 * t + sub;
                    split_pair(cs[j][0], cs[j][1],
                               pfh[t][sub * 2 + 0], pfl[t][sub * 2 + 0]);
                    split_pair(cs[j][2], cs[j][3],
                               pfh[t][sub * 2 + 1], pfl[t][sub * 2 + 1]);
                }

            // ---- O += (Ph+Pl) Vh : fragment-batched ----
#pragma unroll
            for (int t = 0; t < 4; t++) {
                uint32_t vf[4][4];
                int rowv = t * 16 + (lane & 7) + ((lane >> 3) & 1) * 8;
#pragma unroll
                for (int np = 0; np < 4; np++) {
                    int colv = np * 16 + ((lane >> 4) << 3);
                    LDMX4T(vf[np], bVh + rowv * ASTRIDE + colv * 2);
                }
#pragma unroll
                for (int np = 0; np < 4; np++) {
                    MMA_F16(co[2 * np],     pfh[t], vf[np]);
                    MMA_F16(co[2 * np + 1], pfh[t], vf[np] + 2);
                }
#pragma unroll
                for (int np = 0; np < 4; np++) {
                    MMA_F16(co[2 * np],     pfl[t], vf[np]);
                    MMA_F16(co[2 * np + 1], pfl[t], vf[np] + 2);
                }
            }
        }
        __syncthreads();
    };

    const uint32_t st0 = sStg;
    const uint32_t st1 = sStg + 2 * ABYTES;
    for (int kt = 0; kt < ntiles; kt += 2) {
        tile_body(kt,     st0, st1);
        tile_body(kt + 1, st1, st0);
    }

    // ---- epilogue: normalize, write hi-only A layout for proj ----
    float inv0 = 1.0f / li[0], inv1 = 1.0f / li[1];
#pragma unroll
    for (int j = 0; j < 8; j++) {
#pragma unroll
        for (int half = 0; half < 2; half++) {
            float inv = half ? inv1 : inv0;
            int row = (w << 4) + r0 + 8 * half;
            int m = b * TT + q0 + row;
            int Pidx = h * 32 + j * 4 + (lane & 3);
            *(uint32_t*)(atts + (size_t)m * 2048 + pairoffA(Pidx)) =
                pack2h(co[j][2 * half] * inv, co[j][2 * half + 1] * inv);
        }
    }
}

// ---------------------------------------------------------------------------
extern "C" void kernel_launch(void* const* d_in, const int* in_sizes, int n_in,
                              void* d_out, int out_size)
{
    const float* x      = (const float*)d_in[0];
    const float* w_attn = (const float*)d_in[1];
    const float* b_attn = (const float*)d_in[2];
    const float* w_proj = (const float*)d_in[3];
    const float* b_proj = (const float*)d_in[4];

    float* out = (float*)d_out;
    float* a_out = out;
    float* present = out + (size_t)M_TOT * DD;

    unsigned char *xs, *bta, *btp, *atts;
    __half *qsp, *ksp, *vsp;
    cudaGetSymbolAddress((void**)&xs,   g_xs);
    cudaGetSymbolAddress((void**)&bta,  g_bta);
    cudaGetSymbolAddress((void**)&btp,  g_btp);
    cudaGetSymbolAddress((void**)&atts, g_atts);
    cudaGetSymbolAddress((void**)&qsp,  g_qs);
    cudaGetSymbolAddress((void**)&ksp,  g_ks);
    cudaGetSymbolAddress((void**)&vsp,  g_vs);

    cudaFuncSetAttribute(f16_gemm_kernel,
                         cudaFuncAttributeMaxDynamicSharedMemorySize, GSMEM);
    cudaFuncSetAttribute(attn_mma_kernel,
                         cudaFuncAttributeMaxDynamicSharedMemorySize, ATT_SMEM);

    // Prepasses
    split_kernel<<<(M_TOT * DD / 4 + 255) / 256, 256>>>(
        (const float4*)x, xs, M_TOT * DD / 4);
    transpose_split_kernel<<<dim3(3 * DD / 32, DD / 32), dim3(32, 8)>>>(
        w_attn, bta, DD, 3 * DD);
    transpose_split_kernel<<<dim3(DD / 32, DD / 32), dim3(32, 8)>>>(
        w_proj, btp, DD, DD);

    // QKV GEMM (2-term) -> q hi/lo, k/v hi + fp32 present
    f16_gemm_kernel<<<dim3(3 * DD / 128, M_TOT / 128), 256, GSMEM>>>(
        xs, bta, b_attn, nullptr, qsp, ksp, vsp, present, 3 * DD, 0);

    // Tensor-core flash attention (2-term) -> g_atts (hi-only)
    attn_mma_kernel<<<dim3(TT / 128, HH, BB), 256, ATT_SMEM>>>(
        qsp, ksp, vsp, atts);

    // Projection GEMM (2-term) -> a_out
    f16_gemm_kernel<<<dim3(DD / 128, M_TOT / 128), 256, GSMEM>>>(
        atts, btp, b_proj, a_out, nullptr, nullptr, nullptr, nullptr, DD, 1);
}